// round 5
// baseline (speedup 1.0000x reference)
#include <cuda_runtime.h>
#include <cstdint>
#include <math.h>

#define FULLMASK 0xFFFFFFFFu

constexpr int Bz = 8, Np = 4096, Cch = 64, Kn = 30;
constexpr int Mtot = Bz * Np * Kn;           // 983040
constexpr float EPS_BN = 1e-5f;
constexpr float TINYc = 1e-20f;

constexpr int CAND_MAX = 192;
constexpr int KNN_TPB = 512;                 // 16 warps, 1 block/SM
constexpr int QPW = 4;                       // queries per warp

// ---------------- scratch ---------------------------------------------------
__device__ float4 g_pts4[Bz * Np];
__device__ float  g_xT[Bz * Np * Cch];
__device__ int    g_idx[Mtot];
__device__ float  g_h1[6 * Mtot];
__device__ float  g_h2[3 * Mtot];
__device__ float  g_h3[Mtot];
__device__ double g_stats[24];

// ---------------- K_zero: zero stats (launch #1) ---------------------------
__global__ void k_zero() {
    if (threadIdx.x < 24) g_stats[threadIdx.x] = 0.0;
}

// ---------------- K_xt: tiled transpose x -> xT [B,N,C] (launch #2) --------
__global__ void __launch_bounds__(256) k_xt(const float* __restrict__ x) {
    __shared__ float s[64][33];
    int b = blockIdx.y;
    int n0 = blockIdx.x * 32;
    int lane = threadIdx.x & 31, w = threadIdx.x >> 5;
    #pragma unroll
    for (int i = 0; i < 8; i++) {
        int c = w * 8 + i;
        s[c][lane] = x[(((b << 6) + c) << 12) + n0 + lane];
    }
    __syncthreads();
    #pragma unroll
    for (int i = 0; i < 8; i++) {
        int e = i * 256 + threadIdx.x;
        int nl = e >> 6, c = e & 63;
        g_xT[(size_t)(((b << 12) + n0 + nl) << 6) + c] = s[c][nl];
    }
}

// ---------------- K_init: build pts4 (launch #3) ---------------------------
__global__ void __launch_bounds__(256) k_init(const float* __restrict__ xloc) {
    int t = blockIdx.x * blockDim.x + threadIdx.x;
    int stride = gridDim.x * blockDim.x;
    for (int i = t; i < Bz * Np; i += stride) {
        int b = i >> 12, n = i & 4095;
        const float* p = xloc + b * 3 * Np;
        float px = p[n], py = p[Np + n], pz = p[2 * Np + n];
        float xx = fmaf(pz, pz, fmaf(py, py, px * px));
        g_pts4[i] = make_float4(px, py, pz, xx);
    }
}

// ---------------- K_knn: 4 queries/warp (launch #4 -> gets profiled) -------
__device__ __forceinline__ float pdF(float4 q, float4 p) {
    float dot = fmaf(q.z, p.z, fmaf(q.y, p.y, q.x * p.x));
    return fmaf(2.0f, dot, -q.w) - p.w;
}
__device__ __forceinline__ unsigned fkeyU(float f) {
    unsigned b = __float_as_uint(f);
    return b ^ ((unsigned)((int)b >> 31) | 0x80000000u);
}
__device__ __forceinline__ unsigned long long packC(float pd, int j) {
    return ((unsigned long long)fkeyU(pd) << 16) | (unsigned)j;
}

__device__ __forceinline__ void rankWrite(const unsigned long long* cand, int C,
                                          int base, int lane) {
    if (C < Kn) {                            // rare fallback: pad with self-ish
        if (lane < Kn) g_idx[base + lane] = (int)(cand[0] & 0xFFFFULL);
        if (lane < C)  g_idx[base + lane] = (int)(cand[lane] & 0xFFFFULL);
        return;
    }
    for (int tb = 0; tb < C; tb += 128) {
        int t0 = tb + lane;
        unsigned long long v0 = (t0 < C)      ? cand[t0]      : 0ULL;
        unsigned long long v1 = (t0 + 32 < C) ? cand[t0 + 32] : 0ULL;
        unsigned long long v2 = (t0 + 64 < C) ? cand[t0 + 64] : 0ULL;
        unsigned long long v3 = (t0 + 96 < C) ? cand[t0 + 96] : 0ULL;
        int r0 = 0, r1 = 0, r2 = 0, r3 = 0;
        #pragma unroll 4
        for (int s = 0; s < C; s++) {
            unsigned long long w2 = cand[s];
            r0 += (w2 > v0); r1 += (w2 > v1);
            r2 += (w2 > v2); r3 += (w2 > v3);
        }
        if (t0 < C      && r0 < Kn) g_idx[base + r0] = (int)(v0 & 0xFFFFULL);
        if (t0 + 32 < C && r1 < Kn) g_idx[base + r1] = (int)(v1 & 0xFFFFULL);
        if (t0 + 64 < C && r2 < Kn) g_idx[base + r2] = (int)(v2 & 0xFFFFULL);
        if (t0 + 96 < C && r3 < Kn) g_idx[base + r3] = (int)(v3 & 0xFFFFULL);
    }
}

__global__ void __launch_bounds__(KNN_TPB, 1) k_knn() {
    extern __shared__ unsigned char smemRaw[];
    float4* sPts = reinterpret_cast<float4*>(smemRaw);
    unsigned long long* candBase =
        reinterpret_cast<unsigned long long*>(smemRaw + sizeof(float4) * Np);

    int b = blockIdx.y;
    const float4* gp = g_pts4 + b * Np;
    for (int i = threadIdx.x; i < Np; i += KNN_TPB) sPts[i] = gp[i];
    __syncthreads();

    int wid = threadIdx.x >> 5, lane = threadIdx.x & 31;
    unsigned long long* cand = candBase + (size_t)wid * QPW * CAND_MAX;
    unsigned laneLT = (lane == 31) ? 0x7FFFFFFFu : ((1u << lane) - 1u);

    int g0 = blockIdx.x * 64 + wid * QPW;    // 16 blocks x 16 warps x 4 = 1024 groups

    for (int gi = 0; gi < QPW; gi++) {
        int n = g0 + gi;                     // queries n, n+1024, n+2048, n+3072
        float4 q[4];
        #pragma unroll
        for (int qi = 0; qi < 4; qi++) q[qi] = sPts[n + qi * 1024];

        // --- sample pass: contiguous 512-pt window, per-lane top-2 x 4 -----
        int sb = (n & 7) << 9;
        float m1[4], m2[4];
        #pragma unroll
        for (int qi = 0; qi < 4; qi++) { m1[qi] = -3.4e38f; m2[qi] = -3.4e38f; }
        #pragma unroll 2
        for (int t = 0; t < 16; t++) {
            float4 p = sPts[sb + t * 32 + lane];
            #pragma unroll
            for (int qi = 0; qi < 4; qi++) {
                float pd = pdF(q[qi], p);
                if (pd > m2[qi]) {
                    if (pd > m1[qi]) { m2[qi] = m1[qi]; m1[qi] = pd; }
                    else m2[qi] = pd;
                }
            }
        }
        // --- extract 8th & 16th largest per query --------------------------
        float T[4], Tr[4];
        for (int r = 0; r < 16; r++) {
            #pragma unroll
            for (int qi = 0; qi < 4; qi++) {
                float v = m1[qi];
                #pragma unroll
                for (int o = 16; o; o >>= 1)
                    v = fmaxf(v, __shfl_xor_sync(FULLMASK, v, o));
                if (r == 7)  T[qi] = v;
                if (r == 15) Tr[qi] = v;
                unsigned wm = __ballot_sync(FULLMASK, m1[qi] == v);
                if (lane == __ffs(wm) - 1) { m1[qi] = m2[qi]; m2[qi] = -3.4e38f; }
            }
        }

        // --- main scan: 128 pts/iter, 4 queries share the loads ------------
        unsigned cnt[4] = {0, 0, 0, 0};
        for (int j0 = 0; j0 < Np; j0 += 128) {
            float4 p0 = sPts[j0 + lane];
            float4 p1 = sPts[j0 + 32 + lane];
            float4 p2 = sPts[j0 + 64 + lane];
            float4 p3 = sPts[j0 + 96 + lane];
            #pragma unroll
            for (int qi = 0; qi < 4; qi++) {
                float d0 = pdF(q[qi], p0), d1 = pdF(q[qi], p1);
                float d2 = pdF(q[qi], p2), d3 = pdF(q[qi], p3);
                float Tq = T[qi];
                unsigned mk0 = __ballot_sync(FULLMASK, d0 > Tq);
                unsigned mk1 = __ballot_sync(FULLMASK, d1 > Tq);
                unsigned mk2 = __ballot_sync(FULLMASK, d2 > Tq);
                unsigned mk3 = __ballot_sync(FULLMASK, d3 > Tq);
                unsigned long long* cq = cand + qi * CAND_MAX;
                unsigned pos;
                if (d0 > Tq) { pos = cnt[qi] + __popc(mk0 & laneLT); if (pos < CAND_MAX) cq[pos] = packC(d0, j0 + lane); }
                cnt[qi] += __popc(mk0);
                if (d1 > Tq) { pos = cnt[qi] + __popc(mk1 & laneLT); if (pos < CAND_MAX) cq[pos] = packC(d1, j0 + 32 + lane); }
                cnt[qi] += __popc(mk1);
                if (d2 > Tq) { pos = cnt[qi] + __popc(mk2 & laneLT); if (pos < CAND_MAX) cq[pos] = packC(d2, j0 + 64 + lane); }
                cnt[qi] += __popc(mk2);
                if (d3 > Tq) { pos = cnt[qi] + __popc(mk3 & laneLT); if (pos < CAND_MAX) cq[pos] = packC(d3, j0 + 96 + lane); }
                cnt[qi] += __popc(mk3);
            }
        }

        // --- rare per-query retry with looser threshold --------------------
        #pragma unroll
        for (int qi = 0; qi < 4; qi++) {
            if (cnt[qi] < Kn) {              // warp-uniform (from ballots)
                unsigned c = 0;
                float Tq = Tr[qi];
                float4 qq = q[qi];
                unsigned long long* cq = cand + qi * CAND_MAX;
                for (int j0 = 0; j0 < Np; j0 += 64) {
                    float4 p0 = sPts[j0 + lane];
                    float4 p1 = sPts[j0 + 32 + lane];
                    float d0 = pdF(qq, p0), d1 = pdF(qq, p1);
                    unsigned mk0 = __ballot_sync(FULLMASK, d0 > Tq);
                    unsigned mk1 = __ballot_sync(FULLMASK, d1 > Tq);
                    unsigned pos;
                    if (d0 > Tq) { pos = c + __popc(mk0 & laneLT); if (pos < CAND_MAX) cq[pos] = packC(d0, j0 + lane); }
                    c += __popc(mk0);
                    if (d1 > Tq) { pos = c + __popc(mk1 & laneLT); if (pos < CAND_MAX) cq[pos] = packC(d1, j0 + 32 + lane); }
                    c += __popc(mk1);
                }
                cnt[qi] = c;
            }
        }
        __syncwarp();

        // --- rank-based top-30 write per query -----------------------------
        #pragma unroll
        for (int qi = 0; qi < 4; qi++) {
            int nq = n + qi * 1024;
            rankWrite(cand + qi * CAND_MAX, min((int)cnt[qi], CAND_MAX),
                      (b * Np + nq) * Kn, lane);
        }
        __syncwarp();
    }
}

// ---------------- block-level stat accumulation ----------------------------
template <int NV>
__device__ __forceinline__ void accumStats(const float* vals, float* sAcc, int statBase) {
    #pragma unroll
    for (int v = 0; v < NV; v++) {
        float x = vals[v];
        #pragma unroll
        for (int off = 16; off; off >>= 1) x += __shfl_down_sync(FULLMASK, x, off);
        if ((threadIdx.x & 31) == 0) atomicAdd(&sAcc[v], x);
    }
    __syncthreads();
    if (threadIdx.x < NV) atomicAdd(&g_stats[statBase + threadIdx.x], (double)sAcc[threadIdx.x]);
}

// ---------------- K_feat: spherical features + layer1 + stats --------------
__global__ void __launch_bounds__(256, 4) k_feat(const float* __restrict__ W1) {
    __shared__ float sW[36];
    __shared__ float sAcc[12];
    int tid = threadIdx.x;
    if (tid < 36) sW[tid] = W1[tid];
    if (tid < 12) sAcc[tid] = 0.f;
    __syncthreads();
    int wid = tid >> 5, lane = tid & 31;
    float acc[12];
    #pragma unroll
    for (int v = 0; v < 12; v++) acc[v] = 0.f;

    for (int i = 0; i < 8; i++) {
        int r = blockIdx.x * 64 + i * 8 + wid;
        int b = r >> 12;
        if (lane < Kn) {
            int e = r * Kn + lane;
            int j = g_idx[e];
            float4 pn = g_pts4[r];
            float4 pj = g_pts4[(b << 12) + j];
            float xr = pj.x - pn.x, yr = pj.y - pn.y, zr = pj.z - pn.z;
            float sxy2 = fmaf(yr, yr, xr * xr);
            float r2 = fmaf(zr, zr, sxy2);
            float rho = sqrtf(fmaxf(r2, TINYc));
            float sxy = sqrtf(fmaxf(sxy2, TINYc));
            float theta = (r2 < TINYc) ? 0.f : atan2f(zr, sxy);
            float phi = (sxy2 < TINYc) ? 0.f : atan2f(yr, xr);
            float mn = (rho + theta + phi) * (1.f / 3.f);
            float f[6] = {rho, theta, phi, rho - mn, theta - mn, phi - mn};
            #pragma unroll
            for (int o = 0; o < 6; o++) {
                float h = 0.f;
                #pragma unroll
                for (int i2 = 0; i2 < 6; i2++) h = fmaf(sW[o * 6 + i2], f[i2], h);
                g_h1[o * Mtot + e] = h;
                acc[o] += h; acc[6 + o] = fmaf(h, h, acc[6 + o]);
            }
        }
    }
    accumStats<12>(acc, sAcc, 0);
}

__device__ __forceinline__ float lrelu02(float t) { return t > 0.f ? t : 0.2f * t; }

// ---------------- K_l2: BN1 + lrelu + layer2 + stats (float4) --------------
__global__ void __launch_bounds__(256) k_l2(const float* __restrict__ gma,
                                            const float* __restrict__ bta,
                                            const float* __restrict__ W2) {
    __shared__ float sMu[6], sIs[6], sG[6], sB[6], sW[18], sAcc[6];
    int tid = threadIdx.x;
    if (tid < 6) {
        double s = g_stats[tid], sq = g_stats[6 + tid];
        double mu = s / (double)Mtot;
        double var = sq / (double)Mtot - mu * mu;
        sMu[tid] = (float)mu;
        sIs[tid] = (float)(1.0 / sqrt(var + (double)EPS_BN));
        sG[tid] = gma[tid]; sB[tid] = bta[tid];
        sAcc[tid] = 0.f;
    }
    if (tid < 18) sW[tid] = W2[tid];
    __syncthreads();
    int e4 = (blockIdx.x * 256 + tid) * 4;
    float4 a[6];
    #pragma unroll
    for (int i = 0; i < 6; i++) {
        float4 h = *reinterpret_cast<const float4*>(&g_h1[i * Mtot + e4]);
        float sc = sIs[i] * sG[i], mu = sMu[i], bb = sB[i];
        a[i].x = lrelu02(fmaf((h.x - mu), sc, bb));
        a[i].y = lrelu02(fmaf((h.y - mu), sc, bb));
        a[i].z = lrelu02(fmaf((h.z - mu), sc, bb));
        a[i].w = lrelu02(fmaf((h.w - mu), sc, bb));
    }
    float vals[6];
    #pragma unroll
    for (int o = 0; o < 3; o++) {
        float4 h = make_float4(0.f, 0.f, 0.f, 0.f);
        #pragma unroll
        for (int i = 0; i < 6; i++) {
            float w = sW[o * 6 + i];
            h.x = fmaf(w, a[i].x, h.x); h.y = fmaf(w, a[i].y, h.y);
            h.z = fmaf(w, a[i].z, h.z); h.w = fmaf(w, a[i].w, h.w);
        }
        *reinterpret_cast<float4*>(&g_h2[o * Mtot + e4]) = h;
        vals[o] = (h.x + h.y) + (h.z + h.w);
        vals[3 + o] = fmaf(h.x, h.x, h.y * h.y) + fmaf(h.z, h.z, h.w * h.w);
    }
    accumStats<6>(vals, sAcc, 12);
}

// ---------------- K_l3: BN2 + lrelu + layer3 + stats (float4) --------------
__global__ void __launch_bounds__(256) k_l3(const float* __restrict__ gma,
                                            const float* __restrict__ bta,
                                            const float* __restrict__ W3) {
    __shared__ float sMu[3], sIs[3], sG[3], sB[3], sW[3], sAcc[2];
    int tid = threadIdx.x;
    if (tid < 3) {
        double s = g_stats[12 + tid], sq = g_stats[15 + tid];
        double mu = s / (double)Mtot;
        double var = sq / (double)Mtot - mu * mu;
        sMu[tid] = (float)mu;
        sIs[tid] = (float)(1.0 / sqrt(var + (double)EPS_BN));
        sG[tid] = gma[tid]; sB[tid] = bta[tid];
        sW[tid] = W3[tid];
    }
    if (tid < 2) sAcc[tid] = 0.f;
    __syncthreads();
    int e4 = (blockIdx.x * 256 + tid) * 4;
    float4 h = make_float4(0.f, 0.f, 0.f, 0.f);
    #pragma unroll
    for (int i = 0; i < 3; i++) {
        float4 hv = *reinterpret_cast<const float4*>(&g_h2[i * Mtot + e4]);
        float sc = sIs[i] * sG[i], mu = sMu[i], bb = sB[i], w = sW[i];
        h.x = fmaf(w, lrelu02(fmaf((hv.x - mu), sc, bb)), h.x);
        h.y = fmaf(w, lrelu02(fmaf((hv.y - mu), sc, bb)), h.y);
        h.z = fmaf(w, lrelu02(fmaf((hv.z - mu), sc, bb)), h.z);
        h.w = fmaf(w, lrelu02(fmaf((hv.w - mu), sc, bb)), h.w);
    }
    *reinterpret_cast<float4*>(&g_h3[e4]) = h;
    float vals[2];
    vals[0] = (h.x + h.y) + (h.z + h.w);
    vals[1] = fmaf(h.x, h.x, h.y * h.y) + fmaf(h.z, h.z, h.w * h.w);
    accumStats<2>(vals, sAcc, 18);
}

// ---------------- K_out: BN3 + lrelu + softmax + aggregate -----------------
__global__ void __launch_bounds__(256) k_out(const float* __restrict__ x,
                                             const float* __restrict__ g3,
                                             const float* __restrict__ b3,
                                             float* __restrict__ out) {
    __shared__ float sAtt[8][Kn];
    __shared__ int sJ[8][Kn];
    __shared__ float sMu, sIs;
    int tid = threadIdx.x, wid = tid >> 5, lane = tid & 31;
    if (tid == 0) {
        double s = g_stats[18], sq = g_stats[19];
        double mu = s / (double)Mtot;
        double var = sq / (double)Mtot - mu * mu;
        sMu = (float)mu;
        sIs = (float)(1.0 / sqrt(var + (double)EPS_BN));
    }
    __syncthreads();
    int r = blockIdx.x * 8 + wid;
    int b = r >> 12, n = r & 4095;
    float gv = g3[0], bv = b3[0];
    float logit = -INFINITY;
    if (lane < Kn) {
        float h = g_h3[r * Kn + lane];
        float t = fmaf((h - sMu) * sIs, gv, bv);
        logit = t > 0.f ? t : 0.2f * t;
    }
    float mx = logit;
    #pragma unroll
    for (int off = 16; off; off >>= 1) mx = fmaxf(mx, __shfl_xor_sync(FULLMASK, mx, off));
    float ex = (lane < Kn) ? expf(logit - mx) : 0.f;
    float sm = ex;
    #pragma unroll
    for (int off = 16; off; off >>= 1) sm += __shfl_xor_sync(FULLMASK, sm, off);
    float att = ex / sm;
    if (lane < Kn) {
        sAtt[wid][lane] = att;
        sJ[wid][lane] = g_idx[r * Kn + lane];
    }
    __syncwarp();
    float acc0 = 0.f, acc1 = 0.f;
    const float* xb = g_xT + (size_t)(b << 12) * Cch;
    #pragma unroll 5
    for (int kk = 0; kk < Kn; kk++) {
        const float* p = xb + sJ[wid][kk] * Cch;
        float a = sAtt[wid][kk];
        acc0 = fmaf(a, p[lane], acc0);
        acc1 = fmaf(a, p[lane + 32], acc1);
    }
    size_t o0 = (size_t)b * (Cch * Np) + (size_t)lane * Np + (size_t)n;
    size_t o1 = o0 + (size_t)32 * Np;
    out[o0] = x[o0] + acc0;
    out[o1] = x[o1] + acc1;
}

// ---------------- launch ----------------------------------------------------
extern "C" void kernel_launch(void* const* d_in, const int* in_sizes, int n_in,
                              void* d_out, int out_size) {
    const float* xloc = (const float*)d_in[0];
    const float* x    = (const float*)d_in[1];
    const float* W1   = (const float*)d_in[2];
    const float* g1   = (const float*)d_in[3];
    const float* b1   = (const float*)d_in[4];
    const float* W2   = (const float*)d_in[5];
    const float* g2   = (const float*)d_in[6];
    const float* b2   = (const float*)d_in[7];
    const float* W3   = (const float*)d_in[8];
    const float* g3   = (const float*)d_in[9];
    const float* b3   = (const float*)d_in[10];
    float* out = (float*)d_out;

    size_t knnSmem = sizeof(float4) * Np +
                     sizeof(unsigned long long) * (KNN_TPB / 32) * QPW * CAND_MAX;
    cudaFuncSetAttribute(k_knn, cudaFuncAttributeMaxDynamicSharedMemorySize, (int)knnSmem);

    k_zero<<<1, 32>>>();                       // #1
    k_xt<<<dim3(Np / 32, Bz), 256>>>(x);       // #2
    k_init<<<128, 256>>>(xloc);                // #3
    k_knn<<<dim3(16, Bz), KNN_TPB, knnSmem>>>(); // #4  <- profiled
    k_feat<<<512, 256>>>(W1);                  // #5
    k_l2<<<Mtot / 1024, 256>>>(g1, b1, W2);    // #6
    k_l3<<<Mtot / 1024, 256>>>(g2, b2, W3);    // #7
    k_out<<<Bz * Np / 8, 256>>>(x, g3, b3, out); // #8
}

// round 6
// speedup vs baseline: 1.0839x; 1.0839x over previous
#include <cuda_runtime.h>
#include <cstdint>
#include <math.h>

#define FULLMASK 0xFFFFFFFFu

constexpr int Bz = 8, Np = 4096, Cch = 64, Kn = 30;
constexpr int Mtot = Bz * Np * Kn;           // 983040
constexpr float EPS_BN = 1e-5f;
constexpr float TINYc = 1e-20f;

constexpr int CAND_MAX = 192;
constexpr int KNN_TPB = 512;                 // 16 warps
constexpr int KNN_WARPS = KNN_TPB / 32;
constexpr int QPW = 4;                       // queries in flight per warp
constexpr int NGRP = Np / QPW;               // 1024 groups per batch

// ---------------- scratch ---------------------------------------------------
__device__ float4 g_pts4[Bz * Np];           // x,y,z, -0.5*|p|^2
__device__ float  g_xT[Bz * Np * Cch];
__device__ int    g_idx[Mtot];
__device__ float  g_h1[6 * Mtot];
__device__ float  g_h2[3 * Mtot];
__device__ float  g_h3[Mtot];
__device__ double g_stats[24];

// ---------------- K_zero (launch #1) ---------------------------------------
__global__ void k_zero() {
    if (threadIdx.x < 24) g_stats[threadIdx.x] = 0.0;
}

// ---------------- K_xt: tiled transpose x -> xT [B,N,C] (launch #2) --------
__global__ void __launch_bounds__(256) k_xt(const float* __restrict__ x) {
    __shared__ float s[64][33];
    int b = blockIdx.y;
    int n0 = blockIdx.x * 32;
    int lane = threadIdx.x & 31, w = threadIdx.x >> 5;
    #pragma unroll
    for (int i = 0; i < 8; i++) {
        int c = w * 8 + i;
        s[c][lane] = x[(((b << 6) + c) << 12) + n0 + lane];
    }
    __syncthreads();
    #pragma unroll
    for (int i = 0; i < 8; i++) {
        int e = i * 256 + threadIdx.x;
        int nl = e >> 6, c = e & 63;
        g_xT[(size_t)(((b << 12) + n0 + nl) << 6) + c] = s[c][nl];
    }
}

// ---------------- K_init: build pts4 with w = -0.5|p|^2 (launch #3) --------
__global__ void __launch_bounds__(256) k_init(const float* __restrict__ xloc) {
    int t = blockIdx.x * blockDim.x + threadIdx.x;
    int stride = gridDim.x * blockDim.x;
    for (int i = t; i < Bz * Np; i += stride) {
        int b = i >> 12, n = i & 4095;
        const float* p = xloc + b * 3 * Np;
        float px = p[n], py = p[Np + n], pz = p[2 * Np + n];
        float xx = fmaf(pz, pz, fmaf(py, py, px * px));
        g_pts4[i] = make_float4(px, py, pz, -0.5f * xx);
    }
}

// ---------------- K_knn (launch #4 -> profiled) ----------------------------
// score s(q,p) = q.p - 0.5|p|^2 = fma chain from p.w; pd = 2s - |q|^2 so
// s-order == pd-order per query. 3 FMA + 1 FSETP per point per query.
__device__ __forceinline__ float sF(float4 q, float4 p) {
    return fmaf(q.z, p.z, fmaf(q.y, p.y, fmaf(q.x, p.x, p.w)));
}
__device__ __forceinline__ unsigned fkeyU(float f) {
    unsigned b = __float_as_uint(f);
    return b ^ ((unsigned)((int)b >> 31) | 0x80000000u);
}

__device__ __forceinline__ void rankWrite(const unsigned long long* cand, int C,
                                          int base, int lane) {
    if (C < Kn) {                            // astronomically rare fallback
        if (lane < Kn) g_idx[base + lane] = (int)(cand[0] & 0xFFFULL);
        if (lane < C)  g_idx[base + lane] = (int)(cand[lane] & 0xFFFULL);
        return;
    }
    for (int tb = 0; tb < C; tb += 128) {
        int t0 = tb + lane;
        unsigned long long v0 = (t0 < C)      ? cand[t0]      : 0ULL;
        unsigned long long v1 = (t0 + 32 < C) ? cand[t0 + 32] : 0ULL;
        unsigned long long v2 = (t0 + 64 < C) ? cand[t0 + 64] : 0ULL;
        unsigned long long v3 = (t0 + 96 < C) ? cand[t0 + 96] : 0ULL;
        int r0 = 0, r1 = 0, r2 = 0, r3 = 0;
        #pragma unroll 4
        for (int s = 0; s < C; s++) {
            unsigned long long w2 = cand[s];
            r0 += (w2 > v0); r1 += (w2 > v1);
            r2 += (w2 > v2); r3 += (w2 > v3);
        }
        if (t0 < C      && r0 < Kn) g_idx[base + r0] = (int)(v0 & 0xFFFULL);
        if (t0 + 32 < C && r1 < Kn) g_idx[base + r1] = (int)(v1 & 0xFFFULL);
        if (t0 + 64 < C && r2 < Kn) g_idx[base + r2] = (int)(v2 & 0xFFFULL);
        if (t0 + 96 < C && r3 < Kn) g_idx[base + r3] = (int)(v3 & 0xFFFULL);
    }
}

__global__ void __launch_bounds__(KNN_TPB, 1) k_knn() {
    extern __shared__ unsigned char smemRaw[];
    float4* sPts = reinterpret_cast<float4*>(smemRaw);
    unsigned long long* candBase =
        reinterpret_cast<unsigned long long*>(smemRaw + sizeof(float4) * Np);

    int b = blockIdx.y;
    const float4* gp = g_pts4 + b * Np;
    for (int i = threadIdx.x; i < Np; i += KNN_TPB) sPts[i] = gp[i];
    __syncthreads();

    int wid = threadIdx.x >> 5, lane = threadIdx.x & 31;
    unsigned long long* cand = candBase + (size_t)wid * QPW * CAND_MAX;
    unsigned laneLT = (lane == 31) ? 0x7FFFFFFFu : ((1u << lane) - 1u);

    for (int g = blockIdx.x * KNN_WARPS + wid; g < NGRP; g += gridDim.x * KNN_WARPS) {
        int n = g;                           // queries n, n+1024, n+2048, n+3072
        float4 q[4];
        #pragma unroll
        for (int qi = 0; qi < 4; qi++) q[qi] = sPts[n + qi * NGRP];

        // --- sample pass: contiguous 512-pt window, per-lane top-2 x 4 -----
        int sb = (n & 7) << 9;
        float m1[4], m2[4];
        #pragma unroll
        for (int qi = 0; qi < 4; qi++) { m1[qi] = -3.4e38f; m2[qi] = -3.4e38f; }
        #pragma unroll 2
        for (int t = 0; t < 16; t++) {
            float4 p = sPts[sb + t * 32 + lane];
            #pragma unroll
            for (int qi = 0; qi < 4; qi++) {
                float s = sF(q[qi], p);
                if (s > m2[qi]) {
                    if (s > m1[qi]) { m2[qi] = m1[qi]; m1[qi] = s; }
                    else m2[qi] = s;
                }
            }
        }
        // --- extract 8th & 16th largest per query --------------------------
        float T[4], Tr[4];
        for (int r = 0; r < 16; r++) {
            #pragma unroll
            for (int qi = 0; qi < 4; qi++) {
                float v = m1[qi];
                #pragma unroll
                for (int o = 16; o; o >>= 1)
                    v = fmaxf(v, __shfl_xor_sync(FULLMASK, v, o));
                if (r == 7)  T[qi] = v;
                if (r == 15) Tr[qi] = v;
                unsigned wm = __ballot_sync(FULLMASK, m1[qi] == v);
                if (lane == __ffs(wm) - 1) { m1[qi] = m2[qi]; m2[qi] = -3.4e38f; }
            }
        }

        // --- main scan: 128 pts/iter, indices-only collect -----------------
        unsigned cnt[4] = {0, 0, 0, 0};
        for (int j0 = 0; j0 < Np; j0 += 128) {
            float4 p0 = sPts[j0 + lane];
            float4 p1 = sPts[j0 + 32 + lane];
            float4 p2 = sPts[j0 + 64 + lane];
            float4 p3 = sPts[j0 + 96 + lane];
            #pragma unroll
            for (int qi = 0; qi < 4; qi++) {
                float s0 = sF(q[qi], p0), s1 = sF(q[qi], p1);
                float s2 = sF(q[qi], p2), s3 = sF(q[qi], p3);
                float Tq = T[qi];
                unsigned mk0 = __ballot_sync(FULLMASK, s0 > Tq);
                unsigned mk1 = __ballot_sync(FULLMASK, s1 > Tq);
                unsigned mk2 = __ballot_sync(FULLMASK, s2 > Tq);
                unsigned mk3 = __ballot_sync(FULLMASK, s3 > Tq);
                unsigned* cq32 = reinterpret_cast<unsigned*>(cand + qi * CAND_MAX);
                unsigned pos;
                if (s0 > Tq) { pos = cnt[qi] + __popc(mk0 & laneLT); if (pos < CAND_MAX) cq32[2 * pos] = j0 + lane; }
                cnt[qi] += __popc(mk0);
                if (s1 > Tq) { pos = cnt[qi] + __popc(mk1 & laneLT); if (pos < CAND_MAX) cq32[2 * pos] = j0 + 32 + lane; }
                cnt[qi] += __popc(mk1);
                if (s2 > Tq) { pos = cnt[qi] + __popc(mk2 & laneLT); if (pos < CAND_MAX) cq32[2 * pos] = j0 + 64 + lane; }
                cnt[qi] += __popc(mk2);
                if (s3 > Tq) { pos = cnt[qi] + __popc(mk3 & laneLT); if (pos < CAND_MAX) cq32[2 * pos] = j0 + 96 + lane; }
                cnt[qi] += __popc(mk3);
            }
        }

        // --- rare per-query retry with looser threshold --------------------
        #pragma unroll
        for (int qi = 0; qi < 4; qi++) {
            if (cnt[qi] < Kn) {              // warp-uniform (from ballots)
                unsigned c = 0;
                float Tq = Tr[qi];
                float4 qq = q[qi];
                unsigned* cq32 = reinterpret_cast<unsigned*>(cand + qi * CAND_MAX);
                for (int j0 = 0; j0 < Np; j0 += 64) {
                    float s0 = sF(qq, sPts[j0 + lane]);
                    float s1 = sF(qq, sPts[j0 + 32 + lane]);
                    unsigned mk0 = __ballot_sync(FULLMASK, s0 > Tq);
                    unsigned mk1 = __ballot_sync(FULLMASK, s1 > Tq);
                    unsigned pos;
                    if (s0 > Tq) { pos = c + __popc(mk0 & laneLT); if (pos < CAND_MAX) cq32[2 * pos] = j0 + lane; }
                    c += __popc(mk0);
                    if (s1 > Tq) { pos = c + __popc(mk1 & laneLT); if (pos < CAND_MAX) cq32[2 * pos] = j0 + 32 + lane; }
                    c += __popc(mk1);
                }
                cnt[qi] = c;
            }
        }
        __syncwarp();

        // --- pack (key<<12 | idx) then rank-select top-30 ------------------
        #pragma unroll
        for (int qi = 0; qi < 4; qi++) {
            int C = min((int)cnt[qi], CAND_MAX);
            unsigned long long* cq = cand + qi * CAND_MAX;
            unsigned* cq32 = reinterpret_cast<unsigned*>(cq);
            float4 qq = q[qi];
            for (int t = lane; t < C; t += 32) {
                unsigned j = cq32[2 * t];
                float s = sF(qq, sPts[j]);
                cq[t] = ((unsigned long long)fkeyU(s) << 12) | j;
            }
            __syncwarp();
            rankWrite(cq, C, (b * Np + n + qi * NGRP) * Kn, lane);
        }
        __syncwarp();
    }
}

// ---------------- block-level stat accumulation ----------------------------
template <int NV>
__device__ __forceinline__ void accumStats(const float* vals, float* sAcc, int statBase) {
    #pragma unroll
    for (int v = 0; v < NV; v++) {
        float x = vals[v];
        #pragma unroll
        for (int off = 16; off; off >>= 1) x += __shfl_down_sync(FULLMASK, x, off);
        if ((threadIdx.x & 31) == 0) atomicAdd(&sAcc[v], x);
    }
    __syncthreads();
    if (threadIdx.x < NV) atomicAdd(&g_stats[statBase + threadIdx.x], (double)sAcc[threadIdx.x]);
}

// ---------------- K_feat: spherical features + layer1 + stats --------------
__global__ void __launch_bounds__(256, 4) k_feat(const float* __restrict__ W1) {
    __shared__ float sW[36];
    __shared__ float sAcc[12];
    int tid = threadIdx.x;
    if (tid < 36) sW[tid] = W1[tid];
    if (tid < 12) sAcc[tid] = 0.f;
    __syncthreads();
    int wid = tid >> 5, lane = tid & 31;
    float acc[12];
    #pragma unroll
    for (int v = 0; v < 12; v++) acc[v] = 0.f;

    for (int i = 0; i < 8; i++) {
        int r = blockIdx.x * 64 + i * 8 + wid;
        int b = r >> 12;
        if (lane < Kn) {
            int e = r * Kn + lane;
            int j = g_idx[e];
            float4 pn = g_pts4[r];
            float4 pj = g_pts4[(b << 12) + j];
            float xr = pj.x - pn.x, yr = pj.y - pn.y, zr = pj.z - pn.z;
            float sxy2 = fmaf(yr, yr, xr * xr);
            float r2 = fmaf(zr, zr, sxy2);
            float rho = sqrtf(fmaxf(r2, TINYc));
            float sxy = sqrtf(fmaxf(sxy2, TINYc));
            float theta = (r2 < TINYc) ? 0.f : atan2f(zr, sxy);
            float phi = (sxy2 < TINYc) ? 0.f : atan2f(yr, xr);
            float mn = (rho + theta + phi) * (1.f / 3.f);
            float f[6] = {rho, theta, phi, rho - mn, theta - mn, phi - mn};
            #pragma unroll
            for (int o = 0; o < 6; o++) {
                float h = 0.f;
                #pragma unroll
                for (int i2 = 0; i2 < 6; i2++) h = fmaf(sW[o * 6 + i2], f[i2], h);
                g_h1[o * Mtot + e] = h;
                acc[o] += h; acc[6 + o] = fmaf(h, h, acc[6 + o]);
            }
        }
    }
    accumStats<12>(acc, sAcc, 0);
}

__device__ __forceinline__ float lrelu02(float t) { return t > 0.f ? t : 0.2f * t; }

// ---------------- K_l2: BN1 + lrelu + layer2 + stats (float4) --------------
__global__ void __launch_bounds__(256) k_l2(const float* __restrict__ gma,
                                            const float* __restrict__ bta,
                                            const float* __restrict__ W2) {
    __shared__ float sMu[6], sIs[6], sG[6], sB[6], sW[18], sAcc[6];
    int tid = threadIdx.x;
    if (tid < 6) {
        double s = g_stats[tid], sq = g_stats[6 + tid];
        double mu = s / (double)Mtot;
        double var = sq / (double)Mtot - mu * mu;
        sMu[tid] = (float)mu;
        sIs[tid] = (float)(1.0 / sqrt(var + (double)EPS_BN));
        sG[tid] = gma[tid]; sB[tid] = bta[tid];
        sAcc[tid] = 0.f;
    }
    if (tid < 18) sW[tid] = W2[tid];
    __syncthreads();
    int e4 = (blockIdx.x * 256 + tid) * 4;
    float4 a[6];
    #pragma unroll
    for (int i = 0; i < 6; i++) {
        float4 h = *reinterpret_cast<const float4*>(&g_h1[i * Mtot + e4]);
        float sc = sIs[i] * sG[i], mu = sMu[i], bb = sB[i];
        a[i].x = lrelu02(fmaf((h.x - mu), sc, bb));
        a[i].y = lrelu02(fmaf((h.y - mu), sc, bb));
        a[i].z = lrelu02(fmaf((h.z - mu), sc, bb));
        a[i].w = lrelu02(fmaf((h.w - mu), sc, bb));
    }
    float vals[6];
    #pragma unroll
    for (int o = 0; o < 3; o++) {
        float4 h = make_float4(0.f, 0.f, 0.f, 0.f);
        #pragma unroll
        for (int i = 0; i < 6; i++) {
            float w = sW[o * 6 + i];
            h.x = fmaf(w, a[i].x, h.x); h.y = fmaf(w, a[i].y, h.y);
            h.z = fmaf(w, a[i].z, h.z); h.w = fmaf(w, a[i].w, h.w);
        }
        *reinterpret_cast<float4*>(&g_h2[o * Mtot + e4]) = h;
        vals[o] = (h.x + h.y) + (h.z + h.w);
        vals[3 + o] = fmaf(h.x, h.x, h.y * h.y) + fmaf(h.z, h.z, h.w * h.w);
    }
    accumStats<6>(vals, sAcc, 12);
}

// ---------------- K_l3: BN2 + lrelu + layer3 + stats (float4) --------------
__global__ void __launch_bounds__(256) k_l3(const float* __restrict__ gma,
                                            const float* __restrict__ bta,
                                            const float* __restrict__ W3) {
    __shared__ float sMu[3], sIs[3], sG[3], sB[3], sW[3], sAcc[2];
    int tid = threadIdx.x;
    if (tid < 3) {
        double s = g_stats[12 + tid], sq = g_stats[15 + tid];
        double mu = s / (double)Mtot;
        double var = sq / (double)Mtot - mu * mu;
        sMu[tid] = (float)mu;
        sIs[tid] = (float)(1.0 / sqrt(var + (double)EPS_BN));
        sG[tid] = gma[tid]; sB[tid] = bta[tid];
        sW[tid] = W3[tid];
    }
    if (tid < 2) sAcc[tid] = 0.f;
    __syncthreads();
    int e4 = (blockIdx.x * 256 + tid) * 4;
    float4 h = make_float4(0.f, 0.f, 0.f, 0.f);
    #pragma unroll
    for (int i = 0; i < 3; i++) {
        float4 hv = *reinterpret_cast<const float4*>(&g_h2[i * Mtot + e4]);
        float sc = sIs[i] * sG[i], mu = sMu[i], bb = sB[i], w = sW[i];
        h.x = fmaf(w, lrelu02(fmaf((hv.x - mu), sc, bb)), h.x);
        h.y = fmaf(w, lrelu02(fmaf((hv.y - mu), sc, bb)), h.y);
        h.z = fmaf(w, lrelu02(fmaf((hv.z - mu), sc, bb)), h.z);
        h.w = fmaf(w, lrelu02(fmaf((hv.w - mu), sc, bb)), h.w);
    }
    *reinterpret_cast<float4*>(&g_h3[e4]) = h;
    float vals[2];
    vals[0] = (h.x + h.y) + (h.z + h.w);
    vals[1] = fmaf(h.x, h.x, h.y * h.y) + fmaf(h.z, h.z, h.w * h.w);
    accumStats<2>(vals, sAcc, 18);
}

// ---------------- K_out: BN3 + lrelu + softmax + aggregate -----------------
__global__ void __launch_bounds__(256) k_out(const float* __restrict__ x,
                                             const float* __restrict__ g3,
                                             const float* __restrict__ b3,
                                             float* __restrict__ out) {
    __shared__ float sAtt[8][Kn];
    __shared__ int sJ[8][Kn];
    __shared__ float sMu, sIs;
    int tid = threadIdx.x, wid = tid >> 5, lane = tid & 31;
    if (tid == 0) {
        double s = g_stats[18], sq = g_stats[19];
        double mu = s / (double)Mtot;
        double var = sq / (double)Mtot - mu * mu;
        sMu = (float)mu;
        sIs = (float)(1.0 / sqrt(var + (double)EPS_BN));
    }
    __syncthreads();
    int r = blockIdx.x * 8 + wid;
    int b = r >> 12, n = r & 4095;
    float gv = g3[0], bv = b3[0];
    float logit = -INFINITY;
    if (lane < Kn) {
        float h = g_h3[r * Kn + lane];
        float t = fmaf((h - sMu) * sIs, gv, bv);
        logit = t > 0.f ? t : 0.2f * t;
    }
    float mx = logit;
    #pragma unroll
    for (int off = 16; off; off >>= 1) mx = fmaxf(mx, __shfl_xor_sync(FULLMASK, mx, off));
    float ex = (lane < Kn) ? expf(logit - mx) : 0.f;
    float sm = ex;
    #pragma unroll
    for (int off = 16; off; off >>= 1) sm += __shfl_xor_sync(FULLMASK, sm, off);
    float att = ex / sm;
    if (lane < Kn) {
        sAtt[wid][lane] = att;
        sJ[wid][lane] = g_idx[r * Kn + lane];
    }
    __syncwarp();
    float acc0 = 0.f, acc1 = 0.f;
    const float* xb = g_xT + (size_t)(b << 12) * Cch;
    #pragma unroll 5
    for (int kk = 0; kk < Kn; kk++) {
        const float* p = xb + sJ[wid][kk] * Cch;
        float a = sAtt[wid][kk];
        acc0 = fmaf(a, p[lane], acc0);
        acc1 = fmaf(a, p[lane + 32], acc1);
    }
    size_t o0 = (size_t)b * (Cch * Np) + (size_t)lane * Np + (size_t)n;
    size_t o1 = o0 + (size_t)32 * Np;
    out[o0] = x[o0] + acc0;
    out[o1] = x[o1] + acc1;
}

// ---------------- launch ----------------------------------------------------
extern "C" void kernel_launch(void* const* d_in, const int* in_sizes, int n_in,
                              void* d_out, int out_size) {
    const float* xloc = (const float*)d_in[0];
    const float* x    = (const float*)d_in[1];
    const float* W1   = (const float*)d_in[2];
    const float* g1   = (const float*)d_in[3];
    const float* b1   = (const float*)d_in[4];
    const float* W2   = (const float*)d_in[5];
    const float* g2   = (const float*)d_in[6];
    const float* b2   = (const float*)d_in[7];
    const float* W3   = (const float*)d_in[8];
    const float* g3   = (const float*)d_in[9];
    const float* b3   = (const float*)d_in[10];
    float* out = (float*)d_out;

    size_t knnSmem = sizeof(float4) * Np +
                     sizeof(unsigned long long) * KNN_WARPS * QPW * CAND_MAX;
    cudaFuncSetAttribute(k_knn, cudaFuncAttributeMaxDynamicSharedMemorySize, (int)knnSmem);

    k_zero<<<1, 32>>>();                          // #1
    k_xt<<<dim3(Np / 32, Bz), 256>>>(x);          // #2
    k_init<<<128, 256>>>(xloc);                   // #3
    k_knn<<<dim3(37, Bz), KNN_TPB, knnSmem>>>();  // #4  <- profiled
    k_feat<<<512, 256>>>(W1);                     // #5
    k_l2<<<Mtot / 1024, 256>>>(g1, b1, W2);       // #6
    k_l3<<<Mtot / 1024, 256>>>(g2, b2, W3);       // #7
    k_out<<<Bz * Np / 8, 256>>>(x, g3, b3, out);  // #8
}

// round 7
// speedup vs baseline: 1.2279x; 1.1329x over previous
#include <cuda_runtime.h>
#include <cstdint>
#include <math.h>

#define FULLMASK 0xFFFFFFFFu

constexpr int Bz = 8, Np = 4096, Cch = 64, Kn = 30;
constexpr int Mtot = Bz * Np * Kn;           // 983040
constexpr float EPS_BN = 1e-5f;
constexpr float TINYc = 1e-20f;

constexpr int CAND_MAX = 192;
constexpr int KNN_TPB = 512;                 // 16 warps, 2 blocks/SM
constexpr int KNN_WARPS = KNN_TPB / 32;
constexpr int QPW = 2;                       // queries in flight per warp
constexpr int NGRP = Np / QPW;               // 2048 groups per batch

// ---------------- scratch ---------------------------------------------------
__device__ float4 g_pts4[Bz * Np];           // x,y,z, -0.5*|p|^2
__device__ float  g_xT[Bz * Np * Cch];
__device__ int    g_idx[Mtot];
__device__ float  g_h1[6 * Mtot];
__device__ float  g_h2[3 * Mtot];
__device__ float  g_h3[Mtot];
__device__ double g_stats[24];

// ---------------- K_zero (launch #1) ---------------------------------------
__global__ void k_zero() {
    if (threadIdx.x < 24) g_stats[threadIdx.x] = 0.0;
}

// ---------------- K_xt: tiled transpose x -> xT [B,N,C] (launch #2) --------
__global__ void __launch_bounds__(256) k_xt(const float* __restrict__ x) {
    __shared__ float s[64][33];
    int b = blockIdx.y;
    int n0 = blockIdx.x * 32;
    int lane = threadIdx.x & 31, w = threadIdx.x >> 5;
    #pragma unroll
    for (int i = 0; i < 8; i++) {
        int c = w * 8 + i;
        s[c][lane] = x[(((b << 6) + c) << 12) + n0 + lane];
    }
    __syncthreads();
    #pragma unroll
    for (int i = 0; i < 8; i++) {
        int e = i * 256 + threadIdx.x;
        int nl = e >> 6, c = e & 63;
        g_xT[(size_t)(((b << 12) + n0 + nl) << 6) + c] = s[c][nl];
    }
}

// ---------------- K_init: build pts4 with w = -0.5|p|^2 (launch #3) --------
__global__ void __launch_bounds__(256) k_init(const float* __restrict__ xloc) {
    int t = blockIdx.x * blockDim.x + threadIdx.x;
    int stride = gridDim.x * blockDim.x;
    for (int i = t; i < Bz * Np; i += stride) {
        int b = i >> 12, n = i & 4095;
        const float* p = xloc + b * 3 * Np;
        float px = p[n], py = p[Np + n], pz = p[2 * Np + n];
        float xx = fmaf(pz, pz, fmaf(py, py, px * px));
        g_pts4[i] = make_float4(px, py, pz, -0.5f * xx);
    }
}

// ---------------- K_knn (launch #4 -> profiled) ----------------------------
// score s(q,p) = q.p - 0.5|p|^2; pd = 2s - |q|^2, so s-order == pd-order.
__device__ __forceinline__ float sF(float4 q, float4 p) {
    return fmaf(q.z, p.z, fmaf(q.y, p.y, fmaf(q.x, p.x, p.w)));
}
__device__ __forceinline__ unsigned fkeyU(float f) {
    unsigned b = __float_as_uint(f);
    return b ^ ((unsigned)((int)b >> 31) | 0x80000000u);
}

__device__ __forceinline__ void rankWrite(const unsigned long long* cand, int C,
                                          int base, int lane) {
    if (C < Kn) {                            // astronomically rare fallback
        if (lane < Kn) g_idx[base + lane] = (int)(cand[0] & 0xFFFULL);
        if (lane < C)  g_idx[base + lane] = (int)(cand[lane] & 0xFFFULL);
        return;
    }
    for (int tb = 0; tb < C; tb += 128) {
        int t0 = tb + lane;
        unsigned long long v0 = (t0 < C)      ? cand[t0]      : 0ULL;
        unsigned long long v1 = (t0 + 32 < C) ? cand[t0 + 32] : 0ULL;
        unsigned long long v2 = (t0 + 64 < C) ? cand[t0 + 64] : 0ULL;
        unsigned long long v3 = (t0 + 96 < C) ? cand[t0 + 96] : 0ULL;
        int r0 = 0, r1 = 0, r2 = 0, r3 = 0;
        #pragma unroll 4
        for (int s = 0; s < C; s++) {
            unsigned long long w2 = cand[s];
            r0 += (w2 > v0); r1 += (w2 > v1);
            r2 += (w2 > v2); r3 += (w2 > v3);
        }
        if (t0 < C      && r0 < Kn) g_idx[base + r0] = (int)(v0 & 0xFFFULL);
        if (t0 + 32 < C && r1 < Kn) g_idx[base + r1] = (int)(v1 & 0xFFFULL);
        if (t0 + 64 < C && r2 < Kn) g_idx[base + r2] = (int)(v2 & 0xFFFULL);
        if (t0 + 96 < C && r3 < Kn) g_idx[base + r3] = (int)(v3 & 0xFFFULL);
    }
}

__global__ void __launch_bounds__(KNN_TPB, 2) k_knn() {
    extern __shared__ unsigned char smemRaw[];
    float4* sPts = reinterpret_cast<float4*>(smemRaw);
    unsigned long long* candBase =
        reinterpret_cast<unsigned long long*>(smemRaw + sizeof(float4) * Np);

    int b = blockIdx.y;
    const float4* gp = g_pts4 + b * Np;
    for (int i = threadIdx.x; i < Np; i += KNN_TPB) sPts[i] = gp[i];
    __syncthreads();

    int wid = threadIdx.x >> 5, lane = threadIdx.x & 31;
    unsigned long long* cand = candBase + (size_t)wid * QPW * CAND_MAX;
    unsigned laneLT = (lane == 31) ? 0x7FFFFFFFu : ((1u << lane) - 1u);

    for (int g = blockIdx.x * KNN_WARPS + wid; g < NGRP; g += gridDim.x * KNN_WARPS) {
        int n = g;                           // queries n, n+2048
        float4 q[QPW];
        #pragma unroll
        for (int qi = 0; qi < QPW; qi++) q[qi] = sPts[n + qi * NGRP];

        // --- sample pass: contiguous 512-pt window, per-lane top-2 ---------
        int sb = (n & 7) << 9;
        float m1[QPW], m2[QPW];
        #pragma unroll
        for (int qi = 0; qi < QPW; qi++) { m1[qi] = -3.4e38f; m2[qi] = -3.4e38f; }
        #pragma unroll 4
        for (int t = 0; t < 16; t++) {
            float4 p = sPts[sb + t * 32 + lane];
            #pragma unroll
            for (int qi = 0; qi < QPW; qi++) {
                float s = sF(q[qi], p);
                if (s > m2[qi]) {
                    if (s > m1[qi]) { m2[qi] = m1[qi]; m1[qi] = s; }
                    else m2[qi] = s;
                }
            }
        }
        // --- extract 8th & 16th largest per query --------------------------
        float T[QPW], Tr[QPW];
        for (int r = 0; r < 16; r++) {
            #pragma unroll
            for (int qi = 0; qi < QPW; qi++) {
                float v = m1[qi];
                #pragma unroll
                for (int o = 16; o; o >>= 1)
                    v = fmaxf(v, __shfl_xor_sync(FULLMASK, v, o));
                if (r == 7)  T[qi] = v;
                if (r == 15) Tr[qi] = v;
                unsigned wm = __ballot_sync(FULLMASK, m1[qi] == v);
                if (lane == __ffs(wm) - 1) { m1[qi] = m2[qi]; m2[qi] = -3.4e38f; }
            }
        }

        // --- main scan: 128 pts/iter, indices-only collect -----------------
        unsigned cnt[QPW] = {0, 0};
        for (int j0 = 0; j0 < Np; j0 += 128) {
            float4 p0 = sPts[j0 + lane];
            float4 p1 = sPts[j0 + 32 + lane];
            float4 p2 = sPts[j0 + 64 + lane];
            float4 p3 = sPts[j0 + 96 + lane];
            #pragma unroll
            for (int qi = 0; qi < QPW; qi++) {
                float s0 = sF(q[qi], p0), s1 = sF(q[qi], p1);
                float s2 = sF(q[qi], p2), s3 = sF(q[qi], p3);
                float Tq = T[qi];
                unsigned mk0 = __ballot_sync(FULLMASK, s0 > Tq);
                unsigned mk1 = __ballot_sync(FULLMASK, s1 > Tq);
                unsigned mk2 = __ballot_sync(FULLMASK, s2 > Tq);
                unsigned mk3 = __ballot_sync(FULLMASK, s3 > Tq);
                unsigned* cq32 = reinterpret_cast<unsigned*>(cand + qi * CAND_MAX);
                unsigned pos;
                if (s0 > Tq) { pos = cnt[qi] + __popc(mk0 & laneLT); if (pos < CAND_MAX) cq32[2 * pos] = j0 + lane; }
                cnt[qi] += __popc(mk0);
                if (s1 > Tq) { pos = cnt[qi] + __popc(mk1 & laneLT); if (pos < CAND_MAX) cq32[2 * pos] = j0 + 32 + lane; }
                cnt[qi] += __popc(mk1);
                if (s2 > Tq) { pos = cnt[qi] + __popc(mk2 & laneLT); if (pos < CAND_MAX) cq32[2 * pos] = j0 + 64 + lane; }
                cnt[qi] += __popc(mk2);
                if (s3 > Tq) { pos = cnt[qi] + __popc(mk3 & laneLT); if (pos < CAND_MAX) cq32[2 * pos] = j0 + 96 + lane; }
                cnt[qi] += __popc(mk3);
            }
        }

        // --- rare per-query retry with looser threshold --------------------
        #pragma unroll
        for (int qi = 0; qi < QPW; qi++) {
            if (cnt[qi] < Kn) {              // warp-uniform (from ballots)
                unsigned c = 0;
                float Tq = Tr[qi];
                float4 qq = q[qi];
                unsigned* cq32 = reinterpret_cast<unsigned*>(cand + qi * CAND_MAX);
                for (int j0 = 0; j0 < Np; j0 += 64) {
                    float s0 = sF(qq, sPts[j0 + lane]);
                    float s1 = sF(qq, sPts[j0 + 32 + lane]);
                    unsigned mk0 = __ballot_sync(FULLMASK, s0 > Tq);
                    unsigned mk1 = __ballot_sync(FULLMASK, s1 > Tq);
                    unsigned pos;
                    if (s0 > Tq) { pos = c + __popc(mk0 & laneLT); if (pos < CAND_MAX) cq32[2 * pos] = j0 + lane; }
                    c += __popc(mk0);
                    if (s1 > Tq) { pos = c + __popc(mk1 & laneLT); if (pos < CAND_MAX) cq32[2 * pos] = j0 + 32 + lane; }
                    c += __popc(mk1);
                }
                cnt[qi] = c;
            }
        }
        __syncwarp();

        // --- pack (key<<12 | idx) then rank-select top-30 ------------------
        #pragma unroll
        for (int qi = 0; qi < QPW; qi++) {
            int C = min((int)cnt[qi], CAND_MAX);
            unsigned long long* cq = cand + qi * CAND_MAX;
            unsigned* cq32 = reinterpret_cast<unsigned*>(cq);
            float4 qq = q[qi];
            for (int t = lane; t < C; t += 32) {
                unsigned j = cq32[2 * t];
                float s = sF(qq, sPts[j]);
                cq[t] = ((unsigned long long)fkeyU(s) << 12) | j;
            }
            __syncwarp();
            rankWrite(cq, C, (b * Np + n + qi * NGRP) * Kn, lane);
        }
        __syncwarp();
    }
}

// ---------------- block-level stat accumulation ----------------------------
template <int NV>
__device__ __forceinline__ void accumStats(const float* vals, float* sAcc, int statBase) {
    #pragma unroll
    for (int v = 0; v < NV; v++) {
        float x = vals[v];
        #pragma unroll
        for (int off = 16; off; off >>= 1) x += __shfl_down_sync(FULLMASK, x, off);
        if ((threadIdx.x & 31) == 0) atomicAdd(&sAcc[v], x);
    }
    __syncthreads();
    if (threadIdx.x < NV) atomicAdd(&g_stats[statBase + threadIdx.x], (double)sAcc[threadIdx.x]);
}

// ---------------- K_feat: spherical features + layer1 + stats --------------
__global__ void __launch_bounds__(256, 4) k_feat(const float* __restrict__ W1) {
    __shared__ float sW[36];
    __shared__ float sAcc[12];
    int tid = threadIdx.x;
    if (tid < 36) sW[tid] = W1[tid];
    if (tid < 12) sAcc[tid] = 0.f;
    __syncthreads();
    int wid = tid >> 5, lane = tid & 31;
    float acc[12];
    #pragma unroll
    for (int v = 0; v < 12; v++) acc[v] = 0.f;

    for (int i = 0; i < 8; i++) {
        int r = blockIdx.x * 64 + i * 8 + wid;
        int b = r >> 12;
        if (lane < Kn) {
            int e = r * Kn + lane;
            int j = g_idx[e];
            float4 pn = g_pts4[r];
            float4 pj = g_pts4[(b << 12) + j];
            float xr = pj.x - pn.x, yr = pj.y - pn.y, zr = pj.z - pn.z;
            float sxy2 = fmaf(yr, yr, xr * xr);
            float r2 = fmaf(zr, zr, sxy2);
            float rho = sqrtf(fmaxf(r2, TINYc));
            float sxy = sqrtf(fmaxf(sxy2, TINYc));
            float theta = (r2 < TINYc) ? 0.f : atan2f(zr, sxy);
            float phi = (sxy2 < TINYc) ? 0.f : atan2f(yr, xr);
            float mn = (rho + theta + phi) * (1.f / 3.f);
            float f[6] = {rho, theta, phi, rho - mn, theta - mn, phi - mn};
            #pragma unroll
            for (int o = 0; o < 6; o++) {
                float h = 0.f;
                #pragma unroll
                for (int i2 = 0; i2 < 6; i2++) h = fmaf(sW[o * 6 + i2], f[i2], h);
                g_h1[o * Mtot + e] = h;
                acc[o] += h; acc[6 + o] = fmaf(h, h, acc[6 + o]);
            }
        }
    }
    accumStats<12>(acc, sAcc, 0);
}

__device__ __forceinline__ float lrelu02(float t) { return t > 0.f ? t : 0.2f * t; }

// ---------------- K_l2: BN1 + lrelu + layer2 + stats (float4) --------------
__global__ void __launch_bounds__(256) k_l2(const float* __restrict__ gma,
                                            const float* __restrict__ bta,
                                            const float* __restrict__ W2) {
    __shared__ float sMu[6], sIs[6], sG[6], sB[6], sW[18], sAcc[6];
    int tid = threadIdx.x;
    if (tid < 6) {
        double s = g_stats[tid], sq = g_stats[6 + tid];
        double mu = s / (double)Mtot;
        double var = sq / (double)Mtot - mu * mu;
        sMu[tid] = (float)mu;
        sIs[tid] = (float)(1.0 / sqrt(var + (double)EPS_BN));
        sG[tid] = gma[tid]; sB[tid] = bta[tid];
        sAcc[tid] = 0.f;
    }
    if (tid < 18) sW[tid] = W2[tid];
    __syncthreads();
    int e4 = (blockIdx.x * 256 + tid) * 4;
    float4 a[6];
    #pragma unroll
    for (int i = 0; i < 6; i++) {
        float4 h = *reinterpret_cast<const float4*>(&g_h1[i * Mtot + e4]);
        float sc = sIs[i] * sG[i], mu = sMu[i], bb = sB[i];
        a[i].x = lrelu02(fmaf((h.x - mu), sc, bb));
        a[i].y = lrelu02(fmaf((h.y - mu), sc, bb));
        a[i].z = lrelu02(fmaf((h.z - mu), sc, bb));
        a[i].w = lrelu02(fmaf((h.w - mu), sc, bb));
    }
    float vals[6];
    #pragma unroll
    for (int o = 0; o < 3; o++) {
        float4 h = make_float4(0.f, 0.f, 0.f, 0.f);
        #pragma unroll
        for (int i = 0; i < 6; i++) {
            float w = sW[o * 6 + i];
            h.x = fmaf(w, a[i].x, h.x); h.y = fmaf(w, a[i].y, h.y);
            h.z = fmaf(w, a[i].z, h.z); h.w = fmaf(w, a[i].w, h.w);
        }
        *reinterpret_cast<float4*>(&g_h2[o * Mtot + e4]) = h;
        vals[o] = (h.x + h.y) + (h.z + h.w);
        vals[3 + o] = fmaf(h.x, h.x, h.y * h.y) + fmaf(h.z, h.z, h.w * h.w);
    }
    accumStats<6>(vals, sAcc, 12);
}

// ---------------- K_l3: BN2 + lrelu + layer3 + stats (float4) --------------
__global__ void __launch_bounds__(256) k_l3(const float* __restrict__ gma,
                                            const float* __restrict__ bta,
                                            const float* __restrict__ W3) {
    __shared__ float sMu[3], sIs[3], sG[3], sB[3], sW[3], sAcc[2];
    int tid = threadIdx.x;
    if (tid < 3) {
        double s = g_stats[12 + tid], sq = g_stats[15 + tid];
        double mu = s / (double)Mtot;
        double var = sq / (double)Mtot - mu * mu;
        sMu[tid] = (float)mu;
        sIs[tid] = (float)(1.0 / sqrt(var + (double)EPS_BN));
        sG[tid] = gma[tid]; sB[tid] = bta[tid];
        sW[tid] = W3[tid];
    }
    if (tid < 2) sAcc[tid] = 0.f;
    __syncthreads();
    int e4 = (blockIdx.x * 256 + tid) * 4;
    float4 h = make_float4(0.f, 0.f, 0.f, 0.f);
    #pragma unroll
    for (int i = 0; i < 3; i++) {
        float4 hv = *reinterpret_cast<const float4*>(&g_h2[i * Mtot + e4]);
        float sc = sIs[i] * sG[i], mu = sMu[i], bb = sB[i], w = sW[i];
        h.x = fmaf(w, lrelu02(fmaf((hv.x - mu), sc, bb)), h.x);
        h.y = fmaf(w, lrelu02(fmaf((hv.y - mu), sc, bb)), h.y);
        h.z = fmaf(w, lrelu02(fmaf((hv.z - mu), sc, bb)), h.z);
        h.w = fmaf(w, lrelu02(fmaf((hv.w - mu), sc, bb)), h.w);
    }
    *reinterpret_cast<float4*>(&g_h3[e4]) = h;
    float vals[2];
    vals[0] = (h.x + h.y) + (h.z + h.w);
    vals[1] = fmaf(h.x, h.x, h.y * h.y) + fmaf(h.z, h.z, h.w * h.w);
    accumStats<2>(vals, sAcc, 18);
}

// ---------------- K_out: BN3 + lrelu + softmax + aggregate -----------------
__global__ void __launch_bounds__(256) k_out(const float* __restrict__ x,
                                             const float* __restrict__ g3,
                                             const float* __restrict__ b3,
                                             float* __restrict__ out) {
    __shared__ float sAtt[8][Kn];
    __shared__ int sJ[8][Kn];
    __shared__ float sMu, sIs;
    int tid = threadIdx.x, wid = tid >> 5, lane = tid & 31;
    if (tid == 0) {
        double s = g_stats[18], sq = g_stats[19];
        double mu = s / (double)Mtot;
        double var = sq / (double)Mtot - mu * mu;
        sMu = (float)mu;
        sIs = (float)(1.0 / sqrt(var + (double)EPS_BN));
    }
    __syncthreads();
    int r = blockIdx.x * 8 + wid;
    int b = r >> 12, n = r & 4095;
    float gv = g3[0], bv = b3[0];
    float logit = -INFINITY;
    if (lane < Kn) {
        float h = g_h3[r * Kn + lane];
        float t = fmaf((h - sMu) * sIs, gv, bv);
        logit = t > 0.f ? t : 0.2f * t;
    }
    float mx = logit;
    #pragma unroll
    for (int off = 16; off; off >>= 1) mx = fmaxf(mx, __shfl_xor_sync(FULLMASK, mx, off));
    float ex = (lane < Kn) ? expf(logit - mx) : 0.f;
    float sm = ex;
    #pragma unroll
    for (int off = 16; off; off >>= 1) sm += __shfl_xor_sync(FULLMASK, sm, off);
    float att = ex / sm;
    if (lane < Kn) {
        sAtt[wid][lane] = att;
        sJ[wid][lane] = g_idx[r * Kn + lane];
    }
    __syncwarp();
    float acc0 = 0.f, acc1 = 0.f;
    const float* xb = g_xT + (size_t)(b << 12) * Cch;
    #pragma unroll 5
    for (int kk = 0; kk < Kn; kk++) {
        const float* p = xb + sJ[wid][kk] * Cch;
        float a = sAtt[wid][kk];
        acc0 = fmaf(a, p[lane], acc0);
        acc1 = fmaf(a, p[lane + 32], acc1);
    }
    size_t o0 = (size_t)b * (Cch * Np) + (size_t)lane * Np + (size_t)n;
    size_t o1 = o0 + (size_t)32 * Np;
    out[o0] = x[o0] + acc0;
    out[o1] = x[o1] + acc1;
}

// ---------------- launch ----------------------------------------------------
extern "C" void kernel_launch(void* const* d_in, const int* in_sizes, int n_in,
                              void* d_out, int out_size) {
    const float* xloc = (const float*)d_in[0];
    const float* x    = (const float*)d_in[1];
    const float* W1   = (const float*)d_in[2];
    const float* g1   = (const float*)d_in[3];
    const float* b1   = (const float*)d_in[4];
    const float* W2   = (const float*)d_in[5];
    const float* g2   = (const float*)d_in[6];
    const float* b2   = (const float*)d_in[7];
    const float* W3   = (const float*)d_in[8];
    const float* g3   = (const float*)d_in[9];
    const float* b3   = (const float*)d_in[10];
    float* out = (float*)d_out;

    size_t knnSmem = sizeof(float4) * Np +
                     sizeof(unsigned long long) * KNN_WARPS * QPW * CAND_MAX;  // 112 KB
    cudaFuncSetAttribute(k_knn, cudaFuncAttributeMaxDynamicSharedMemorySize, (int)knnSmem);

    k_zero<<<1, 32>>>();                          // #1
    k_xt<<<dim3(Np / 32, Bz), 256>>>(x);          // #2
    k_init<<<128, 256>>>(xloc);                   // #3
    k_knn<<<dim3(37, Bz), KNN_TPB, knnSmem>>>();  // #4  <- profiled
    k_feat<<<512, 256>>>(W1);                     // #5
    k_l2<<<Mtot / 1024, 256>>>(g1, b1, W2);       // #6
    k_l3<<<Mtot / 1024, 256>>>(g2, b2, W3);       // #7
    k_out<<<Bz * Np / 8, 256>>>(x, g3, b3, out);  // #8
}

// round 9
// speedup vs baseline: 1.3548x; 1.1033x over previous
#include <cuda_runtime.h>
#include <cstdint>
#include <math.h>

#define FULLMASK 0xFFFFFFFFu

constexpr int Bz = 8, Np = 4096, Cch = 64, Kn = 30;
constexpr int Mtot = Bz * Np * Kn;           // 983040
constexpr float EPS_BN = 1e-5f;
constexpr float TINYc = 1e-20f;

constexpr int CAND_MAX = 192;
constexpr int KNN_TPB = 512;                 // 16 warps, 2 blocks/SM
constexpr int KNN_WARPS = KNN_TPB / 32;
constexpr int QPW = 2;
constexpr int NGRP = Np / QPW;               // 2048

// ---------------- scratch ---------------------------------------------------
__device__ float4 g_pts4[Bz * Np];           // x,y,z, -0.5*|p|^2
__device__ float  g_xT[Bz * Np * Cch];
__device__ int    g_idx[Mtot];
__device__ float  g_h1[6 * Mtot];
__device__ float  g_h2[3 * Mtot];
__device__ float  g_h3[Mtot];
__device__ double g_stats[24];

// ---------------- packed f32x2 helpers --------------------------------------
__device__ __forceinline__ unsigned long long fma2(unsigned long long a,
                                                   unsigned long long b,
                                                   unsigned long long c) {
    unsigned long long d;
    asm("fma.rn.f32x2 %0, %1, %2, %3;" : "=l"(d) : "l"(a), "l"(b), "l"(c));
    return d;
}
__device__ __forceinline__ unsigned long long pack2(float lo, float hi) {
    unsigned long long v;
    asm("mov.b64 %0, {%1, %2};" : "=l"(v) : "f"(lo), "f"(hi));
    return v;
}
__device__ __forceinline__ void unpack2(unsigned long long v, float& lo, float& hi) {
    asm("mov.b64 {%0, %1}, %2;" : "=f"(lo), "=f"(hi) : "l"(v));
}

// ---------------- K_zero (launch #1) ---------------------------------------
__global__ void k_zero() {
    if (threadIdx.x < 24) g_stats[threadIdx.x] = 0.0;
}

// ---------------- K_xt: tiled transpose x -> xT [B,N,C] (launch #2) --------
__global__ void __launch_bounds__(256) k_xt(const float* __restrict__ x) {
    __shared__ float s[64][33];
    int b = blockIdx.y;
    int n0 = blockIdx.x * 32;
    int lane = threadIdx.x & 31, w = threadIdx.x >> 5;
    #pragma unroll
    for (int i = 0; i < 8; i++) {
        int c = w * 8 + i;
        s[c][lane] = x[(((b << 6) + c) << 12) + n0 + lane];
    }
    __syncthreads();
    #pragma unroll
    for (int i = 0; i < 8; i++) {
        int e = i * 256 + threadIdx.x;
        int nl = e >> 6, c = e & 63;
        g_xT[(size_t)(((b << 12) + n0 + nl) << 6) + c] = s[c][nl];
    }
}

// ---------------- K_init: build pts4 with w = -0.5|p|^2 (launch #3) --------
__global__ void __launch_bounds__(256) k_init(const float* __restrict__ xloc) {
    int t = blockIdx.x * blockDim.x + threadIdx.x;
    int stride = gridDim.x * blockDim.x;
    for (int i = t; i < Bz * Np; i += stride) {
        int b = i >> 12, n = i & 4095;
        const float* p = xloc + b * 3 * Np;
        float px = p[n], py = p[Np + n], pz = p[2 * Np + n];
        float xx = fmaf(pz, pz, fmaf(py, py, px * px));
        g_pts4[i] = make_float4(px, py, pz, -0.5f * xx);
    }
}

// ---------------- K_knn (launch #4 -> profiled) ----------------------------
__device__ __forceinline__ unsigned fkeyU(float f) {
    unsigned b = __float_as_uint(f);
    return b ^ ((unsigned)((int)b >> 31) | 0x80000000u);
}

__device__ __forceinline__ void rankWrite(const unsigned long long* cand, int C,
                                          int base, int lane) {
    if (C < Kn) {                            // astronomically rare fallback
        if (lane < Kn) g_idx[base + lane] = (int)(cand[0] & 0xFFFULL);
        if (lane < C)  g_idx[base + lane] = (int)(cand[lane] & 0xFFFULL);
        return;
    }
    for (int tb = 0; tb < C; tb += 128) {
        int t0 = tb + lane;
        unsigned long long v0 = (t0 < C)      ? cand[t0]      : 0ULL;
        unsigned long long v1 = (t0 + 32 < C) ? cand[t0 + 32] : 0ULL;
        unsigned long long v2 = (t0 + 64 < C) ? cand[t0 + 64] : 0ULL;
        unsigned long long v3 = (t0 + 96 < C) ? cand[t0 + 96] : 0ULL;
        int r0 = 0, r1 = 0, r2 = 0, r3 = 0;
        #pragma unroll 4
        for (int s = 0; s < C; s++) {
            unsigned long long w2 = cand[s];
            r0 += (w2 > v0); r1 += (w2 > v1);
            r2 += (w2 > v2); r3 += (w2 > v3);
        }
        if (t0 < C      && r0 < Kn) g_idx[base + r0] = (int)(v0 & 0xFFFULL);
        if (t0 + 32 < C && r1 < Kn) g_idx[base + r1] = (int)(v1 & 0xFFFULL);
        if (t0 + 64 < C && r2 < Kn) g_idx[base + r2] = (int)(v2 & 0xFFFULL);
        if (t0 + 96 < C && r3 < Kn) g_idx[base + r3] = (int)(v3 & 0xFFFULL);
    }
}

__global__ void __launch_bounds__(KNN_TPB, 2) k_knn() {
    extern __shared__ unsigned char smemRaw[];
    float* xs = reinterpret_cast<float*>(smemRaw);
    float* ys = xs + Np;
    float* zs = ys + Np;
    float* ws = zs + Np;
    unsigned long long* candBase =
        reinterpret_cast<unsigned long long*>(smemRaw + 4u * Np * sizeof(float));
    const float2* xs2 = reinterpret_cast<const float2*>(xs);
    const float2* ys2 = reinterpret_cast<const float2*>(ys);
    const float2* zs2 = reinterpret_cast<const float2*>(zs);
    const float2* ws2 = reinterpret_cast<const float2*>(ws);

    int b = blockIdx.y;
    const float4* gp = g_pts4 + b * Np;
    for (int i = threadIdx.x; i < Np; i += KNN_TPB) {
        float4 p = gp[i];
        xs[i] = p.x; ys[i] = p.y; zs[i] = p.z; ws[i] = p.w;
    }
    __syncthreads();

    int wid = threadIdx.x >> 5, lane = threadIdx.x & 31;
    unsigned long long* cand = candBase + (size_t)wid * QPW * CAND_MAX;
    unsigned laneLT = (lane == 31) ? 0x7FFFFFFFu : ((1u << lane) - 1u);

    for (int g = blockIdx.x * KNN_WARPS + wid; g < NGRP; g += gridDim.x * KNN_WARPS) {
        int n = g;                           // queries n, n+2048
        float qsx[QPW], qsy[QPW], qsz[QPW];
        unsigned long long qX[QPW], qY[QPW], qZ[QPW];
        #pragma unroll
        for (int qi = 0; qi < QPW; qi++) {
            int nq = n + qi * NGRP;
            qsx[qi] = xs[nq]; qsy[qi] = ys[nq]; qsz[qi] = zs[nq];
            qX[qi] = pack2(qsx[qi], qsx[qi]);
            qY[qi] = pack2(qsy[qi], qsy[qi]);
            qZ[qi] = pack2(qsz[qi], qsz[qi]);
        }

        // --- sample pass: contiguous 512-pt window, packed, per-lane top-2 -
        int sb2 = (n & 7) << 8;              // float2 index base
        float m1[QPW], m2[QPW];
        #pragma unroll
        for (int qi = 0; qi < QPW; qi++) { m1[qi] = -3.4e38f; m2[qi] = -3.4e38f; }
        #pragma unroll 2
        for (int t = 0; t < 8; t++) {
            int i2 = sb2 + t * 32 + lane;
            float2 px = xs2[i2], py = ys2[i2], pz = zs2[i2], pw = ws2[i2];
            unsigned long long X = pack2(px.x, px.y), Y = pack2(py.x, py.y);
            unsigned long long Z = pack2(pz.x, pz.y), Wp = pack2(pw.x, pw.y);
            #pragma unroll
            for (int qi = 0; qi < QPW; qi++) {
                unsigned long long s2 = fma2(qZ[qi], Z, fma2(qY[qi], Y, fma2(qX[qi], X, Wp)));
                float slo, shi; unpack2(s2, slo, shi);
                if (slo > m2[qi]) {
                    if (slo > m1[qi]) { m2[qi] = m1[qi]; m1[qi] = slo; } else m2[qi] = slo;
                }
                if (shi > m2[qi]) {
                    if (shi > m1[qi]) { m2[qi] = m1[qi]; m1[qi] = shi; } else m2[qi] = shi;
                }
            }
        }
        // --- extract 8th & 16th largest (of 64 lane-top2) per query --------
        float T[QPW], Tr[QPW];
        for (int r = 0; r < 16; r++) {
            #pragma unroll
            for (int qi = 0; qi < QPW; qi++) {
                float v = m1[qi];
                #pragma unroll
                for (int o = 16; o; o >>= 1)
                    v = fmaxf(v, __shfl_xor_sync(FULLMASK, v, o));
                if (r == 7)  T[qi] = v;
                if (r == 15) Tr[qi] = v;
                unsigned wm = __ballot_sync(FULLMASK, m1[qi] == v);
                if (lane == __ffs(wm) - 1) { m1[qi] = m2[qi]; m2[qi] = -3.4e38f; }
            }
        }

        // --- main scan: 64 pts/iter packed; store hit-masks only -----------
        #pragma unroll 2
        for (int j0 = 0; j0 < Np; j0 += 64) {
            int i2 = (j0 >> 1) + lane;
            float2 px = xs2[i2], py = ys2[i2], pz = zs2[i2], pw = ws2[i2];
            unsigned long long X = pack2(px.x, px.y), Y = pack2(py.x, py.y);
            unsigned long long Z = pack2(pz.x, pz.y), Wp = pack2(pw.x, pw.y);
            #pragma unroll
            for (int qi = 0; qi < QPW; qi++) {
                unsigned long long s2 = fma2(qZ[qi], Z, fma2(qY[qi], Y, fma2(qX[qi], X, Wp)));
                float slo, shi; unpack2(s2, slo, shi);
                unsigned mlo = __ballot_sync(FULLMASK, slo > T[qi]);
                unsigned mhi = __ballot_sync(FULLMASK, shi > T[qi]);
                if (lane == 0) {
                    unsigned* mw = reinterpret_cast<unsigned*>(cand + qi * CAND_MAX);
                    mw[(j0 >> 5)] = mlo;         // word 2*blk
                    mw[(j0 >> 5) + 1] = mhi;     // word 2*blk+1
                }
            }
        }
        __syncwarp();

        // --- extraction: masks -> candidate index list ---------------------
        int cnt[QPW];
        #pragma unroll
        for (int qi = 0; qi < QPW; qi++) {
            unsigned* mw = reinterpret_cast<unsigned*>(cand + qi * CAND_MAX);
            unsigned w0 = mw[lane], w1 = mw[lane + 32];
            unsigned w2 = mw[lane + 64], w3 = mw[lane + 96];
            __syncwarp();
            int tot = __popc(w0) + __popc(w1) + __popc(w2) + __popc(w3);
            int incl = tot;
            #pragma unroll
            for (int o = 1; o < 32; o <<= 1) {
                int v = __shfl_up_sync(FULLMASK, incl, o);
                if (lane >= o) incl += v;
            }
            int Cq = __shfl_sync(FULLMASK, incl, 31);
            int pos = incl - tot;
            unsigned* cq32 = mw;
            unsigned wv[4] = {w0, w1, w2, w3};
            #pragma unroll
            for (int k = 0; k < 4; k++) {
                int word = lane + 32 * k;
                int pbase = ((word >> 1) << 6) + (word & 1);
                unsigned v = wv[k];
                while (v) {
                    int bit = __ffs(v) - 1;
                    v &= v - 1;
                    if (pos < CAND_MAX) cq32[2 * pos] = pbase + 2 * bit;
                    pos++;
                }
            }
            cnt[qi] = Cq;
            __syncwarp();
        }

        // --- rare per-query retry with looser threshold --------------------
        #pragma unroll
        for (int qi = 0; qi < QPW; qi++) {
            if (cnt[qi] < Kn) {
                unsigned c = 0;
                float Tq = Tr[qi];
                float qx = qsx[qi], qy = qsy[qi], qz = qsz[qi];
                unsigned* cq32 = reinterpret_cast<unsigned*>(cand + qi * CAND_MAX);
                for (int j0 = 0; j0 < Np; j0 += 32) {
                    int j = j0 + lane;
                    float s = fmaf(qz, zs[j], fmaf(qy, ys[j], fmaf(qx, xs[j], ws[j])));
                    unsigned mk = __ballot_sync(FULLMASK, s > Tq);
                    if (s > Tq) {
                        unsigned p = c + __popc(mk & laneLT);
                        if (p < CAND_MAX) cq32[2 * p] = j;
                    }
                    c += __popc(mk);
                }
                cnt[qi] = c;
            }
        }
        __syncwarp();

        // --- pack (key<<12 | idx) then rank-select top-30 ------------------
        #pragma unroll
        for (int qi = 0; qi < QPW; qi++) {
            int C = min(cnt[qi], CAND_MAX);
            unsigned long long* cq = cand + qi * CAND_MAX;
            unsigned* cq32 = reinterpret_cast<unsigned*>(cq);
            float qx = qsx[qi], qy = qsy[qi], qz = qsz[qi];
            for (int t = lane; t < C; t += 32) {
                unsigned j = cq32[2 * t];
                float s = fmaf(qz, zs[j], fmaf(qy, ys[j], fmaf(qx, xs[j], ws[j])));
                cq[t] = ((unsigned long long)fkeyU(s) << 12) | j;
            }
            __syncwarp();
            rankWrite(cq, C, (b * Np + n + qi * NGRP) * Kn, lane);
        }
        __syncwarp();
    }
}

// ---------------- block-level stat accumulation ----------------------------
template <int NV>
__device__ __forceinline__ void accumStats(const float* vals, float* sAcc, int statBase) {
    #pragma unroll
    for (int v = 0; v < NV; v++) {
        float x = vals[v];
        #pragma unroll
        for (int off = 16; off; off >>= 1) x += __shfl_down_sync(FULLMASK, x, off);
        if ((threadIdx.x & 31) == 0) atomicAdd(&sAcc[v], x);
    }
    __syncthreads();
    if (threadIdx.x < NV) atomicAdd(&g_stats[statBase + threadIdx.x], (double)sAcc[threadIdx.x]);
}

// ---------------- K_feat: spherical features + layer1 + stats --------------
__global__ void __launch_bounds__(256, 4) k_feat(const float* __restrict__ W1) {
    __shared__ float sW[36];
    __shared__ float sAcc[12];
    int tid = threadIdx.x;
    if (tid < 36) sW[tid] = W1[tid];
    if (tid < 12) sAcc[tid] = 0.f;
    __syncthreads();
    int wid = tid >> 5, lane = tid & 31;
    float acc[12];
    #pragma unroll
    for (int v = 0; v < 12; v++) acc[v] = 0.f;

    for (int i = 0; i < 8; i++) {
        int r = blockIdx.x * 64 + i * 8 + wid;
        int b = r >> 12;
        if (lane < Kn) {
            int e = r * Kn + lane;
            int j = g_idx[e];
            float4 pn = g_pts4[r];
            float4 pj = g_pts4[(b << 12) + j];
            float xr = pj.x - pn.x, yr = pj.y - pn.y, zr = pj.z - pn.z;
            float sxy2 = fmaf(yr, yr, xr * xr);
            float r2 = fmaf(zr, zr, sxy2);
            float rho = sqrtf(fmaxf(r2, TINYc));
            float sxy = sqrtf(fmaxf(sxy2, TINYc));
            float theta = (r2 < TINYc) ? 0.f : atan2f(zr, sxy);
            float phi = (sxy2 < TINYc) ? 0.f : atan2f(yr, xr);
            float mn = (rho + theta + phi) * (1.f / 3.f);
            float f[6] = {rho, theta, phi, rho - mn, theta - mn, phi - mn};
            #pragma unroll
            for (int o = 0; o < 6; o++) {
                float h = 0.f;
                #pragma unroll
                for (int i2 = 0; i2 < 6; i2++) h = fmaf(sW[o * 6 + i2], f[i2], h);
                g_h1[o * Mtot + e] = h;
                acc[o] += h; acc[6 + o] = fmaf(h, h, acc[6 + o]);
            }
        }
    }
    accumStats<12>(acc, sAcc, 0);
}

__device__ __forceinline__ float lrelu02(float t) { return t > 0.f ? t : 0.2f * t; }

// ---------------- K_l2: BN1 + lrelu + layer2 + stats (float4) --------------
__global__ void __launch_bounds__(256) k_l2(const float* __restrict__ gma,
                                            const float* __restrict__ bta,
                                            const float* __restrict__ W2) {
    __shared__ float sMu[6], sIs[6], sG[6], sB[6], sW[18], sAcc[6];
    int tid = threadIdx.x;
    if (tid < 6) {
        double s = g_stats[tid], sq = g_stats[6 + tid];
        double mu = s / (double)Mtot;
        double var = sq / (double)Mtot - mu * mu;
        sMu[tid] = (float)mu;
        sIs[tid] = (float)(1.0 / sqrt(var + (double)EPS_BN));
        sG[tid] = gma[tid]; sB[tid] = bta[tid];
        sAcc[tid] = 0.f;
    }
    if (tid < 18) sW[tid] = W2[tid];
    __syncthreads();
    int e4 = (blockIdx.x * 256 + tid) * 4;
    float4 a[6];
    #pragma unroll
    for (int i = 0; i < 6; i++) {
        float4 h = *reinterpret_cast<const float4*>(&g_h1[i * Mtot + e4]);
        float sc = sIs[i] * sG[i], mu = sMu[i], bb = sB[i];
        a[i].x = lrelu02(fmaf((h.x - mu), sc, bb));
        a[i].y = lrelu02(fmaf((h.y - mu), sc, bb));
        a[i].z = lrelu02(fmaf((h.z - mu), sc, bb));
        a[i].w = lrelu02(fmaf((h.w - mu), sc, bb));
    }
    float vals[6];
    #pragma unroll
    for (int o = 0; o < 3; o++) {
        float4 h = make_float4(0.f, 0.f, 0.f, 0.f);
        #pragma unroll
        for (int i = 0; i < 6; i++) {
            float w = sW[o * 6 + i];
            h.x = fmaf(w, a[i].x, h.x); h.y = fmaf(w, a[i].y, h.y);
            h.z = fmaf(w, a[i].z, h.z); h.w = fmaf(w, a[i].w, h.w);
        }
        *reinterpret_cast<float4*>(&g_h2[o * Mtot + e4]) = h;
        vals[o] = (h.x + h.y) + (h.z + h.w);
        vals[3 + o] = fmaf(h.x, h.x, h.y * h.y) + fmaf(h.z, h.z, h.w * h.w);
    }
    accumStats<6>(vals, sAcc, 12);
}

// ---------------- K_l3: BN2 + lrelu + layer3 + stats (float4) --------------
__global__ void __launch_bounds__(256) k_l3(const float* __restrict__ gma,
                                            const float* __restrict__ bta,
                                            const float* __restrict__ W3) {
    __shared__ float sMu[3], sIs[3], sG[3], sB[3], sW[3], sAcc[2];
    int tid = threadIdx.x;
    if (tid < 3) {
        double s = g_stats[12 + tid], sq = g_stats[15 + tid];
        double mu = s / (double)Mtot;
        double var = sq / (double)Mtot - mu * mu;
        sMu[tid] = (float)mu;
        sIs[tid] = (float)(1.0 / sqrt(var + (double)EPS_BN));
        sG[tid] = gma[tid]; sB[tid] = bta[tid];
        sW[tid] = W3[tid];
    }
    if (tid < 2) sAcc[tid] = 0.f;
    __syncthreads();
    int e4 = (blockIdx.x * 256 + tid) * 4;
    float4 h = make_float4(0.f, 0.f, 0.f, 0.f);
    #pragma unroll
    for (int i = 0; i < 3; i++) {
        float4 hv = *reinterpret_cast<const float4*>(&g_h2[i * Mtot + e4]);
        float sc = sIs[i] * sG[i], mu = sMu[i], bb = sB[i], w = sW[i];
        h.x = fmaf(w, lrelu02(fmaf((hv.x - mu), sc, bb)), h.x);
        h.y = fmaf(w, lrelu02(fmaf((hv.y - mu), sc, bb)), h.y);
        h.z = fmaf(w, lrelu02(fmaf((hv.z - mu), sc, bb)), h.z);
        h.w = fmaf(w, lrelu02(fmaf((hv.w - mu), sc, bb)), h.w);
    }
    *reinterpret_cast<float4*>(&g_h3[e4]) = h;
    float vals[2];
    vals[0] = (h.x + h.y) + (h.z + h.w);
    vals[1] = fmaf(h.x, h.x, h.y * h.y) + fmaf(h.z, h.z, h.w * h.w);
    accumStats<2>(vals, sAcc, 18);
}

// ---------------- K_out: BN3 + lrelu + softmax + aggregate -----------------
__global__ void __launch_bounds__(256) k_out(const float* __restrict__ x,
                                             const float* __restrict__ g3,
                                             const float* __restrict__ b3,
                                             float* __restrict__ out) {
    __shared__ float sAtt[8][Kn];
    __shared__ int sJ[8][Kn];
    __shared__ float sMu, sIs;
    int tid = threadIdx.x, wid = tid >> 5, lane = tid & 31;
    if (tid == 0) {
        double s = g_stats[18], sq = g_stats[19];
        double mu = s / (double)Mtot;
        double var = sq / (double)Mtot - mu * mu;
        sMu = (float)mu;
        sIs = (float)(1.0 / sqrt(var + (double)EPS_BN));
    }
    __syncthreads();
    int r = blockIdx.x * 8 + wid;
    int b = r >> 12, n = r & 4095;
    float gv = g3[0], bv = b3[0];
    float logit = -INFINITY;
    if (lane < Kn) {
        float h = g_h3[r * Kn + lane];
        float t = fmaf((h - sMu) * sIs, gv, bv);
        logit = t > 0.f ? t : 0.2f * t;
    }
    float mx = logit;
    #pragma unroll
    for (int off = 16; off; off >>= 1) mx = fmaxf(mx, __shfl_xor_sync(FULLMASK, mx, off));
    float ex = (lane < Kn) ? expf(logit - mx) : 0.f;
    float sm = ex;
    #pragma unroll
    for (int off = 16; off; off >>= 1) sm += __shfl_xor_sync(FULLMASK, sm, off);
    float att = ex / sm;
    if (lane < Kn) {
        sAtt[wid][lane] = att;
        sJ[wid][lane] = g_idx[r * Kn + lane];
    }
    __syncwarp();
    float acc0 = 0.f, acc1 = 0.f;
    const float* xb = g_xT + (size_t)(b << 12) * Cch;
    #pragma unroll 5
    for (int kk = 0; kk < Kn; kk++) {
        const float* p = xb + sJ[wid][kk] * Cch;
        float a = sAtt[wid][kk];
        acc0 = fmaf(a, p[lane], acc0);
        acc1 = fmaf(a, p[lane + 32], acc1);
    }
    size_t o0 = (size_t)b * (Cch * Np) + (size_t)lane * Np + (size_t)n;
    size_t o1 = o0 + (size_t)32 * Np;
    out[o0] = x[o0] + acc0;
    out[o1] = x[o1] + acc1;
}

// ---------------- launch ----------------------------------------------------
extern "C" void kernel_launch(void* const* d_in, const int* in_sizes, int n_in,
                              void* d_out, int out_size) {
    const float* xloc = (const float*)d_in[0];
    const float* x    = (const float*)d_in[1];
    const float* W1   = (const float*)d_in[2];
    const float* g1   = (const float*)d_in[3];
    const float* b1   = (const float*)d_in[4];
    const float* W2   = (const float*)d_in[5];
    const float* g2   = (const float*)d_in[6];
    const float* b2   = (const float*)d_in[7];
    const float* W3   = (const float*)d_in[8];
    const float* g3   = (const float*)d_in[9];
    const float* b3   = (const float*)d_in[10];
    float* out = (float*)d_out;

    size_t knnSmem = 4u * Np * sizeof(float) +
                     sizeof(unsigned long long) * KNN_WARPS * QPW * CAND_MAX;  // 112 KB
    cudaFuncSetAttribute(k_knn, cudaFuncAttributeMaxDynamicSharedMemorySize, (int)knnSmem);

    k_zero<<<1, 32>>>();                          // #1
    k_xt<<<dim3(Np / 32, Bz), 256>>>(x);          // #2
    k_init<<<128, 256>>>(xloc);                   // #3
    k_knn<<<dim3(37, Bz), KNN_TPB, knnSmem>>>();  // #4  <- profiled
    k_feat<<<512, 256>>>(W1);                     // #5
    k_l2<<<Mtot / 1024, 256>>>(g1, b1, W2);       // #6
    k_l3<<<Mtot / 1024, 256>>>(g2, b2, W3);       // #7
    k_out<<<Bz * Np / 8, 256>>>(x, g3, b3, out);  // #8
}

// round 10
// speedup vs baseline: 1.4362x; 1.0601x over previous
#include <cuda_runtime.h>
#include <cstdint>
#include <math.h>

#define FULLMASK 0xFFFFFFFFu

constexpr int Bz = 8, Np = 4096, Cch = 64, Kn = 30;
constexpr int Mtot = Bz * Np * Kn;           // 983040
constexpr float EPS_BN = 1e-5f;
constexpr float TINYc = 1e-20f;

constexpr int CAND_MAX = 192;
constexpr int KNN_TPB = 512;                 // 16 warps, 2 blocks/SM
constexpr int KNN_WARPS = KNN_TPB / 32;
constexpr int QPW = 2;
constexpr int NGRP = Np / QPW;               // 2048

// ---------------- scratch ---------------------------------------------------
__device__ float4 g_pts4[Bz * Np];           // x,y,z, -0.5*|p|^2
__device__ float  g_xT[Bz * Np * Cch];
__device__ int    g_idx[Mtot];
__device__ float  g_h1[6 * Mtot];
__device__ float  g_h2[3 * Mtot];
__device__ float  g_h3[Mtot];
__device__ double g_stats[24];
__device__ int    g_work[Bz];                // work-stealing counters

// ---------------- packed f32x2 helpers --------------------------------------
__device__ __forceinline__ unsigned long long fma2(unsigned long long a,
                                                   unsigned long long b,
                                                   unsigned long long c) {
    unsigned long long d;
    asm("fma.rn.f32x2 %0, %1, %2, %3;" : "=l"(d) : "l"(a), "l"(b), "l"(c));
    return d;
}
__device__ __forceinline__ unsigned long long pack2(float lo, float hi) {
    unsigned long long v;
    asm("mov.b64 %0, {%1, %2};" : "=l"(v) : "f"(lo), "f"(hi));
    return v;
}
__device__ __forceinline__ void unpack2(unsigned long long v, float& lo, float& hi) {
    asm("mov.b64 {%0, %1}, %2;" : "=f"(lo), "=f"(hi) : "l"(v));
}

// ---------------- K_zero (launch #1): stats + work counters ----------------
__global__ void k_zero() {
    if (threadIdx.x < 24) g_stats[threadIdx.x] = 0.0;
    if (threadIdx.x >= 24 && threadIdx.x < 24 + Bz) g_work[threadIdx.x - 24] = 0;
}

// ---------------- K_xt: tiled transpose x -> xT [B,N,C] (launch #2) --------
__global__ void __launch_bounds__(256) k_xt(const float* __restrict__ x) {
    __shared__ float s[64][33];
    int b = blockIdx.y;
    int n0 = blockIdx.x * 32;
    int lane = threadIdx.x & 31, w = threadIdx.x >> 5;
    #pragma unroll
    for (int i = 0; i < 8; i++) {
        int c = w * 8 + i;
        s[c][lane] = x[(((b << 6) + c) << 12) + n0 + lane];
    }
    __syncthreads();
    #pragma unroll
    for (int i = 0; i < 8; i++) {
        int e = i * 256 + threadIdx.x;
        int nl = e >> 6, c = e & 63;
        g_xT[(size_t)(((b << 12) + n0 + nl) << 6) + c] = s[c][nl];
    }
}

// ---------------- K_init: build pts4 with w = -0.5|p|^2 (launch #3) --------
__global__ void __launch_bounds__(256) k_init(const float* __restrict__ xloc) {
    int t = blockIdx.x * blockDim.x + threadIdx.x;
    int stride = gridDim.x * blockDim.x;
    for (int i = t; i < Bz * Np; i += stride) {
        int b = i >> 12, n = i & 4095;
        const float* p = xloc + b * 3 * Np;
        float px = p[n], py = p[Np + n], pz = p[2 * Np + n];
        float xx = fmaf(pz, pz, fmaf(py, py, px * px));
        g_pts4[i] = make_float4(px, py, pz, -0.5f * xx);
    }
}

// ---------------- K_knn (launch #4 -> profiled) ----------------------------
__device__ __forceinline__ unsigned fkeyU(float f) {
    unsigned b = __float_as_uint(f);
    return b ^ ((unsigned)((int)b >> 31) | 0x80000000u);
}

__device__ __forceinline__ void rankWrite(const unsigned long long* cand, int C,
                                          int base, int lane) {
    if (C < Kn) {                            // astronomically rare fallback
        if (lane < Kn) g_idx[base + lane] = (int)(cand[0] & 0xFFFULL);
        if (lane < C)  g_idx[base + lane] = (int)(cand[lane] & 0xFFFULL);
        return;
    }
    if (C <= 64) {                           // ~50% of queries: 2-cand path
        unsigned long long v0 = (lane < C)      ? cand[lane]      : 0ULL;
        unsigned long long v1 = (lane + 32 < C) ? cand[lane + 32] : 0ULL;
        int r0 = 0, r1 = 0;
        #pragma unroll 4
        for (int s = 0; s < C; s++) {
            unsigned long long w2 = cand[s];
            r0 += (w2 > v0); r1 += (w2 > v1);
        }
        if (lane < C      && r0 < Kn) g_idx[base + r0] = (int)(v0 & 0xFFFULL);
        if (lane + 32 < C && r1 < Kn) g_idx[base + r1] = (int)(v1 & 0xFFFULL);
        return;
    }
    for (int tb = 0; tb < C; tb += 128) {
        int t0 = tb + lane;
        unsigned long long v0 = (t0 < C)      ? cand[t0]      : 0ULL;
        unsigned long long v1 = (t0 + 32 < C) ? cand[t0 + 32] : 0ULL;
        unsigned long long v2 = (t0 + 64 < C) ? cand[t0 + 64] : 0ULL;
        unsigned long long v3 = (t0 + 96 < C) ? cand[t0 + 96] : 0ULL;
        int r0 = 0, r1 = 0, r2 = 0, r3 = 0;
        #pragma unroll 4
        for (int s = 0; s < C; s++) {
            unsigned long long w2 = cand[s];
            r0 += (w2 > v0); r1 += (w2 > v1);
            r2 += (w2 > v2); r3 += (w2 > v3);
        }
        if (t0 < C      && r0 < Kn) g_idx[base + r0] = (int)(v0 & 0xFFFULL);
        if (t0 + 32 < C && r1 < Kn) g_idx[base + r1] = (int)(v1 & 0xFFFULL);
        if (t0 + 64 < C && r2 < Kn) g_idx[base + r2] = (int)(v2 & 0xFFFULL);
        if (t0 + 96 < C && r3 < Kn) g_idx[base + r3] = (int)(v3 & 0xFFFULL);
    }
}

__global__ void __launch_bounds__(KNN_TPB, 2) k_knn() {
    extern __shared__ unsigned char smemRaw[];
    float* xs = reinterpret_cast<float*>(smemRaw);
    float* ys = xs + Np;
    float* zs = ys + Np;
    float* ws = zs + Np;
    unsigned long long* candBase =
        reinterpret_cast<unsigned long long*>(smemRaw + 4u * Np * sizeof(float));
    const float2* xs2 = reinterpret_cast<const float2*>(xs);
    const float2* ys2 = reinterpret_cast<const float2*>(ys);
    const float2* zs2 = reinterpret_cast<const float2*>(zs);
    const float2* ws2 = reinterpret_cast<const float2*>(ws);

    int b = blockIdx.y;
    const float4* gp = g_pts4 + b * Np;
    for (int i = threadIdx.x; i < Np; i += KNN_TPB) {
        float4 p = gp[i];
        xs[i] = p.x; ys[i] = p.y; zs[i] = p.z; ws[i] = p.w;
    }
    __syncthreads();

    int wid = threadIdx.x >> 5, lane = threadIdx.x & 31;
    unsigned long long* cand = candBase + (size_t)wid * QPW * CAND_MAX;
    unsigned laneLT = (lane == 31) ? 0x7FFFFFFFu : ((1u << lane) - 1u);

    // --- work-stealing group loop (prefetched steal hides ATOMG latency) ---
    int fetched = 0;
    if (lane == 0) fetched = atomicAdd(&g_work[b], 1);
    int nextg = __shfl_sync(FULLMASK, fetched, 0);

    while (nextg < NGRP) {
        int n = nextg;                       // queries n, n+2048
        if (lane == 0) fetched = atomicAdd(&g_work[b], 1);   // prefetch next

        float qsx[QPW], qsy[QPW], qsz[QPW];
        unsigned long long qX[QPW], qY[QPW], qZ[QPW];
        #pragma unroll
        for (int qi = 0; qi < QPW; qi++) {
            int nq = n + qi * NGRP;
            qsx[qi] = xs[nq]; qsy[qi] = ys[nq]; qsz[qi] = zs[nq];
            qX[qi] = pack2(qsx[qi], qsx[qi]);
            qY[qi] = pack2(qsy[qi], qsy[qi]);
            qZ[qi] = pack2(qsz[qi], qsz[qi]);
        }

        // --- sample pass: contiguous 512-pt window, packed, per-lane top-2 -
        int sb2 = (n & 7) << 8;              // float2 index base
        float m1[QPW], m2[QPW];
        #pragma unroll
        for (int qi = 0; qi < QPW; qi++) { m1[qi] = -3.4e38f; m2[qi] = -3.4e38f; }
        #pragma unroll 2
        for (int t = 0; t < 8; t++) {
            int i2 = sb2 + t * 32 + lane;
            float2 px = xs2[i2], py = ys2[i2], pz = zs2[i2], pw = ws2[i2];
            unsigned long long X = pack2(px.x, px.y), Y = pack2(py.x, py.y);
            unsigned long long Z = pack2(pz.x, pz.y), Wp = pack2(pw.x, pw.y);
            #pragma unroll
            for (int qi = 0; qi < QPW; qi++) {
                unsigned long long s2 = fma2(qZ[qi], Z, fma2(qY[qi], Y, fma2(qX[qi], X, Wp)));
                float slo, shi; unpack2(s2, slo, shi);
                if (slo > m2[qi]) {
                    if (slo > m1[qi]) { m2[qi] = m1[qi]; m1[qi] = slo; } else m2[qi] = slo;
                }
                if (shi > m2[qi]) {
                    if (shi > m1[qi]) { m2[qi] = m1[qi]; m1[qi] = shi; } else m2[qi] = shi;
                }
            }
        }
        // --- extract 8th & 16th largest (of 64 lane-top2) per query --------
        float T[QPW], Tr[QPW];
        for (int r = 0; r < 16; r++) {
            #pragma unroll
            for (int qi = 0; qi < QPW; qi++) {
                float v = m1[qi];
                #pragma unroll
                for (int o = 16; o; o >>= 1)
                    v = fmaxf(v, __shfl_xor_sync(FULLMASK, v, o));
                if (r == 7)  T[qi] = v;
                if (r == 15) Tr[qi] = v;
                unsigned wm = __ballot_sync(FULLMASK, m1[qi] == v);
                if (lane == __ffs(wm) - 1) { m1[qi] = m2[qi]; m2[qi] = -3.4e38f; }
            }
        }

        // --- main scan: 64 pts/iter packed; store hit-masks only -----------
        #pragma unroll 2
        for (int j0 = 0; j0 < Np; j0 += 64) {
            int i2 = (j0 >> 1) + lane;
            float2 px = xs2[i2], py = ys2[i2], pz = zs2[i2], pw = ws2[i2];
            unsigned long long X = pack2(px.x, px.y), Y = pack2(py.x, py.y);
            unsigned long long Z = pack2(pz.x, pz.y), Wp = pack2(pw.x, pw.y);
            #pragma unroll
            for (int qi = 0; qi < QPW; qi++) {
                unsigned long long s2 = fma2(qZ[qi], Z, fma2(qY[qi], Y, fma2(qX[qi], X, Wp)));
                float slo, shi; unpack2(s2, slo, shi);
                unsigned mlo = __ballot_sync(FULLMASK, slo > T[qi]);
                unsigned mhi = __ballot_sync(FULLMASK, shi > T[qi]);
                if (lane == 0) {
                    unsigned* mw = reinterpret_cast<unsigned*>(cand + qi * CAND_MAX);
                    mw[(j0 >> 5)] = mlo;
                    mw[(j0 >> 5) + 1] = mhi;
                }
            }
        }
        __syncwarp();

        // --- extraction: masks -> candidate index list ---------------------
        int cnt[QPW];
        #pragma unroll
        for (int qi = 0; qi < QPW; qi++) {
            unsigned* mw = reinterpret_cast<unsigned*>(cand + qi * CAND_MAX);
            unsigned w0 = mw[lane], w1 = mw[lane + 32];
            unsigned w2 = mw[lane + 64], w3 = mw[lane + 96];
            __syncwarp();
            int tot = __popc(w0) + __popc(w1) + __popc(w2) + __popc(w3);
            int incl = tot;
            #pragma unroll
            for (int o = 1; o < 32; o <<= 1) {
                int v = __shfl_up_sync(FULLMASK, incl, o);
                if (lane >= o) incl += v;
            }
            int Cq = __shfl_sync(FULLMASK, incl, 31);
            int pos = incl - tot;
            unsigned* cq32 = mw;
            unsigned wv[4] = {w0, w1, w2, w3};
            #pragma unroll
            for (int k = 0; k < 4; k++) {
                int word = lane + 32 * k;
                int pbase = ((word >> 1) << 6) + (word & 1);
                unsigned v = wv[k];
                while (v) {
                    int bit = __ffs(v) - 1;
                    v &= v - 1;
                    if (pos < CAND_MAX) cq32[2 * pos] = pbase + 2 * bit;
                    pos++;
                }
            }
            cnt[qi] = Cq;
            __syncwarp();
        }

        // --- rare per-query retry with looser threshold --------------------
        #pragma unroll
        for (int qi = 0; qi < QPW; qi++) {
            if (cnt[qi] < Kn) {
                unsigned c = 0;
                float Tq = Tr[qi];
                float qx = qsx[qi], qy = qsy[qi], qz = qsz[qi];
                unsigned* cq32 = reinterpret_cast<unsigned*>(cand + qi * CAND_MAX);
                for (int j0 = 0; j0 < Np; j0 += 32) {
                    int j = j0 + lane;
                    float s = fmaf(qz, zs[j], fmaf(qy, ys[j], fmaf(qx, xs[j], ws[j])));
                    unsigned mk = __ballot_sync(FULLMASK, s > Tq);
                    if (s > Tq) {
                        unsigned p = c + __popc(mk & laneLT);
                        if (p < CAND_MAX) cq32[2 * p] = j;
                    }
                    c += __popc(mk);
                }
                cnt[qi] = c;
            }
        }
        __syncwarp();

        // --- pack (key<<12 | idx) then rank-select top-30 ------------------
        #pragma unroll
        for (int qi = 0; qi < QPW; qi++) {
            int C = min(cnt[qi], CAND_MAX);
            unsigned long long* cq = cand + qi * CAND_MAX;
            unsigned* cq32 = reinterpret_cast<unsigned*>(cq);
            float qx = qsx[qi], qy = qsy[qi], qz = qsz[qi];
            for (int t = lane; t < C; t += 32) {
                unsigned j = cq32[2 * t];
                float s = fmaf(qz, zs[j], fmaf(qy, ys[j], fmaf(qx, xs[j], ws[j])));
                cq[t] = ((unsigned long long)fkeyU(s) << 12) | j;
            }
            __syncwarp();
            rankWrite(cq, C, (b * Np + n + qi * NGRP) * Kn, lane);
        }
        __syncwarp();

        nextg = __shfl_sync(FULLMASK, fetched, 0);
    }
}

// ---------------- block-level stat accumulation ----------------------------
template <int NV>
__device__ __forceinline__ void accumStats(const float* vals, float* sAcc, int statBase) {
    #pragma unroll
    for (int v = 0; v < NV; v++) {
        float x = vals[v];
        #pragma unroll
        for (int off = 16; off; off >>= 1) x += __shfl_down_sync(FULLMASK, x, off);
        if ((threadIdx.x & 31) == 0) atomicAdd(&sAcc[v], x);
    }
    __syncthreads();
    if (threadIdx.x < NV) atomicAdd(&g_stats[statBase + threadIdx.x], (double)sAcc[threadIdx.x]);
}

// ---------------- K_feat: spherical features + layer1 + stats --------------
__global__ void __launch_bounds__(256, 4) k_feat(const float* __restrict__ W1) {
    __shared__ float sW[36];
    __shared__ float sAcc[12];
    int tid = threadIdx.x;
    if (tid < 36) sW[tid] = W1[tid];
    if (tid < 12) sAcc[tid] = 0.f;
    __syncthreads();
    int wid = tid >> 5, lane = tid & 31;
    float acc[12];
    #pragma unroll
    for (int v = 0; v < 12; v++) acc[v] = 0.f;

    for (int i = 0; i < 8; i++) {
        int r = blockIdx.x * 64 + i * 8 + wid;
        int b = r >> 12;
        if (lane < Kn) {
            int e = r * Kn + lane;
            int j = g_idx[e];
            float4 pn = g_pts4[r];
            float4 pj = g_pts4[(b << 12) + j];
            float xr = pj.x - pn.x, yr = pj.y - pn.y, zr = pj.z - pn.z;
            float sxy2 = fmaf(yr, yr, xr * xr);
            float r2 = fmaf(zr, zr, sxy2);
            float rho = sqrtf(fmaxf(r2, TINYc));
            float sxy = sqrtf(fmaxf(sxy2, TINYc));
            float theta = (r2 < TINYc) ? 0.f : atan2f(zr, sxy);
            float phi = (sxy2 < TINYc) ? 0.f : atan2f(yr, xr);
            float mn = (rho + theta + phi) * (1.f / 3.f);
            float f[6] = {rho, theta, phi, rho - mn, theta - mn, phi - mn};
            #pragma unroll
            for (int o = 0; o < 6; o++) {
                float h = 0.f;
                #pragma unroll
                for (int i2 = 0; i2 < 6; i2++) h = fmaf(sW[o * 6 + i2], f[i2], h);
                g_h1[o * Mtot + e] = h;
                acc[o] += h; acc[6 + o] = fmaf(h, h, acc[6 + o]);
            }
        }
    }
    accumStats<12>(acc, sAcc, 0);
}

__device__ __forceinline__ float lrelu02(float t) { return t > 0.f ? t : 0.2f * t; }

// ---------------- K_l2: BN1 + lrelu + layer2 + stats (float4) --------------
__global__ void __launch_bounds__(256) k_l2(const float* __restrict__ gma,
                                            const float* __restrict__ bta,
                                            const float* __restrict__ W2) {
    __shared__ float sMu[6], sIs[6], sG[6], sB[6], sW[18], sAcc[6];
    int tid = threadIdx.x;
    if (tid < 6) {
        double s = g_stats[tid], sq = g_stats[6 + tid];
        double mu = s / (double)Mtot;
        double var = sq / (double)Mtot - mu * mu;
        sMu[tid] = (float)mu;
        sIs[tid] = (float)(1.0 / sqrt(var + (double)EPS_BN));
        sG[tid] = gma[tid]; sB[tid] = bta[tid];
        sAcc[tid] = 0.f;
    }
    if (tid < 18) sW[tid] = W2[tid];
    __syncthreads();
    int e4 = (blockIdx.x * 256 + tid) * 4;
    float4 a[6];
    #pragma unroll
    for (int i = 0; i < 6; i++) {
        float4 h = *reinterpret_cast<const float4*>(&g_h1[i * Mtot + e4]);
        float sc = sIs[i] * sG[i], mu = sMu[i], bb = sB[i];
        a[i].x = lrelu02(fmaf((h.x - mu), sc, bb));
        a[i].y = lrelu02(fmaf((h.y - mu), sc, bb));
        a[i].z = lrelu02(fmaf((h.z - mu), sc, bb));
        a[i].w = lrelu02(fmaf((h.w - mu), sc, bb));
    }
    float vals[6];
    #pragma unroll
    for (int o = 0; o < 3; o++) {
        float4 h = make_float4(0.f, 0.f, 0.f, 0.f);
        #pragma unroll
        for (int i = 0; i < 6; i++) {
            float w = sW[o * 6 + i];
            h.x = fmaf(w, a[i].x, h.x); h.y = fmaf(w, a[i].y, h.y);
            h.z = fmaf(w, a[i].z, h.z); h.w = fmaf(w, a[i].w, h.w);
        }
        *reinterpret_cast<float4*>(&g_h2[o * Mtot + e4]) = h;
        vals[o] = (h.x + h.y) + (h.z + h.w);
        vals[3 + o] = fmaf(h.x, h.x, h.y * h.y) + fmaf(h.z, h.z, h.w * h.w);
    }
    accumStats<6>(vals, sAcc, 12);
}

// ---------------- K_l3: BN2 + lrelu + layer3 + stats (float4) --------------
__global__ void __launch_bounds__(256) k_l3(const float* __restrict__ gma,
                                            const float* __restrict__ bta,
                                            const float* __restrict__ W3) {
    __shared__ float sMu[3], sIs[3], sG[3], sB[3], sW[3], sAcc[2];
    int tid = threadIdx.x;
    if (tid < 3) {
        double s = g_stats[12 + tid], sq = g_stats[15 + tid];
        double mu = s / (double)Mtot;
        double var = sq / (double)Mtot - mu * mu;
        sMu[tid] = (float)mu;
        sIs[tid] = (float)(1.0 / sqrt(var + (double)EPS_BN));
        sG[tid] = gma[tid]; sB[tid] = bta[tid];
        sW[tid] = W3[tid];
    }
    if (tid < 2) sAcc[tid] = 0.f;
    __syncthreads();
    int e4 = (blockIdx.x * 256 + tid) * 4;
    float4 h = make_float4(0.f, 0.f, 0.f, 0.f);
    #pragma unroll
    for (int i = 0; i < 3; i++) {
        float4 hv = *reinterpret_cast<const float4*>(&g_h2[i * Mtot + e4]);
        float sc = sIs[i] * sG[i], mu = sMu[i], bb = sB[i], w = sW[i];
        h.x = fmaf(w, lrelu02(fmaf((hv.x - mu), sc, bb)), h.x);
        h.y = fmaf(w, lrelu02(fmaf((hv.y - mu), sc, bb)), h.y);
        h.z = fmaf(w, lrelu02(fmaf((hv.z - mu), sc, bb)), h.z);
        h.w = fmaf(w, lrelu02(fmaf((hv.w - mu), sc, bb)), h.w);
    }
    *reinterpret_cast<float4*>(&g_h3[e4]) = h;
    float vals[2];
    vals[0] = (h.x + h.y) + (h.z + h.w);
    vals[1] = fmaf(h.x, h.x, h.y * h.y) + fmaf(h.z, h.z, h.w * h.w);
    accumStats<2>(vals, sAcc, 18);
}

// ---------------- K_out: BN3 + lrelu + softmax + aggregate -----------------
__global__ void __launch_bounds__(256) k_out(const float* __restrict__ x,
                                             const float* __restrict__ g3,
                                             const float* __restrict__ b3,
                                             float* __restrict__ out) {
    __shared__ float sAtt[8][Kn];
    __shared__ int sJ[8][Kn];
    __shared__ float sMu, sIs;
    int tid = threadIdx.x, wid = tid >> 5, lane = tid & 31;
    if (tid == 0) {
        double s = g_stats[18], sq = g_stats[19];
        double mu = s / (double)Mtot;
        double var = sq / (double)Mtot - mu * mu;
        sMu = (float)mu;
        sIs = (float)(1.0 / sqrt(var + (double)EPS_BN));
    }
    __syncthreads();
    int r = blockIdx.x * 8 + wid;
    int b = r >> 12, n = r & 4095;
    float gv = g3[0], bv = b3[0];
    float logit = -INFINITY;
    if (lane < Kn) {
        float h = g_h3[r * Kn + lane];
        float t = fmaf((h - sMu) * sIs, gv, bv);
        logit = t > 0.f ? t : 0.2f * t;
    }
    float mx = logit;
    #pragma unroll
    for (int off = 16; off; off >>= 1) mx = fmaxf(mx, __shfl_xor_sync(FULLMASK, mx, off));
    float ex = (lane < Kn) ? expf(logit - mx) : 0.f;
    float sm = ex;
    #pragma unroll
    for (int off = 16; off; off >>= 1) sm += __shfl_xor_sync(FULLMASK, sm, off);
    float att = ex / sm;
    if (lane < Kn) {
        sAtt[wid][lane] = att;
        sJ[wid][lane] = g_idx[r * Kn + lane];
    }
    __syncwarp();
    float acc0 = 0.f, acc1 = 0.f;
    const float* xb = g_xT + (size_t)(b << 12) * Cch;
    #pragma unroll 5
    for (int kk = 0; kk < Kn; kk++) {
        const float* p = xb + sJ[wid][kk] * Cch;
        float a = sAtt[wid][kk];
        acc0 = fmaf(a, p[lane], acc0);
        acc1 = fmaf(a, p[lane + 32], acc1);
    }
    size_t o0 = (size_t)b * (Cch * Np) + (size_t)lane * Np + (size_t)n;
    size_t o1 = o0 + (size_t)32 * Np;
    out[o0] = x[o0] + acc0;
    out[o1] = x[o1] + acc1;
}

// ---------------- launch ----------------------------------------------------
extern "C" void kernel_launch(void* const* d_in, const int* in_sizes, int n_in,
                              void* d_out, int out_size) {
    const float* xloc = (const float*)d_in[0];
    const float* x    = (const float*)d_in[1];
    const float* W1   = (const float*)d_in[2];
    const float* g1   = (const float*)d_in[3];
    const float* b1   = (const float*)d_in[4];
    const float* W2   = (const float*)d_in[5];
    const float* g2   = (const float*)d_in[6];
    const float* b2   = (const float*)d_in[7];
    const float* W3   = (const float*)d_in[8];
    const float* g3   = (const float*)d_in[9];
    const float* b3   = (const float*)d_in[10];
    float* out = (float*)d_out;

    size_t knnSmem = 4u * Np * sizeof(float) +
                     sizeof(unsigned long long) * KNN_WARPS * QPW * CAND_MAX;  // 112 KB
    cudaFuncSetAttribute(k_knn, cudaFuncAttributeMaxDynamicSharedMemorySize, (int)knnSmem);

    k_zero<<<1, 32>>>();                          // #1
    k_xt<<<dim3(Np / 32, Bz), 256>>>(x);          // #2
    k_init<<<128, 256>>>(xloc);                   // #3
    k_knn<<<dim3(37, Bz), KNN_TPB, knnSmem>>>();  // #4  <- profiled
    k_feat<<<512, 256>>>(W1);                     // #5
    k_l2<<<Mtot / 1024, 256>>>(g1, b1, W2);       // #6
    k_l3<<<Mtot / 1024, 256>>>(g2, b2, W3);       // #7
    k_out<<<Bz * Np / 8, 256>>>(x, g3, b3, out);  // #8
}

// round 11
// speedup vs baseline: 1.4975x; 1.0427x over previous
#include <cuda_runtime.h>
#include <cstdint>
#include <math.h>

#define FULLMASK 0xFFFFFFFFu

constexpr int Bz = 8, Np = 4096, Cch = 64, Kn = 30;
constexpr int Mtot = Bz * Np * Kn;           // 983040
constexpr float EPS_BN = 1e-5f;
constexpr float TINYc = 1e-20f;

constexpr int CAND_MAX = 192;
constexpr int KNN_TPB = 512;                 // 16 warps, 2 blocks/SM
constexpr int KNN_WARPS = KNN_TPB / 32;
constexpr int QPW = 2;
constexpr int NGRP = Np / QPW;               // 2048

// ---------------- scratch ---------------------------------------------------
__device__ float4 g_pts4[Bz * Np];           // x,y,z, -0.5*|p|^2
__device__ float  g_xT[Bz * Np * Cch];
__device__ int    g_idx[Mtot];
__device__ float  g_h1[6 * Mtot];
__device__ float  g_h2[3 * Mtot];
__device__ float  g_h3[Mtot];
__device__ double g_stats[24];
__device__ int    g_work[Bz];                // work-stealing counters

// ---------------- packed f32x2 helpers --------------------------------------
__device__ __forceinline__ unsigned long long fma2(unsigned long long a,
                                                   unsigned long long b,
                                                   unsigned long long c) {
    unsigned long long d;
    asm("fma.rn.f32x2 %0, %1, %2, %3;" : "=l"(d) : "l"(a), "l"(b), "l"(c));
    return d;
}
__device__ __forceinline__ unsigned long long pack2(float lo, float hi) {
    unsigned long long v;
    asm("mov.b64 %0, {%1, %2};" : "=l"(v) : "f"(lo), "f"(hi));
    return v;
}
__device__ __forceinline__ void unpack2(unsigned long long v, float& lo, float& hi) {
    asm("mov.b64 {%0, %1}, %2;" : "=f"(lo), "=f"(hi) : "l"(v));
}

// ---------------- K_zero (launch #1): stats + work counters ----------------
__global__ void k_zero() {
    if (threadIdx.x < 24) g_stats[threadIdx.x] = 0.0;
    if (threadIdx.x >= 24 && threadIdx.x < 24 + Bz) g_work[threadIdx.x - 24] = 0;
}

// ---------------- K_xt: transpose x -> xT AND build pts4 (launch #2) -------
__global__ void __launch_bounds__(256) k_xt(const float* __restrict__ x,
                                            const float* __restrict__ xloc) {
    __shared__ float s[64][33];
    int b = blockIdx.y;
    int n0 = blockIdx.x * 32;
    int lane = threadIdx.x & 31, w = threadIdx.x >> 5;
    #pragma unroll
    for (int i = 0; i < 8; i++) {
        int c = w * 8 + i;
        s[c][lane] = x[(((b << 6) + c) << 12) + n0 + lane];
    }
    if (threadIdx.x < 32) {                  // fused pts4 build for these 32 n's
        int n = n0 + threadIdx.x;
        const float* p = xloc + b * 3 * Np;
        float px = p[n], py = p[Np + n], pz = p[2 * Np + n];
        float xx = fmaf(pz, pz, fmaf(py, py, px * px));
        g_pts4[(b << 12) + n] = make_float4(px, py, pz, -0.5f * xx);
    }
    __syncthreads();
    #pragma unroll
    for (int i = 0; i < 8; i++) {
        int e = i * 256 + threadIdx.x;
        int nl = e >> 6, c = e & 63;
        g_xT[(size_t)(((b << 12) + n0 + nl) << 6) + c] = s[c][nl];
    }
}

// ---------------- K_knn (launch #3) ----------------------------------------
__device__ __forceinline__ unsigned fkeyU(float f) {
    unsigned b = __float_as_uint(f);
    return b ^ ((unsigned)((int)b >> 31) | 0x80000000u);
}

__device__ __forceinline__ void rankWrite(const unsigned long long* cand, int C,
                                          int base, int lane) {
    if (C < Kn) {                            // astronomically rare fallback
        if (lane < Kn) g_idx[base + lane] = (int)(cand[0] & 0xFFFULL);
        if (lane < C)  g_idx[base + lane] = (int)(cand[lane] & 0xFFFULL);
        return;
    }
    if (C <= 64) {                           // common path: 2-cand/lane
        unsigned long long v0 = (lane < C)      ? cand[lane]      : 0ULL;
        unsigned long long v1 = (lane + 32 < C) ? cand[lane + 32] : 0ULL;
        int r0 = 0, r1 = 0;
        #pragma unroll 4
        for (int s = 0; s < C; s++) {
            unsigned long long w2 = cand[s];
            r0 += (w2 > v0); r1 += (w2 > v1);
        }
        if (lane < C      && r0 < Kn) g_idx[base + r0] = (int)(v0 & 0xFFFULL);
        if (lane + 32 < C && r1 < Kn) g_idx[base + r1] = (int)(v1 & 0xFFFULL);
        return;
    }
    for (int tb = 0; tb < C; tb += 128) {
        int t0 = tb + lane;
        unsigned long long v0 = (t0 < C)      ? cand[t0]      : 0ULL;
        unsigned long long v1 = (t0 + 32 < C) ? cand[t0 + 32] : 0ULL;
        unsigned long long v2 = (t0 + 64 < C) ? cand[t0 + 64] : 0ULL;
        unsigned long long v3 = (t0 + 96 < C) ? cand[t0 + 96] : 0ULL;
        int r0 = 0, r1 = 0, r2 = 0, r3 = 0;
        #pragma unroll 4
        for (int s = 0; s < C; s++) {
            unsigned long long w2 = cand[s];
            r0 += (w2 > v0); r1 += (w2 > v1);
            r2 += (w2 > v2); r3 += (w2 > v3);
        }
        if (t0 < C      && r0 < Kn) g_idx[base + r0] = (int)(v0 & 0xFFFULL);
        if (t0 + 32 < C && r1 < Kn) g_idx[base + r1] = (int)(v1 & 0xFFFULL);
        if (t0 + 64 < C && r2 < Kn) g_idx[base + r2] = (int)(v2 & 0xFFFULL);
        if (t0 + 96 < C && r3 < Kn) g_idx[base + r3] = (int)(v3 & 0xFFFULL);
    }
}

__global__ void __launch_bounds__(KNN_TPB, 2) k_knn() {
    extern __shared__ unsigned char smemRaw[];
    float* xs = reinterpret_cast<float*>(smemRaw);
    float* ys = xs + Np;
    float* zs = ys + Np;
    float* ws = zs + Np;
    unsigned long long* candBase =
        reinterpret_cast<unsigned long long*>(smemRaw + 4u * Np * sizeof(float));
    const float2* xs2 = reinterpret_cast<const float2*>(xs);
    const float2* ys2 = reinterpret_cast<const float2*>(ys);
    const float2* zs2 = reinterpret_cast<const float2*>(zs);
    const float2* ws2 = reinterpret_cast<const float2*>(ws);

    int b = blockIdx.y;
    const float4* gp = g_pts4 + b * Np;
    for (int i = threadIdx.x; i < Np; i += KNN_TPB) {
        float4 p = gp[i];
        xs[i] = p.x; ys[i] = p.y; zs[i] = p.z; ws[i] = p.w;
    }
    __syncthreads();

    int wid = threadIdx.x >> 5, lane = threadIdx.x & 31;
    unsigned long long* cand = candBase + (size_t)wid * QPW * CAND_MAX;
    unsigned laneLT = (lane == 31) ? 0x7FFFFFFFu : ((1u << lane) - 1u);

    // --- work-stealing group loop (prefetched steal hides ATOMG latency) ---
    int fetched = 0;
    if (lane == 0) fetched = atomicAdd(&g_work[b], 1);
    int nextg = __shfl_sync(FULLMASK, fetched, 0);

    while (nextg < NGRP) {
        int n = nextg;                       // queries n, n+2048
        if (lane == 0) fetched = atomicAdd(&g_work[b], 1);   // prefetch next

        float qsx[QPW], qsy[QPW], qsz[QPW];
        unsigned long long qX[QPW], qY[QPW], qZ[QPW];
        #pragma unroll
        for (int qi = 0; qi < QPW; qi++) {
            int nq = n + qi * NGRP;
            qsx[qi] = xs[nq]; qsy[qi] = ys[nq]; qsz[qi] = zs[nq];
            qX[qi] = pack2(qsx[qi], qsx[qi]);
            qY[qi] = pack2(qsy[qi], qsy[qi]);
            qZ[qi] = pack2(qsz[qi], qsz[qi]);
        }

        // --- sample pass: contiguous 512-pt window, packed, per-lane top-2 -
        int sb2 = (n & 7) << 8;              // float2 index base
        float m1[QPW], m2[QPW];
        #pragma unroll
        for (int qi = 0; qi < QPW; qi++) { m1[qi] = -3.4e38f; m2[qi] = -3.4e38f; }
        #pragma unroll 2
        for (int t = 0; t < 8; t++) {
            int i2 = sb2 + t * 32 + lane;
            float2 px = xs2[i2], py = ys2[i2], pz = zs2[i2], pw = ws2[i2];
            unsigned long long X = pack2(px.x, px.y), Y = pack2(py.x, py.y);
            unsigned long long Z = pack2(pz.x, pz.y), Wp = pack2(pw.x, pw.y);
            #pragma unroll
            for (int qi = 0; qi < QPW; qi++) {
                unsigned long long s2 = fma2(qZ[qi], Z, fma2(qY[qi], Y, fma2(qX[qi], X, Wp)));
                float slo, shi; unpack2(s2, slo, shi);
                if (slo > m2[qi]) {
                    if (slo > m1[qi]) { m2[qi] = m1[qi]; m1[qi] = slo; } else m2[qi] = slo;
                }
                if (shi > m2[qi]) {
                    if (shi > m1[qi]) { m2[qi] = m1[qi]; m1[qi] = shi; } else m2[qi] = shi;
                }
            }
        }
        // --- extract 8th largest per query (Tr computed lazily on retry) ---
        float T[QPW];
        for (int r = 0; r < 8; r++) {
            #pragma unroll
            for (int qi = 0; qi < QPW; qi++) {
                float v = m1[qi];
                #pragma unroll
                for (int o = 16; o; o >>= 1)
                    v = fmaxf(v, __shfl_xor_sync(FULLMASK, v, o));
                if (r == 7) T[qi] = v;
                unsigned wm = __ballot_sync(FULLMASK, m1[qi] == v);
                if (lane == __ffs(wm) - 1) { m1[qi] = m2[qi]; m2[qi] = -3.4e38f; }
            }
        }

        // --- main scan: 64 pts/iter packed; store hit-masks only -----------
        #pragma unroll 2
        for (int j0 = 0; j0 < Np; j0 += 64) {
            int i2 = (j0 >> 1) + lane;
            float2 px = xs2[i2], py = ys2[i2], pz = zs2[i2], pw = ws2[i2];
            unsigned long long X = pack2(px.x, px.y), Y = pack2(py.x, py.y);
            unsigned long long Z = pack2(pz.x, pz.y), Wp = pack2(pw.x, pw.y);
            #pragma unroll
            for (int qi = 0; qi < QPW; qi++) {
                unsigned long long s2 = fma2(qZ[qi], Z, fma2(qY[qi], Y, fma2(qX[qi], X, Wp)));
                float slo, shi; unpack2(s2, slo, shi);
                unsigned mlo = __ballot_sync(FULLMASK, slo > T[qi]);
                unsigned mhi = __ballot_sync(FULLMASK, shi > T[qi]);
                if (lane == 0) {
                    unsigned* mw = reinterpret_cast<unsigned*>(cand + qi * CAND_MAX);
                    mw[(j0 >> 5)] = mlo;
                    mw[(j0 >> 5) + 1] = mhi;
                }
            }
        }
        __syncwarp();

        // --- extraction: masks -> candidate index list ---------------------
        int cnt[QPW];
        #pragma unroll
        for (int qi = 0; qi < QPW; qi++) {
            unsigned* mw = reinterpret_cast<unsigned*>(cand + qi * CAND_MAX);
            unsigned w0 = mw[lane], w1 = mw[lane + 32];
            unsigned w2 = mw[lane + 64], w3 = mw[lane + 96];
            __syncwarp();
            int tot = __popc(w0) + __popc(w1) + __popc(w2) + __popc(w3);
            int incl = tot;
            #pragma unroll
            for (int o = 1; o < 32; o <<= 1) {
                int v = __shfl_up_sync(FULLMASK, incl, o);
                if (lane >= o) incl += v;
            }
            int Cq = __shfl_sync(FULLMASK, incl, 31);
            int pos = incl - tot;
            unsigned* cq32 = mw;
            unsigned wv[4] = {w0, w1, w2, w3};
            #pragma unroll
            for (int k = 0; k < 4; k++) {
                int word = lane + 32 * k;
                int pbase = ((word >> 1) << 6) + (word & 1);
                unsigned v = wv[k];
                while (v) {
                    int bit = __ffs(v) - 1;
                    v &= v - 1;
                    if (pos < CAND_MAX) cq32[2 * pos] = pbase + 2 * bit;
                    pos++;
                }
            }
            cnt[qi] = Cq;
            __syncwarp();
        }

        // --- rare per-query retry: lazily recompute Tr (16th of samples) ---
        #pragma unroll
        for (int qi = 0; qi < QPW; qi++) {
            if (cnt[qi] < Kn) {
                float qx = qsx[qi], qy = qsy[qi], qz = qsz[qi];
                // recompute sample top-2 for this query (bit-identical values)
                float n1 = -3.4e38f, n2 = -3.4e38f;
                for (int t = 0; t < 8; t++) {
                    int i2 = sb2 + t * 32 + lane;
                    float2 px = xs2[i2], py = ys2[i2], pz = zs2[i2], pw = ws2[i2];
                    float slo = fmaf(qz, pz.x, fmaf(qy, py.x, fmaf(qx, px.x, pw.x)));
                    float shi = fmaf(qz, pz.y, fmaf(qy, py.y, fmaf(qx, px.y, pw.y)));
                    if (slo > n2) {
                        if (slo > n1) { n2 = n1; n1 = slo; } else n2 = slo;
                    }
                    if (shi > n2) {
                        if (shi > n1) { n2 = n1; n1 = shi; } else n2 = shi;
                    }
                }
                float Tq = -3.4e38f;
                for (int r = 0; r < 16; r++) {
                    float v = n1;
                    #pragma unroll
                    for (int o = 16; o; o >>= 1)
                        v = fmaxf(v, __shfl_xor_sync(FULLMASK, v, o));
                    if (r == 15) Tq = v;
                    unsigned wm = __ballot_sync(FULLMASK, n1 == v);
                    if (lane == __ffs(wm) - 1) { n1 = n2; n2 = -3.4e38f; }
                }
                // rescan with looser threshold
                unsigned c = 0;
                unsigned* cq32 = reinterpret_cast<unsigned*>(cand + qi * CAND_MAX);
                for (int j0 = 0; j0 < Np; j0 += 32) {
                    int j = j0 + lane;
                    float s = fmaf(qz, zs[j], fmaf(qy, ys[j], fmaf(qx, xs[j], ws[j])));
                    unsigned mk = __ballot_sync(FULLMASK, s > Tq);
                    if (s > Tq) {
                        unsigned p = c + __popc(mk & laneLT);
                        if (p < CAND_MAX) cq32[2 * p] = j;
                    }
                    c += __popc(mk);
                }
                cnt[qi] = c;
            }
        }
        __syncwarp();

        // --- pack (key<<12 | idx) then rank-select top-30 ------------------
        #pragma unroll
        for (int qi = 0; qi < QPW; qi++) {
            int C = min(cnt[qi], CAND_MAX);
            unsigned long long* cq = cand + qi * CAND_MAX;
            unsigned* cq32 = reinterpret_cast<unsigned*>(cq);
            float qx = qsx[qi], qy = qsy[qi], qz = qsz[qi];
            for (int t = lane; t < C; t += 32) {
                unsigned j = cq32[2 * t];
                float s = fmaf(qz, zs[j], fmaf(qy, ys[j], fmaf(qx, xs[j], ws[j])));
                cq[t] = ((unsigned long long)fkeyU(s) << 12) | j;
            }
            __syncwarp();
            rankWrite(cq, C, (b * Np + n + qi * NGRP) * Kn, lane);
        }
        __syncwarp();

        nextg = __shfl_sync(FULLMASK, fetched, 0);
    }
}

// ---------------- block-level stat accumulation ----------------------------
template <int NV>
__device__ __forceinline__ void accumStats(const float* vals, float* sAcc, int statBase) {
    #pragma unroll
    for (int v = 0; v < NV; v++) {
        float x = vals[v];
        #pragma unroll
        for (int off = 16; off; off >>= 1) x += __shfl_down_sync(FULLMASK, x, off);
        if ((threadIdx.x & 31) == 0) atomicAdd(&sAcc[v], x);
    }
    __syncthreads();
    if (threadIdx.x < NV) atomicAdd(&g_stats[statBase + threadIdx.x], (double)sAcc[threadIdx.x]);
}

// ---------------- K_feat: element-parallel, 4 elems/thread -----------------
__global__ void __launch_bounds__(256) k_feat(const float* __restrict__ W1) {
    __shared__ float sW[36];
    __shared__ float sAcc[12];
    int tid = threadIdx.x;
    if (tid < 36) sW[tid] = W1[tid];
    if (tid < 12) sAcc[tid] = 0.f;
    __syncthreads();
    float acc[12];
    #pragma unroll
    for (int v = 0; v < 12; v++) acc[v] = 0.f;

    int e0 = (blockIdx.x * 256 + tid) * 4;
    float4 hv[6];
    #pragma unroll
    for (int u = 0; u < 4; u++) {
        int e = e0 + u;
        int r = e / Kn;
        int b = r >> 12;
        int j = g_idx[e];
        float4 pn = g_pts4[r];
        float4 pj = g_pts4[(b << 12) + j];
        float xr = pj.x - pn.x, yr = pj.y - pn.y, zr = pj.z - pn.z;
        float sxy2 = fmaf(yr, yr, xr * xr);
        float r2 = fmaf(zr, zr, sxy2);
        float rho = sqrtf(fmaxf(r2, TINYc));
        float sxy = sqrtf(fmaxf(sxy2, TINYc));
        float theta = (r2 < TINYc) ? 0.f : atan2f(zr, sxy);
        float phi = (sxy2 < TINYc) ? 0.f : atan2f(yr, xr);
        float mn = (rho + theta + phi) * (1.f / 3.f);
        float f[6] = {rho, theta, phi, rho - mn, theta - mn, phi - mn};
        #pragma unroll
        for (int o = 0; o < 6; o++) {
            float h = 0.f;
            #pragma unroll
            for (int i2 = 0; i2 < 6; i2++) h = fmaf(sW[o * 6 + i2], f[i2], h);
            (&hv[o].x)[u] = h;
            acc[o] += h;
            acc[6 + o] = fmaf(h, h, acc[6 + o]);
        }
    }
    #pragma unroll
    for (int o = 0; o < 6; o++)
        *reinterpret_cast<float4*>(&g_h1[o * Mtot + e0]) = hv[o];
    accumStats<12>(acc, sAcc, 0);
}

__device__ __forceinline__ float lrelu02(float t) { return t > 0.f ? t : 0.2f * t; }

// ---------------- K_l2: BN1 + lrelu + layer2 + stats (float4) --------------
__global__ void __launch_bounds__(256) k_l2(const float* __restrict__ gma,
                                            const float* __restrict__ bta,
                                            const float* __restrict__ W2) {
    __shared__ float sMu[6], sIs[6], sG[6], sB[6], sW[18], sAcc[6];
    int tid = threadIdx.x;
    if (tid < 6) {
        double s = g_stats[tid], sq = g_stats[6 + tid];
        double mu = s / (double)Mtot;
        double var = sq / (double)Mtot - mu * mu;
        sMu[tid] = (float)mu;
        sIs[tid] = (float)(1.0 / sqrt(var + (double)EPS_BN));
        sG[tid] = gma[tid]; sB[tid] = bta[tid];
        sAcc[tid] = 0.f;
    }
    if (tid < 18) sW[tid] = W2[tid];
    __syncthreads();
    int e4 = (blockIdx.x * 256 + tid) * 4;
    float4 a[6];
    #pragma unroll
    for (int i = 0; i < 6; i++) {
        float4 h = *reinterpret_cast<const float4*>(&g_h1[i * Mtot + e4]);
        float sc = sIs[i] * sG[i], mu = sMu[i], bb = sB[i];
        a[i].x = lrelu02(fmaf((h.x - mu), sc, bb));
        a[i].y = lrelu02(fmaf((h.y - mu), sc, bb));
        a[i].z = lrelu02(fmaf((h.z - mu), sc, bb));
        a[i].w = lrelu02(fmaf((h.w - mu), sc, bb));
    }
    float vals[6];
    #pragma unroll
    for (int o = 0; o < 3; o++) {
        float4 h = make_float4(0.f, 0.f, 0.f, 0.f);
        #pragma unroll
        for (int i = 0; i < 6; i++) {
            float w = sW[o * 6 + i];
            h.x = fmaf(w, a[i].x, h.x); h.y = fmaf(w, a[i].y, h.y);
            h.z = fmaf(w, a[i].z, h.z); h.w = fmaf(w, a[i].w, h.w);
        }
        *reinterpret_cast<float4*>(&g_h2[o * Mtot + e4]) = h;
        vals[o] = (h.x + h.y) + (h.z + h.w);
        vals[3 + o] = fmaf(h.x, h.x, h.y * h.y) + fmaf(h.z, h.z, h.w * h.w);
    }
    accumStats<6>(vals, sAcc, 12);
}

// ---------------- K_l3: BN2 + lrelu + layer3 + stats (float4) --------------
__global__ void __launch_bounds__(256) k_l3(const float* __restrict__ gma,
                                            const float* __restrict__ bta,
                                            const float* __restrict__ W3) {
    __shared__ float sMu[3], sIs[3], sG[3], sB[3], sW[3], sAcc[2];
    int tid = threadIdx.x;
    if (tid < 3) {
        double s = g_stats[12 + tid], sq = g_stats[15 + tid];
        double mu = s / (double)Mtot;
        double var = sq / (double)Mtot - mu * mu;
        sMu[tid] = (float)mu;
        sIs[tid] = (float)(1.0 / sqrt(var + (double)EPS_BN));
        sG[tid] = gma[tid]; sB[tid] = bta[tid];
        sW[tid] = W3[tid];
    }
    if (tid < 2) sAcc[tid] = 0.f;
    __syncthreads();
    int e4 = (blockIdx.x * 256 + tid) * 4;
    float4 h = make_float4(0.f, 0.f, 0.f, 0.f);
    #pragma unroll
    for (int i = 0; i < 3; i++) {
        float4 hv = *reinterpret_cast<const float4*>(&g_h2[i * Mtot + e4]);
        float sc = sIs[i] * sG[i], mu = sMu[i], bb = sB[i], w = sW[i];
        h.x = fmaf(w, lrelu02(fmaf((hv.x - mu), sc, bb)), h.x);
        h.y = fmaf(w, lrelu02(fmaf((hv.y - mu), sc, bb)), h.y);
        h.z = fmaf(w, lrelu02(fmaf((hv.z - mu), sc, bb)), h.z);
        h.w = fmaf(w, lrelu02(fmaf((hv.w - mu), sc, bb)), h.w);
    }
    *reinterpret_cast<float4*>(&g_h3[e4]) = h;
    float vals[2];
    vals[0] = (h.x + h.y) + (h.z + h.w);
    vals[1] = fmaf(h.x, h.x, h.y * h.y) + fmaf(h.z, h.z, h.w * h.w);
    accumStats<2>(vals, sAcc, 18);
}

// ---------------- K_out: BN3 + lrelu + softmax + aggregate -----------------
__global__ void __launch_bounds__(256) k_out(const float* __restrict__ x,
                                             const float* __restrict__ g3,
                                             const float* __restrict__ b3,
                                             float* __restrict__ out) {
    __shared__ float sAtt[8][Kn];
    __shared__ int sJ[8][Kn];
    __shared__ float sMu, sIs;
    int tid = threadIdx.x, wid = tid >> 5, lane = tid & 31;
    if (tid == 0) {
        double s = g_stats[18], sq = g_stats[19];
        double mu = s / (double)Mtot;
        double var = sq / (double)Mtot - mu * mu;
        sMu = (float)mu;
        sIs = (float)(1.0 / sqrt(var + (double)EPS_BN));
    }
    __syncthreads();
    int r = blockIdx.x * 8 + wid;
    int b = r >> 12, n = r & 4095;
    float gv = g3[0], bv = b3[0];
    float logit = -INFINITY;
    if (lane < Kn) {
        float h = g_h3[r * Kn + lane];
        float t = fmaf((h - sMu) * sIs, gv, bv);
        logit = t > 0.f ? t : 0.2f * t;
    }
    float mx = logit;
    #pragma unroll
    for (int off = 16; off; off >>= 1) mx = fmaxf(mx, __shfl_xor_sync(FULLMASK, mx, off));
    float ex = (lane < Kn) ? expf(logit - mx) : 0.f;
    float sm = ex;
    #pragma unroll
    for (int off = 16; off; off >>= 1) sm += __shfl_xor_sync(FULLMASK, sm, off);
    float att = ex / sm;
    if (lane < Kn) {
        sAtt[wid][lane] = att;
        sJ[wid][lane] = g_idx[r * Kn + lane];
    }
    __syncwarp();
    float acc0 = 0.f, acc1 = 0.f;
    const float* xb = g_xT + (size_t)(b << 12) * Cch;
    #pragma unroll 5
    for (int kk = 0; kk < Kn; kk++) {
        const float* p = xb + sJ[wid][kk] * Cch;
        float a = sAtt[wid][kk];
        acc0 = fmaf(a, p[lane], acc0);
        acc1 = fmaf(a, p[lane + 32], acc1);
    }
    size_t o0 = (size_t)b * (Cch * Np) + (size_t)lane * Np + (size_t)n;
    size_t o1 = o0 + (size_t)32 * Np;
    out[o0] = x[o0] + acc0;
    out[o1] = x[o1] + acc1;
}

// ---------------- launch ----------------------------------------------------
extern "C" void kernel_launch(void* const* d_in, const int* in_sizes, int n_in,
                              void* d_out, int out_size) {
    const float* xloc = (const float*)d_in[0];
    const float* x    = (const float*)d_in[1];
    const float* W1   = (const float*)d_in[2];
    const float* g1   = (const float*)d_in[3];
    const float* b1   = (const float*)d_in[4];
    const float* W2   = (const float*)d_in[5];
    const float* g2   = (const float*)d_in[6];
    const float* b2   = (const float*)d_in[7];
    const float* W3   = (const float*)d_in[8];
    const float* g3   = (const float*)d_in[9];
    const float* b3   = (const float*)d_in[10];
    float* out = (float*)d_out;

    size_t knnSmem = 4u * Np * sizeof(float) +
                     sizeof(unsigned long long) * KNN_WARPS * QPW * CAND_MAX;  // 112 KB
    cudaFuncSetAttribute(k_knn, cudaFuncAttributeMaxDynamicSharedMemorySize, (int)knnSmem);

    k_zero<<<1, 32>>>();                          // #1
    k_xt<<<dim3(Np / 32, Bz), 256>>>(x, xloc);    // #2 (transpose + pts4)
    k_knn<<<dim3(37, Bz), KNN_TPB, knnSmem>>>();  // #3
    k_feat<<<Mtot / 1024, 256>>>(W1);             // #4  <- profiled
    k_l2<<<Mtot / 1024, 256>>>(g1, b1, W2);       // #5
    k_l3<<<Mtot / 1024, 256>>>(g2, b2, W3);       // #6
    k_out<<<Bz * Np / 8, 256>>>(x, g3, b3, out);  // #7
}

// round 16
// speedup vs baseline: 1.6098x; 1.0750x over previous
#include <cuda_runtime.h>
#include <cstdint>
#include <math.h>

#define FULLMASK 0xFFFFFFFFu

constexpr int Bz = 8, Np = 4096, Cch = 64, Kn = 30;
constexpr int Mtot = Bz * Np * Kn;           // 983040
constexpr float EPS_BN = 1e-5f;
constexpr float TINYc = 1e-20f;

constexpr int CAND_MAX = 192;
constexpr int KNN_TPB = 512;                 // 16 warps, 2 blocks/SM
constexpr int KNN_WARPS = KNN_TPB / 32;
constexpr int NGRP = Np / 2;                 // 2048 adjacent-pair groups

// ---------------- scratch ---------------------------------------------------
__device__ float4 g_pts4[Bz * Np];           // orig order: x,y,z, -0.5|p|^2
__device__ float4 g_spts4[Bz * Np];          // x-sorted order
__device__ int    g_perm[Bz * Np];           // sorted pos -> orig idx
__device__ int    g_boff[Bz * 257];          // bucket offsets
__device__ float  g_xT[Bz * Np * Cch];
__device__ int    g_idx[Mtot];
__device__ float  g_h1[6 * Mtot];
__device__ float  g_h2[3 * Mtot];
__device__ float  g_h3[Mtot];
__device__ double g_stats[24];
__device__ int    g_work[Bz];                // work-stealing counters

// ---------------- packed f32x2 helpers --------------------------------------
__device__ __forceinline__ unsigned long long fma2(unsigned long long a,
                                                   unsigned long long b,
                                                   unsigned long long c) {
    unsigned long long d;
    asm("fma.rn.f32x2 %0, %1, %2, %3;" : "=l"(d) : "l"(a), "l"(b), "l"(c));
    return d;
}
__device__ __forceinline__ unsigned long long pack2(float lo, float hi) {
    unsigned long long v;
    asm("mov.b64 %0, {%1, %2};" : "=l"(v) : "f"(lo), "f"(hi));
    return v;
}
__device__ __forceinline__ void unpack2(unsigned long long v, float& lo, float& hi) {
    asm("mov.b64 {%0, %1}, %2;" : "=f"(lo), "=f"(hi) : "l"(v));
}
__device__ __forceinline__ unsigned fkeyU(float f) {
    unsigned b = __float_as_uint(f);
    return b ^ ((unsigned)((int)b >> 31) | 0x80000000u);
}
__device__ __forceinline__ float keyToF(unsigned k) {
    unsigned m = (k & 0x80000000u) ? 0x80000000u : 0xFFFFFFFFu;
    return __uint_as_float(k ^ m);
}
__device__ __forceinline__ int bucketOf(float x) {
    int bk = (int)((x + 5.0f) * 25.6f);
    return min(255, max(0, bk));
}

// ---------------- K_zero (launch #1) ---------------------------------------
__global__ void k_zero() {
    if (threadIdx.x < 24) g_stats[threadIdx.x] = 0.0;
    if (threadIdx.x >= 24 && threadIdx.x < 24 + Bz) g_work[threadIdx.x - 24] = 0;
}

// ---------------- K_xt: transpose x -> xT AND build pts4 (launch #2) -------
__global__ void __launch_bounds__(256) k_xt(const float* __restrict__ x,
                                            const float* __restrict__ xloc) {
    __shared__ float s[64][33];
    int b = blockIdx.y;
    int n0 = blockIdx.x * 32;
    int lane = threadIdx.x & 31, w = threadIdx.x >> 5;
    #pragma unroll
    for (int i = 0; i < 8; i++) {
        int c = w * 8 + i;
        s[c][lane] = x[(((b << 6) + c) << 12) + n0 + lane];
    }
    if (threadIdx.x < 32) {
        int n = n0 + threadIdx.x;
        const float* p = xloc + b * 3 * Np;
        float px = p[n], py = p[Np + n], pz = p[2 * Np + n];
        float xx = fmaf(pz, pz, fmaf(py, py, px * px));
        g_pts4[(b << 12) + n] = make_float4(px, py, pz, -0.5f * xx);
    }
    __syncthreads();
    #pragma unroll
    for (int i = 0; i < 8; i++) {
        int e = i * 256 + threadIdx.x;
        int nl = e >> 6, c = e & 63;
        g_xT[(size_t)(((b << 12) + n0 + nl) << 6) + c] = s[c][nl];
    }
}

// ---------------- K_sort: bucket-sort points by x (launch #3) --------------
__global__ void __launch_bounds__(512) k_sort() {
    __shared__ int hist[256];
    __shared__ int incl[256];
    __shared__ int offs[256];
    int b = blockIdx.x;
    int tid = threadIdx.x;
    if (tid < 256) hist[tid] = 0;
    __syncthreads();
    int bks[8];
    #pragma unroll
    for (int u = 0; u < 8; u++) {
        int i = u * 512 + tid;
        float xv = g_pts4[(b << 12) + i].x;
        int bk = bucketOf(xv);
        bks[u] = bk;
        atomicAdd(&hist[bk], 1);
    }
    __syncthreads();
    if (tid < 256) incl[tid] = hist[tid];
    __syncthreads();
    for (int off = 1; off < 256; off <<= 1) {
        int v = 0;
        if (tid < 256 && tid >= off) v = incl[tid - off];
        __syncthreads();
        if (tid < 256) incl[tid] += v;
        __syncthreads();
    }
    if (tid < 256) {
        int excl = incl[tid] - hist[tid];
        offs[tid] = excl;
        g_boff[b * 257 + tid] = excl;
    }
    if (tid == 0) g_boff[b * 257 + 256] = Np;
    __syncthreads();
    #pragma unroll
    for (int u = 0; u < 8; u++) {
        int i = u * 512 + tid;
        int pos = atomicAdd(&offs[bks[u]], 1);
        g_spts4[(b << 12) + pos] = g_pts4[(b << 12) + i];
        g_perm[(b << 12) + pos] = i;
    }
}

// ---------------- K_knn (launch #4 -> profiled) ----------------------------
__device__ __forceinline__ void rankWrite(const unsigned long long* cand, int C,
                                          int base, int lane) {
    if (C < Kn) {                            // astronomically rare fallback
        if (lane < Kn) g_idx[base + lane] = (int)(cand[0] & 0xFFFULL);
        if (lane < C)  g_idx[base + lane] = (int)(cand[lane] & 0xFFFULL);
        return;
    }
    if (C <= 64) {                           // common path: 2-cand/lane
        unsigned long long v0 = (lane < C)      ? cand[lane]      : 0ULL;
        unsigned long long v1 = (lane + 32 < C) ? cand[lane + 32] : 0ULL;
        int r0 = 0, r1 = 0;
        #pragma unroll 4
        for (int s = 0; s < C; s++) {
            unsigned long long w2 = cand[s];
            r0 += (w2 > v0); r1 += (w2 > v1);
        }
        if (lane < C      && r0 < Kn) g_idx[base + r0] = (int)(v0 & 0xFFFULL);
        if (lane + 32 < C && r1 < Kn) g_idx[base + r1] = (int)(v1 & 0xFFFULL);
        return;
    }
    for (int tb = 0; tb < C; tb += 128) {
        int t0 = tb + lane;
        unsigned long long v0 = (t0 < C)      ? cand[t0]      : 0ULL;
        unsigned long long v1 = (t0 + 32 < C) ? cand[t0 + 32] : 0ULL;
        unsigned long long v2 = (t0 + 64 < C) ? cand[t0 + 64] : 0ULL;
        unsigned long long v3 = (t0 + 96 < C) ? cand[t0 + 96] : 0ULL;
        int r0 = 0, r1 = 0, r2 = 0, r3 = 0;
        #pragma unroll 4
        for (int s = 0; s < C; s++) {
            unsigned long long w2 = cand[s];
            r0 += (w2 > v0); r1 += (w2 > v1);
            r2 += (w2 > v2); r3 += (w2 > v3);
        }
        if (t0 < C      && r0 < Kn) g_idx[base + r0] = (int)(v0 & 0xFFFULL);
        if (t0 + 32 < C && r1 < Kn) g_idx[base + r1] = (int)(v1 & 0xFFFULL);
        if (t0 + 64 < C && r2 < Kn) g_idx[base + r2] = (int)(v2 & 0xFFFULL);
        if (t0 + 96 < C && r3 < Kn) g_idx[base + r3] = (int)(v3 & 0xFFFULL);
    }
}

__global__ void __launch_bounds__(KNN_TPB, 2) k_knn() {
    extern __shared__ unsigned char smemRaw[];
    float* xs = reinterpret_cast<float*>(smemRaw);
    float* ys = xs + Np;
    float* zs = ys + Np;
    float* ws = zs + Np;
    unsigned long long* candBase =
        reinterpret_cast<unsigned long long*>(smemRaw + 4u * Np * sizeof(float));
    const float2* xs2 = reinterpret_cast<const float2*>(xs);
    const float2* ys2 = reinterpret_cast<const float2*>(ys);
    const float2* zs2 = reinterpret_cast<const float2*>(zs);
    const float2* ws2 = reinterpret_cast<const float2*>(ws);

    int b = blockIdx.y;
    const float4* gp = g_spts4 + b * Np;     // SORTED points
    for (int i = threadIdx.x; i < Np; i += KNN_TPB) {
        float4 p = gp[i];
        xs[i] = p.x; ys[i] = p.y; zs[i] = p.z; ws[i] = p.w;
    }
    __syncthreads();

    int wid = threadIdx.x >> 5, lane = threadIdx.x & 31;
    unsigned long long* cand = candBase + (size_t)wid * 2 * CAND_MAX;
    unsigned laneLT = (lane == 31) ? 0x7FFFFFFFu : ((1u << lane) - 1u);
    const int* boffB = g_boff + b * 257;
    const int* permB = g_perm + (b << 12);

    int fetched = 0;
    if (lane == 0) fetched = atomicAdd(&g_work[b], 1);
    int nextg = __shfl_sync(FULLMASK, fetched, 0);

    while (nextg < NGRP) {
        int nA = 2 * nextg, nB = nA + 1;     // adjacent sorted positions
        if (lane == 0) fetched = atomicAdd(&g_work[b], 1);

        float qx[2], qy[2], qz[2], qw[2];
        unsigned long long qX[2], qY[2], qZ[2];
        #pragma unroll
        for (int qi = 0; qi < 2; qi++) {
            int nq = nA + qi;
            qx[qi] = xs[nq]; qy[qi] = ys[nq]; qz[qi] = zs[nq]; qw[qi] = ws[nq];
            qX[qi] = pack2(qx[qi], qx[qi]);
            qY[qi] = pack2(qy[qi], qy[qi]);
            qZ[qi] = pack2(qz[qi], qz[qi]);
        }

        // --- sample pass: 512 strided samples (i*125 mod 4096) -------------
        int sBase = (lane * 125 + nA * 16) & 4095;
        float m1[2], m2[2];
        #pragma unroll
        for (int qi = 0; qi < 2; qi++) { m1[qi] = -3.4e38f; m2[qi] = -3.4e38f; }
        #pragma unroll 2
        for (int t = 0; t < 16; t++) {
            int idx = (sBase + t * 4000) & 4095;
            float px = xs[idx], py = ys[idx], pz = zs[idx], pw = ws[idx];
            #pragma unroll
            for (int qi = 0; qi < 2; qi++) {
                float s = fmaf(qz[qi], pz, fmaf(qy[qi], py, fmaf(qx[qi], px, pw)));
                if (s > m2[qi]) {
                    if (s > m1[qi]) { m2[qi] = m1[qi]; m1[qi] = s; } else m2[qi] = s;
                }
            }
        }
        // --- extract 8th largest per query via REDUX -----------------------
        float T[2];
        for (int r = 0; r < 8; r++) {
            #pragma unroll
            for (int qi = 0; qi < 2; qi++) {
                unsigned k1 = fkeyU(m1[qi]);
                unsigned vm = __reduce_max_sync(FULLMASK, k1);
                if (r == 7) T[qi] = keyToF(vm);
                unsigned wm = __ballot_sync(FULLMASK, k1 == vm);
                if (lane == __ffs(wm) - 1) { m1[qi] = m2[qi]; m2[qi] = -3.4e38f; }
            }
        }

        // --- slab bounds from D^2 = |q|^2 - 2T = -2(w + T) -----------------
        float DA = sqrtf(fmaxf(0.f, -2.0f * (qw[0] + T[0])));
        float DB = sqrtf(fmaxf(0.f, -2.0f * (qw[1] + T[1])));
        float xlo = fminf(qx[0] - DA, qx[1] - DB);
        float xhi = fmaxf(qx[0] + DA, qx[1] + DB);
        int jlo = boffB[bucketOf(xlo)] & ~63;
        int jhi = (boffB[bucketOf(xhi) + 1] + 63) & ~63;

        // --- zero mask words ------------------------------------------------
        {
            unsigned* mw0 = reinterpret_cast<unsigned*>(cand);
            unsigned* mw1 = reinterpret_cast<unsigned*>(cand + CAND_MAX);
            #pragma unroll
            for (int k = 0; k < 4; k++) {
                mw0[lane + 32 * k] = 0;
                mw1[lane + 32 * k] = 0;
            }
        }
        __syncwarp();

        // --- main scan over slab: 64 pts/iter packed; store hit-masks ------
        for (int j0 = jlo; j0 < jhi; j0 += 64) {
            int i2 = (j0 >> 1) + lane;
            float2 px = xs2[i2], py = ys2[i2], pz = zs2[i2], pw = ws2[i2];
            unsigned long long X = pack2(px.x, px.y), Y = pack2(py.x, py.y);
            unsigned long long Z = pack2(pz.x, pz.y), Wp = pack2(pw.x, pw.y);
            #pragma unroll
            for (int qi = 0; qi < 2; qi++) {
                unsigned long long s2 = fma2(qZ[qi], Z, fma2(qY[qi], Y, fma2(qX[qi], X, Wp)));
                float slo, shi; unpack2(s2, slo, shi);
                unsigned mlo = __ballot_sync(FULLMASK, slo > T[qi]);
                unsigned mhi = __ballot_sync(FULLMASK, shi > T[qi]);
                if (lane == 0) {
                    unsigned* mw = reinterpret_cast<unsigned*>(cand + qi * CAND_MAX);
                    mw[(j0 >> 5)] = mlo;
                    mw[(j0 >> 5) + 1] = mhi;
                }
            }
        }
        __syncwarp();

        // --- extraction: masks -> candidate (sorted) index list ------------
        int cnt[2];
        #pragma unroll
        for (int qi = 0; qi < 2; qi++) {
            unsigned* mw = reinterpret_cast<unsigned*>(cand + qi * CAND_MAX);
            unsigned w0 = mw[lane], w1 = mw[lane + 32];
            unsigned w2 = mw[lane + 64], w3 = mw[lane + 96];
            __syncwarp();
            int tot = __popc(w0) + __popc(w1) + __popc(w2) + __popc(w3);
            int incl = tot;
            #pragma unroll
            for (int o = 1; o < 32; o <<= 1) {
                int v = __shfl_up_sync(FULLMASK, incl, o);
                if (lane >= o) incl += v;
            }
            int Cq = __shfl_sync(FULLMASK, incl, 31);
            int pos = incl - tot;
            unsigned* cq32 = mw;
            unsigned wv[4] = {w0, w1, w2, w3};
            #pragma unroll
            for (int k = 0; k < 4; k++) {
                int word = lane + 32 * k;
                int pbase = ((word >> 1) << 6) + (word & 1);
                unsigned v = wv[k];
                while (v) {
                    int bit = __ffs(v) - 1;
                    v &= v - 1;
                    if (pos < CAND_MAX) cq32[2 * pos] = pbase + 2 * bit;
                    pos++;
                }
            }
            cnt[qi] = Cq;
            __syncwarp();
        }

        // --- rare retry: 16th-sample threshold, FULL scan ------------------
        #pragma unroll
        for (int qi = 0; qi < 2; qi++) {
            if (cnt[qi] < Kn) {
                float qxx = qx[qi], qyy = qy[qi], qzz = qz[qi];
                float n1 = -3.4e38f, n2 = -3.4e38f;
                for (int t = 0; t < 16; t++) {
                    int idx = (sBase + t * 4000) & 4095;
                    float s = fmaf(qzz, zs[idx], fmaf(qyy, ys[idx], fmaf(qxx, xs[idx], ws[idx])));
                    if (s > n2) {
                        if (s > n1) { n2 = n1; n1 = s; } else n2 = s;
                    }
                }
                float Tq = -3.4e38f;
                for (int r = 0; r < 16; r++) {
                    unsigned k1 = fkeyU(n1);
                    unsigned vm = __reduce_max_sync(FULLMASK, k1);
                    if (r == 15) Tq = keyToF(vm);
                    unsigned wm = __ballot_sync(FULLMASK, k1 == vm);
                    if (lane == __ffs(wm) - 1) { n1 = n2; n2 = -3.4e38f; }
                }
                unsigned c = 0;
                unsigned* cq32 = reinterpret_cast<unsigned*>(cand + qi * CAND_MAX);
                for (int j0 = 0; j0 < Np; j0 += 32) {
                    int j = j0 + lane;
                    float s = fmaf(qzz, zs[j], fmaf(qyy, ys[j], fmaf(qxx, xs[j], ws[j])));
                    unsigned mk = __ballot_sync(FULLMASK, s > Tq);
                    if (s > Tq) {
                        unsigned p = c + __popc(mk & laneLT);
                        if (p < CAND_MAX) cq32[2 * p] = j;
                    }
                    c += __popc(mk);
                }
                cnt[qi] = c;
            }
        }
        __syncwarp();

        // --- pack (key<<12 | ORIG idx) then rank-select top-30 -------------
        #pragma unroll
        for (int qi = 0; qi < 2; qi++) {
            int C = min(cnt[qi], CAND_MAX);
            unsigned long long* cq = cand + qi * CAND_MAX;
            unsigned* cq32 = reinterpret_cast<unsigned*>(cq);
            float qxx = qx[qi], qyy = qy[qi], qzz = qz[qi];
            for (int t = lane; t < C; t += 32) {
                unsigned j = cq32[2 * t];
                float s = fmaf(qzz, zs[j], fmaf(qyy, ys[j], fmaf(qxx, xs[j], ws[j])));
                int orig = permB[j];
                cq[t] = ((unsigned long long)fkeyU(s) << 12) | (unsigned)orig;
            }
            __syncwarp();
            int origQ = permB[nA + qi];
            rankWrite(cq, C, (b * Np + origQ) * Kn, lane);
        }
        __syncwarp();

        nextg = __shfl_sync(FULLMASK, fetched, 0);
    }
}

// ---------------- block-level stat accumulation ----------------------------
template <int NV>
__device__ __forceinline__ void accumStats(const float* vals, float* sAcc, int statBase) {
    #pragma unroll
    for (int v = 0; v < NV; v++) {
        float x = vals[v];
        #pragma unroll
        for (int off = 16; off; off >>= 1) x += __shfl_down_sync(FULLMASK, x, off);
        if ((threadIdx.x & 31) == 0) atomicAdd(&sAcc[v], x);
    }
    __syncthreads();
    if (threadIdx.x < NV) atomicAdd(&g_stats[statBase + threadIdx.x], (double)sAcc[threadIdx.x]);
}

// ---------------- K_feat: element-parallel, 2 elems/thread -----------------
__global__ void __launch_bounds__(256) k_feat(const float* __restrict__ W1) {
    __shared__ float sW[36];
    __shared__ float sAcc[12];
    int tid = threadIdx.x;
    if (tid < 36) sW[tid] = W1[tid];
    if (tid < 12) sAcc[tid] = 0.f;
    __syncthreads();
    float acc[12];
    #pragma unroll
    for (int v = 0; v < 12; v++) acc[v] = 0.f;

    int e0 = (blockIdx.x * 256 + tid) * 2;
    float2 hv[6];
    #pragma unroll
    for (int u = 0; u < 2; u++) {
        int e = e0 + u;
        int r = e / Kn;
        int b = r >> 12;
        int j = g_idx[e];
        float4 pn = g_pts4[r];
        float4 pj = g_pts4[(b << 12) + j];
        float xr = pj.x - pn.x, yr = pj.y - pn.y, zr = pj.z - pn.z;
        float sxy2 = fmaf(yr, yr, xr * xr);
        float r2 = fmaf(zr, zr, sxy2);
        float rho = sqrtf(fmaxf(r2, TINYc));
        float sxy = sqrtf(fmaxf(sxy2, TINYc));
        float theta = (r2 < TINYc) ? 0.f : atan2f(zr, sxy);
        float phi = (sxy2 < TINYc) ? 0.f : atan2f(yr, xr);
        float mn = (rho + theta + phi) * (1.f / 3.f);
        float f[6] = {rho, theta, phi, rho - mn, theta - mn, phi - mn};
        #pragma unroll
        for (int o = 0; o < 6; o++) {
            float h = 0.f;
            #pragma unroll
            for (int i2 = 0; i2 < 6; i2++) h = fmaf(sW[o * 6 + i2], f[i2], h);
            (&hv[o].x)[u] = h;
            acc[o] += h;
            acc[6 + o] = fmaf(h, h, acc[6 + o]);
        }
    }
    #pragma unroll
    for (int o = 0; o < 6; o++)
        *reinterpret_cast<float2*>(&g_h1[o * Mtot + e0]) = hv[o];
    accumStats<12>(acc, sAcc, 0);
}

__device__ __forceinline__ float lrelu02(float t) { return t > 0.f ? t : 0.2f * t; }

// ---------------- K_l2: BN1 + lrelu + layer2 + stats (float4) --------------
__global__ void __launch_bounds__(256) k_l2(const float* __restrict__ gma,
                                            const float* __restrict__ bta,
                                            const float* __restrict__ W2) {
    __shared__ float sMu[6], sIs[6], sG[6], sB[6], sW[18], sAcc[6];
    int tid = threadIdx.x;
    if (tid < 6) {
        double s = g_stats[tid], sq = g_stats[6 + tid];
        double mu = s / (double)Mtot;
        double var = sq / (double)Mtot - mu * mu;
        sMu[tid] = (float)mu;
        sIs[tid] = (float)(1.0 / sqrt(var + (double)EPS_BN));
        sG[tid] = gma[tid]; sB[tid] = bta[tid];
        sAcc[tid] = 0.f;
    }
    if (tid < 18) sW[tid] = W2[tid];
    __syncthreads();
    int e4 = (blockIdx.x * 256 + tid) * 4;
    float4 a[6];
    #pragma unroll
    for (int i = 0; i < 6; i++) {
        float4 h = *reinterpret_cast<const float4*>(&g_h1[i * Mtot + e4]);
        float sc = sIs[i] * sG[i], mu = sMu[i], bb = sB[i];
        a[i].x = lrelu02(fmaf((h.x - mu), sc, bb));
        a[i].y = lrelu02(fmaf((h.y - mu), sc, bb));
        a[i].z = lrelu02(fmaf((h.z - mu), sc, bb));
        a[i].w = lrelu02(fmaf((h.w - mu), sc, bb));
    }
    float vals[6];
    #pragma unroll
    for (int o = 0; o < 3; o++) {
        float4 h = make_float4(0.f, 0.f, 0.f, 0.f);
        #pragma unroll
        for (int i = 0; i < 6; i++) {
            float w = sW[o * 6 + i];
            h.x = fmaf(w, a[i].x, h.x); h.y = fmaf(w, a[i].y, h.y);
            h.z = fmaf(w, a[i].z, h.z); h.w = fmaf(w, a[i].w, h.w);
        }
        *reinterpret_cast<float4*>(&g_h2[o * Mtot + e4]) = h;
        vals[o] = (h.x + h.y) + (h.z + h.w);
        vals[3 + o] = fmaf(h.x, h.x, h.y * h.y) + fmaf(h.z, h.z, h.w * h.w);
    }
    accumStats<6>(vals, sAcc, 12);
}

// ---------------- K_l3: BN2 + lrelu + layer3 + stats (float4) --------------
__global__ void __launch_bounds__(256) k_l3(const float* __restrict__ gma,
                                            const float* __restrict__ bta,
                                            const float* __restrict__ W3) {
    __shared__ float sMu[3], sIs[3], sG[3], sB[3], sW[3], sAcc[2];
    int tid = threadIdx.x;
    if (tid < 3) {
        double s = g_stats[12 + tid], sq = g_stats[15 + tid];
        double mu = s / (double)Mtot;
        double var = sq / (double)Mtot - mu * mu;
        sMu[tid] = (float)mu;
        sIs[tid] = (float)(1.0 / sqrt(var + (double)EPS_BN));
        sG[tid] = gma[tid]; sB[tid] = bta[tid];
        sW[tid] = W3[tid];
    }
    if (tid < 2) sAcc[tid] = 0.f;
    __syncthreads();
    int e4 = (blockIdx.x * 256 + tid) * 4;
    float4 h = make_float4(0.f, 0.f, 0.f, 0.f);
    #pragma unroll
    for (int i = 0; i < 3; i++) {
        float4 hv = *reinterpret_cast<const float4*>(&g_h2[i * Mtot + e4]);
        float sc = sIs[i] * sG[i], mu = sMu[i], bb = sB[i], w = sW[i];
        h.x = fmaf(w, lrelu02(fmaf((hv.x - mu), sc, bb)), h.x);
        h.y = fmaf(w, lrelu02(fmaf((hv.y - mu), sc, bb)), h.y);
        h.z = fmaf(w, lrelu02(fmaf((hv.z - mu), sc, bb)), h.z);
        h.w = fmaf(w, lrelu02(fmaf((hv.w - mu), sc, bb)), h.w);
    }
    *reinterpret_cast<float4*>(&g_h3[e4]) = h;
    float vals[2];
    vals[0] = (h.x + h.y) + (h.z + h.w);
    vals[1] = fmaf(h.x, h.x, h.y * h.y) + fmaf(h.z, h.z, h.w * h.w);
    accumStats<2>(vals, sAcc, 18);
}

// ---------------- K_out: BN3 + lrelu + softmax + aggregate -----------------
__global__ void __launch_bounds__(256) k_out(const float* __restrict__ x,
                                             const float* __restrict__ g3,
                                             const float* __restrict__ b3,
                                             float* __restrict__ out) {
    __shared__ float sAtt[8][Kn];
    __shared__ int sJ[8][Kn];
    __shared__ float sMu, sIs;
    int tid = threadIdx.x, wid = tid >> 5, lane = tid & 31;
    if (tid == 0) {
        double s = g_stats[18], sq = g_stats[19];
        double mu = s / (double)Mtot;
        double var = sq / (double)Mtot - mu * mu;
        sMu = (float)mu;
        sIs = (float)(1.0 / sqrt(var + (double)EPS_BN));
    }
    __syncthreads();
    int r = blockIdx.x * 8 + wid;
    int b = r >> 12, n = r & 4095;
    float gv = g3[0], bv = b3[0];
    float logit = -INFINITY;
    if (lane < Kn) {
        float h = g_h3[r * Kn + lane];
        float t = fmaf((h - sMu) * sIs, gv, bv);
        logit = t > 0.f ? t : 0.2f * t;
    }
    float mx = logit;
    #pragma unroll
    for (int off = 16; off; off >>= 1) mx = fmaxf(mx, __shfl_xor_sync(FULLMASK, mx, off));
    float ex = (lane < Kn) ? expf(logit - mx) : 0.f;
    float sm = ex;
    #pragma unroll
    for (int off = 16; off; off >>= 1) sm += __shfl_xor_sync(FULLMASK, sm, off);
    float att = ex / sm;
    if (lane < Kn) {
        sAtt[wid][lane] = att;
        sJ[wid][lane] = g_idx[r * Kn + lane];
    }
    __syncwarp();
    float acc0 = 0.f, acc1 = 0.f;
    const float* xb = g_xT + (size_t)(b << 12) * Cch;
    #pragma unroll 5
    for (int kk = 0; kk < Kn; kk++) {
        const float* p = xb + sJ[wid][kk] * Cch;
        float a = sAtt[wid][kk];
        acc0 = fmaf(a, p[lane], acc0);
        acc1 = fmaf(a, p[lane + 32], acc1);
    }
    size_t o0 = (size_t)b * (Cch * Np) + (size_t)lane * Np + (size_t)n;
    size_t o1 = o0 + (size_t)32 * Np;
    out[o0] = x[o0] + acc0;
    out[o1] = x[o1] + acc1;
}

// ---------------- launch ----------------------------------------------------
extern "C" void kernel_launch(void* const* d_in, const int* in_sizes, int n_in,
                              void* d_out, int out_size) {
    const float* xloc = (const float*)d_in[0];
    const float* x    = (const float*)d_in[1];
    const float* W1   = (const float*)d_in[2];
    const float* g1   = (const float*)d_in[3];
    const float* b1   = (const float*)d_in[4];
    const float* W2   = (const float*)d_in[5];
    const float* g2   = (const float*)d_in[6];
    const float* b2   = (const float*)d_in[7];
    const float* W3   = (const float*)d_in[8];
    const float* g3   = (const float*)d_in[9];
    const float* b3   = (const float*)d_in[10];
    float* out = (float*)d_out;

    size_t knnSmem = 4u * Np * sizeof(float) +
                     sizeof(unsigned long long) * KNN_WARPS * 2 * CAND_MAX;  // 112 KB
    cudaFuncSetAttribute(k_knn, cudaFuncAttributeMaxDynamicSharedMemorySize, (int)knnSmem);

    k_zero<<<1, 32>>>();                          // #1
    k_xt<<<dim3(Np / 32, Bz), 256>>>(x, xloc);    // #2 (transpose + pts4)
    k_sort<<<Bz, 512>>>();                        // #3 (bucket sort by x)
    k_knn<<<dim3(37, Bz), KNN_TPB, knnSmem>>>();  // #4  <- profiled
    k_feat<<<Mtot / 512, 256>>>(W1);              // #5
    k_l2<<<Mtot / 1024, 256>>>(g1, b1, W2);       // #6
    k_l3<<<Mtot / 1024, 256>>>(g2, b2, W3);       // #7
    k_out<<<Bz * Np / 8, 256>>>(x, g3, b3, out);  // #8
}

// round 17
// speedup vs baseline: 1.6939x; 1.0523x over previous
#include <cuda_runtime.h>
#include <cstdint>
#include <math.h>

#define FULLMASK 0xFFFFFFFFu

constexpr int Bz = 8, Np = 4096, Cch = 64, Kn = 30;
constexpr int Mtot = Bz * Np * Kn;           // 983040
constexpr float EPS_BN = 1e-5f;
constexpr float TINYc = 1e-20f;

constexpr int CAND_MAX = 192;
constexpr int KNN_TPB = 512;                 // 16 warps, 2 blocks/SM
constexpr int KNN_WARPS = KNN_TPB / 32;
constexpr int NGRP = Np / 2;                 // 2048 adjacent-pair groups

// ---------------- scratch ---------------------------------------------------
__device__ float4 g_pts4[Bz * Np];           // orig order: x,y,z, -0.5|p|^2
__device__ float4 g_spts4[Bz * Np];          // x-sorted order
__device__ int    g_perm[Bz * Np];           // sorted pos -> orig idx
__device__ int    g_boff[Bz * 257];          // bucket offsets
__device__ float  g_xT[Bz * Np * Cch];
__device__ int    g_idx[Mtot];
__device__ float  g_h1[6 * Mtot];
__device__ float  g_h2[3 * Mtot];
__device__ float  g_h3[Mtot];
__device__ double g_stats[24];
__device__ int    g_work[Bz];                // work-stealing counters

// ---------------- packed f32x2 helpers --------------------------------------
__device__ __forceinline__ unsigned long long fma2(unsigned long long a,
                                                   unsigned long long b,
                                                   unsigned long long c) {
    unsigned long long d;
    asm("fma.rn.f32x2 %0, %1, %2, %3;" : "=l"(d) : "l"(a), "l"(b), "l"(c));
    return d;
}
__device__ __forceinline__ unsigned long long pack2(float lo, float hi) {
    unsigned long long v;
    asm("mov.b64 %0, {%1, %2};" : "=l"(v) : "f"(lo), "f"(hi));
    return v;
}
__device__ __forceinline__ void unpack2(unsigned long long v, float& lo, float& hi) {
    asm("mov.b64 {%0, %1}, %2;" : "=f"(lo), "=f"(hi) : "l"(v));
}
__device__ __forceinline__ unsigned fkeyU(float f) {
    unsigned b = __float_as_uint(f);
    return b ^ ((unsigned)((int)b >> 31) | 0x80000000u);
}
__device__ __forceinline__ float keyToF(unsigned k) {
    unsigned m = (k & 0x80000000u) ? 0x80000000u : 0xFFFFFFFFu;
    return __uint_as_float(k ^ m);
}
__device__ __forceinline__ int bucketOf(float x) {
    int bk = (int)((x + 5.0f) * 25.6f);
    return min(255, max(0, bk));
}

// ---------------- K_pts: build pts4 + zero stats/work (launch #1, main) ----
__global__ void __launch_bounds__(256) k_pts(const float* __restrict__ xloc) {
    if (blockIdx.x == 0) {
        if (threadIdx.x < 24) g_stats[threadIdx.x] = 0.0;
        else if (threadIdx.x < 24 + Bz) g_work[threadIdx.x - 24] = 0;
    }
    int t = blockIdx.x * 256 + threadIdx.x;
    int b = t >> 12, n = t & 4095;
    const float* p = xloc + b * 3 * Np;
    float px = p[n], py = p[Np + n], pz = p[2 * Np + n];
    float xx = fmaf(pz, pz, fmaf(py, py, px * px));
    g_pts4[t] = make_float4(px, py, pz, -0.5f * xx);
}

// ---------------- K_xt: transpose-only x -> xT (stream 2, overlaps knn) ----
__global__ void __launch_bounds__(256) k_xt(const float* __restrict__ x) {
    __shared__ float s[64][33];
    int b = blockIdx.y;
    int n0 = blockIdx.x * 32;
    int lane = threadIdx.x & 31, w = threadIdx.x >> 5;
    #pragma unroll
    for (int i = 0; i < 8; i++) {
        int c = w * 8 + i;
        s[c][lane] = x[(((b << 6) + c) << 12) + n0 + lane];
    }
    __syncthreads();
    #pragma unroll
    for (int i = 0; i < 8; i++) {
        int e = i * 256 + threadIdx.x;
        int nl = e >> 6, c = e & 63;
        g_xT[(size_t)(((b << 12) + n0 + nl) << 6) + c] = s[c][nl];
    }
}

// ---------------- K_sort: bucket-sort points by x (launch #2, main) --------
__global__ void __launch_bounds__(512) k_sort() {
    __shared__ int hist[256];
    __shared__ int incl[256];
    __shared__ int offs[256];
    int b = blockIdx.x;
    int tid = threadIdx.x;
    if (tid < 256) hist[tid] = 0;
    __syncthreads();
    int bks[8];
    #pragma unroll
    for (int u = 0; u < 8; u++) {
        int i = u * 512 + tid;
        float xv = g_pts4[(b << 12) + i].x;
        int bk = bucketOf(xv);
        bks[u] = bk;
        atomicAdd(&hist[bk], 1);
    }
    __syncthreads();
    if (tid < 256) incl[tid] = hist[tid];
    __syncthreads();
    for (int off = 1; off < 256; off <<= 1) {
        int v = 0;
        if (tid < 256 && tid >= off) v = incl[tid - off];
        __syncthreads();
        if (tid < 256) incl[tid] += v;
        __syncthreads();
    }
    if (tid < 256) {
        int excl = incl[tid] - hist[tid];
        offs[tid] = excl;
        g_boff[b * 257 + tid] = excl;
    }
    if (tid == 0) g_boff[b * 257 + 256] = Np;
    __syncthreads();
    #pragma unroll
    for (int u = 0; u < 8; u++) {
        int i = u * 512 + tid;
        int pos = atomicAdd(&offs[bks[u]], 1);
        g_spts4[(b << 12) + pos] = g_pts4[(b << 12) + i];
        g_perm[(b << 12) + pos] = i;
    }
}

// ---------------- K_knn ------------------------------------------------------
__device__ __forceinline__ void rankWrite(const unsigned long long* cand, int C,
                                          int base, int lane) {
    if (C < Kn) {                            // astronomically rare fallback
        if (lane < Kn) g_idx[base + lane] = (int)(cand[0] & 0xFFFULL);
        if (lane < C)  g_idx[base + lane] = (int)(cand[lane] & 0xFFFULL);
        return;
    }
    if (C <= 64) {                           // common path: 2-cand/lane
        unsigned long long v0 = (lane < C)      ? cand[lane]      : 0ULL;
        unsigned long long v1 = (lane + 32 < C) ? cand[lane + 32] : 0ULL;
        int r0 = 0, r1 = 0;
        #pragma unroll 4
        for (int s = 0; s < C; s++) {
            unsigned long long w2 = cand[s];
            r0 += (w2 > v0); r1 += (w2 > v1);
        }
        if (lane < C      && r0 < Kn) g_idx[base + r0] = (int)(v0 & 0xFFFULL);
        if (lane + 32 < C && r1 < Kn) g_idx[base + r1] = (int)(v1 & 0xFFFULL);
        return;
    }
    for (int tb = 0; tb < C; tb += 128) {
        int t0 = tb + lane;
        unsigned long long v0 = (t0 < C)      ? cand[t0]      : 0ULL;
        unsigned long long v1 = (t0 + 32 < C) ? cand[t0 + 32] : 0ULL;
        unsigned long long v2 = (t0 + 64 < C) ? cand[t0 + 64] : 0ULL;
        unsigned long long v3 = (t0 + 96 < C) ? cand[t0 + 96] : 0ULL;
        int r0 = 0, r1 = 0, r2 = 0, r3 = 0;
        #pragma unroll 4
        for (int s = 0; s < C; s++) {
            unsigned long long w2 = cand[s];
            r0 += (w2 > v0); r1 += (w2 > v1);
            r2 += (w2 > v2); r3 += (w2 > v3);
        }
        if (t0 < C      && r0 < Kn) g_idx[base + r0] = (int)(v0 & 0xFFFULL);
        if (t0 + 32 < C && r1 < Kn) g_idx[base + r1] = (int)(v1 & 0xFFFULL);
        if (t0 + 64 < C && r2 < Kn) g_idx[base + r2] = (int)(v2 & 0xFFFULL);
        if (t0 + 96 < C && r3 < Kn) g_idx[base + r3] = (int)(v3 & 0xFFFULL);
    }
}

__global__ void __launch_bounds__(KNN_TPB, 2) k_knn() {
    extern __shared__ unsigned char smemRaw[];
    float* xs = reinterpret_cast<float*>(smemRaw);
    float* ys = xs + Np;
    float* zs = ys + Np;
    float* ws = zs + Np;
    unsigned long long* candBase =
        reinterpret_cast<unsigned long long*>(smemRaw + 4u * Np * sizeof(float));
    const float2* xs2 = reinterpret_cast<const float2*>(xs);
    const float2* ys2 = reinterpret_cast<const float2*>(ys);
    const float2* zs2 = reinterpret_cast<const float2*>(zs);
    const float2* ws2 = reinterpret_cast<const float2*>(ws);

    int b = blockIdx.y;
    const float4* gp = g_spts4 + b * Np;     // SORTED points
    for (int i = threadIdx.x; i < Np; i += KNN_TPB) {
        float4 p = gp[i];
        xs[i] = p.x; ys[i] = p.y; zs[i] = p.z; ws[i] = p.w;
    }
    __syncthreads();

    int wid = threadIdx.x >> 5, lane = threadIdx.x & 31;
    unsigned long long* cand = candBase + (size_t)wid * 2 * CAND_MAX;
    unsigned laneLT = (lane == 31) ? 0x7FFFFFFFu : ((1u << lane) - 1u);
    const int* boffB = g_boff + b * 257;
    const int* permB = g_perm + (b << 12);

    int fetched = 0;
    if (lane == 0) fetched = atomicAdd(&g_work[b], 1);
    int nextg = __shfl_sync(FULLMASK, fetched, 0);

    while (nextg < NGRP) {
        int nA = 2 * nextg;                  // adjacent sorted positions
        if (lane == 0) fetched = atomicAdd(&g_work[b], 1);

        float qx[2], qy[2], qz[2], qw[2];
        unsigned long long qX[2], qY[2], qZ[2];
        #pragma unroll
        for (int qi = 0; qi < 2; qi++) {
            int nq = nA + qi;
            qx[qi] = xs[nq]; qy[qi] = ys[nq]; qz[qi] = zs[nq]; qw[qi] = ws[nq];
            qX[qi] = pack2(qx[qi], qx[qi]);
            qY[qi] = pack2(qy[qi], qy[qi]);
            qZ[qi] = pack2(qz[qi], qz[qi]);
        }

        // --- sample pass: 512 strided samples ------------------------------
        int sBase = (lane * 125 + nA * 16) & 4095;
        float m1[2], m2[2];
        #pragma unroll
        for (int qi = 0; qi < 2; qi++) { m1[qi] = -3.4e38f; m2[qi] = -3.4e38f; }
        #pragma unroll 2
        for (int t = 0; t < 16; t++) {
            int idx = (sBase + t * 4000) & 4095;
            float px = xs[idx], py = ys[idx], pz = zs[idx], pw = ws[idx];
            #pragma unroll
            for (int qi = 0; qi < 2; qi++) {
                float s = fmaf(qz[qi], pz, fmaf(qy[qi], py, fmaf(qx[qi], px, pw)));
                if (s > m2[qi]) {
                    if (s > m1[qi]) { m2[qi] = m1[qi]; m1[qi] = s; } else m2[qi] = s;
                }
            }
        }
        // --- extract 8th largest per query via REDUX -----------------------
        float T[2];
        for (int r = 0; r < 8; r++) {
            #pragma unroll
            for (int qi = 0; qi < 2; qi++) {
                unsigned k1 = fkeyU(m1[qi]);
                unsigned vm = __reduce_max_sync(FULLMASK, k1);
                if (r == 7) T[qi] = keyToF(vm);
                unsigned wm = __ballot_sync(FULLMASK, k1 == vm);
                if (lane == __ffs(wm) - 1) { m1[qi] = m2[qi]; m2[qi] = -3.4e38f; }
            }
        }

        // --- slab bounds ----------------------------------------------------
        float DA = sqrtf(fmaxf(0.f, -2.0f * (qw[0] + T[0])));
        float DB = sqrtf(fmaxf(0.f, -2.0f * (qw[1] + T[1])));
        float xlo = fminf(qx[0] - DA, qx[1] - DB);
        float xhi = fmaxf(qx[0] + DA, qx[1] + DB);
        int jlo = boffB[bucketOf(xlo)] & ~63;
        int jhi = (boffB[bucketOf(xhi) + 1] + 63) & ~63;

        // --- zero mask words ------------------------------------------------
        {
            unsigned* mw0 = reinterpret_cast<unsigned*>(cand);
            unsigned* mw1 = reinterpret_cast<unsigned*>(cand + CAND_MAX);
            #pragma unroll
            for (int k = 0; k < 4; k++) {
                mw0[lane + 32 * k] = 0;
                mw1[lane + 32 * k] = 0;
            }
        }
        __syncwarp();

        // --- main scan over slab -------------------------------------------
        for (int j0 = jlo; j0 < jhi; j0 += 64) {
            int i2 = (j0 >> 1) + lane;
            float2 px = xs2[i2], py = ys2[i2], pz = zs2[i2], pw = ws2[i2];
            unsigned long long X = pack2(px.x, px.y), Y = pack2(py.x, py.y);
            unsigned long long Z = pack2(pz.x, pz.y), Wp = pack2(pw.x, pw.y);
            #pragma unroll
            for (int qi = 0; qi < 2; qi++) {
                unsigned long long s2 = fma2(qZ[qi], Z, fma2(qY[qi], Y, fma2(qX[qi], X, Wp)));
                float slo, shi; unpack2(s2, slo, shi);
                unsigned mlo = __ballot_sync(FULLMASK, slo > T[qi]);
                unsigned mhi = __ballot_sync(FULLMASK, shi > T[qi]);
                if (lane == 0) {
                    unsigned* mw = reinterpret_cast<unsigned*>(cand + qi * CAND_MAX);
                    mw[(j0 >> 5)] = mlo;
                    mw[(j0 >> 5) + 1] = mhi;
                }
            }
        }
        __syncwarp();

        // --- extraction: masks -> candidate (sorted) index list ------------
        int cnt[2];
        #pragma unroll
        for (int qi = 0; qi < 2; qi++) {
            unsigned* mw = reinterpret_cast<unsigned*>(cand + qi * CAND_MAX);
            unsigned w0 = mw[lane], w1 = mw[lane + 32];
            unsigned w2 = mw[lane + 64], w3 = mw[lane + 96];
            __syncwarp();
            int tot = __popc(w0) + __popc(w1) + __popc(w2) + __popc(w3);
            int incl = tot;
            #pragma unroll
            for (int o = 1; o < 32; o <<= 1) {
                int v = __shfl_up_sync(FULLMASK, incl, o);
                if (lane >= o) incl += v;
            }
            int Cq = __shfl_sync(FULLMASK, incl, 31);
            int pos = incl - tot;
            unsigned* cq32 = mw;
            unsigned wv[4] = {w0, w1, w2, w3};
            #pragma unroll
            for (int k = 0; k < 4; k++) {
                int word = lane + 32 * k;
                int pbase = ((word >> 1) << 6) + (word & 1);
                unsigned v = wv[k];
                while (v) {
                    int bit = __ffs(v) - 1;
                    v &= v - 1;
                    if (pos < CAND_MAX) cq32[2 * pos] = pbase + 2 * bit;
                    pos++;
                }
            }
            cnt[qi] = Cq;
            __syncwarp();
        }

        // --- rare retry: 16th-sample threshold, FULL scan ------------------
        #pragma unroll
        for (int qi = 0; qi < 2; qi++) {
            if (cnt[qi] < Kn) {
                float qxx = qx[qi], qyy = qy[qi], qzz = qz[qi];
                float n1 = -3.4e38f, n2 = -3.4e38f;
                for (int t = 0; t < 16; t++) {
                    int idx = (sBase + t * 4000) & 4095;
                    float s = fmaf(qzz, zs[idx], fmaf(qyy, ys[idx], fmaf(qxx, xs[idx], ws[idx])));
                    if (s > n2) {
                        if (s > n1) { n2 = n1; n1 = s; } else n2 = s;
                    }
                }
                float Tq = -3.4e38f;
                for (int r = 0; r < 16; r++) {
                    unsigned k1 = fkeyU(n1);
                    unsigned vm = __reduce_max_sync(FULLMASK, k1);
                    if (r == 15) Tq = keyToF(vm);
                    unsigned wm = __ballot_sync(FULLMASK, k1 == vm);
                    if (lane == __ffs(wm) - 1) { n1 = n2; n2 = -3.4e38f; }
                }
                unsigned c = 0;
                unsigned* cq32 = reinterpret_cast<unsigned*>(cand + qi * CAND_MAX);
                for (int j0 = 0; j0 < Np; j0 += 32) {
                    int j = j0 + lane;
                    float s = fmaf(qzz, zs[j], fmaf(qyy, ys[j], fmaf(qxx, xs[j], ws[j])));
                    unsigned mk = __ballot_sync(FULLMASK, s > Tq);
                    if (s > Tq) {
                        unsigned p = c + __popc(mk & laneLT);
                        if (p < CAND_MAX) cq32[2 * p] = j;
                    }
                    c += __popc(mk);
                }
                cnt[qi] = c;
            }
        }
        __syncwarp();

        // --- pack (key<<12 | ORIG idx) then rank-select top-30 -------------
        #pragma unroll
        for (int qi = 0; qi < 2; qi++) {
            int C = min(cnt[qi], CAND_MAX);
            unsigned long long* cq = cand + qi * CAND_MAX;
            unsigned* cq32 = reinterpret_cast<unsigned*>(cq);
            float qxx = qx[qi], qyy = qy[qi], qzz = qz[qi];
            for (int t = lane; t < C; t += 32) {
                unsigned j = cq32[2 * t];
                float s = fmaf(qzz, zs[j], fmaf(qyy, ys[j], fmaf(qxx, xs[j], ws[j])));
                int orig = permB[j];
                cq[t] = ((unsigned long long)fkeyU(s) << 12) | (unsigned)orig;
            }
            __syncwarp();
            int origQ = permB[nA + qi];
            rankWrite(cq, C, (b * Np + origQ) * Kn, lane);
        }
        __syncwarp();

        nextg = __shfl_sync(FULLMASK, fetched, 0);
    }
}

// ---------------- block-level stat accumulation ----------------------------
template <int NV>
__device__ __forceinline__ void accumStats(const float* vals, float* sAcc, int statBase) {
    #pragma unroll
    for (int v = 0; v < NV; v++) {
        float x = vals[v];
        #pragma unroll
        for (int off = 16; off; off >>= 1) x += __shfl_down_sync(FULLMASK, x, off);
        if ((threadIdx.x & 31) == 0) atomicAdd(&sAcc[v], x);
    }
    __syncthreads();
    if (threadIdx.x < NV) atomicAdd(&g_stats[statBase + threadIdx.x], (double)sAcc[threadIdx.x]);
}

// ---------------- K_feat: element-parallel, 2 elems/thread -----------------
__global__ void __launch_bounds__(256) k_feat(const float* __restrict__ W1) {
    __shared__ float sW[36];
    __shared__ float sAcc[12];
    int tid = threadIdx.x;
    if (tid < 36) sW[tid] = W1[tid];
    if (tid < 12) sAcc[tid] = 0.f;
    __syncthreads();
    float acc[12];
    #pragma unroll
    for (int v = 0; v < 12; v++) acc[v] = 0.f;

    int e0 = (blockIdx.x * 256 + tid) * 2;
    float2 hv[6];
    #pragma unroll
    for (int u = 0; u < 2; u++) {
        int e = e0 + u;
        int r = e / Kn;
        int b = r >> 12;
        int j = g_idx[e];
        float4 pn = g_pts4[r];
        float4 pj = g_pts4[(b << 12) + j];
        float xr = pj.x - pn.x, yr = pj.y - pn.y, zr = pj.z - pn.z;
        float sxy2 = fmaf(yr, yr, xr * xr);
        float r2 = fmaf(zr, zr, sxy2);
        float rho = sqrtf(fmaxf(r2, TINYc));
        float sxy = sqrtf(fmaxf(sxy2, TINYc));
        float theta = (r2 < TINYc) ? 0.f : atan2f(zr, sxy);
        float phi = (sxy2 < TINYc) ? 0.f : atan2f(yr, xr);
        float mn = (rho + theta + phi) * (1.f / 3.f);
        float f[6] = {rho, theta, phi, rho - mn, theta - mn, phi - mn};
        #pragma unroll
        for (int o = 0; o < 6; o++) {
            float h = 0.f;
            #pragma unroll
            for (int i2 = 0; i2 < 6; i2++) h = fmaf(sW[o * 6 + i2], f[i2], h);
            (&hv[o].x)[u] = h;
            acc[o] += h;
            acc[6 + o] = fmaf(h, h, acc[6 + o]);
        }
    }
    #pragma unroll
    for (int o = 0; o < 6; o++)
        *reinterpret_cast<float2*>(&g_h1[o * Mtot + e0]) = hv[o];
    accumStats<12>(acc, sAcc, 0);
}

__device__ __forceinline__ float lrelu02(float t) { return t > 0.f ? t : 0.2f * t; }

// ---------------- K_l2: BN1 + lrelu + layer2 + stats (float4) --------------
__global__ void __launch_bounds__(256) k_l2(const float* __restrict__ gma,
                                            const float* __restrict__ bta,
                                            const float* __restrict__ W2) {
    __shared__ float sMu[6], sIs[6], sG[6], sB[6], sW[18], sAcc[6];
    int tid = threadIdx.x;
    if (tid < 6) {
        double s = g_stats[tid], sq = g_stats[6 + tid];
        double mu = s / (double)Mtot;
        double var = sq / (double)Mtot - mu * mu;
        sMu[tid] = (float)mu;
        sIs[tid] = (float)(1.0 / sqrt(var + (double)EPS_BN));
        sG[tid] = gma[tid]; sB[tid] = bta[tid];
        sAcc[tid] = 0.f;
    }
    if (tid < 18) sW[tid] = W2[tid];
    __syncthreads();
    int e4 = (blockIdx.x * 256 + tid) * 4;
    float4 a[6];
    #pragma unroll
    for (int i = 0; i < 6; i++) {
        float4 h = *reinterpret_cast<const float4*>(&g_h1[i * Mtot + e4]);
        float sc = sIs[i] * sG[i], mu = sMu[i], bb = sB[i];
        a[i].x = lrelu02(fmaf((h.x - mu), sc, bb));
        a[i].y = lrelu02(fmaf((h.y - mu), sc, bb));
        a[i].z = lrelu02(fmaf((h.z - mu), sc, bb));
        a[i].w = lrelu02(fmaf((h.w - mu), sc, bb));
    }
    float vals[6];
    #pragma unroll
    for (int o = 0; o < 3; o++) {
        float4 h = make_float4(0.f, 0.f, 0.f, 0.f);
        #pragma unroll
        for (int i = 0; i < 6; i++) {
            float w = sW[o * 6 + i];
            h.x = fmaf(w, a[i].x, h.x); h.y = fmaf(w, a[i].y, h.y);
            h.z = fmaf(w, a[i].z, h.z); h.w = fmaf(w, a[i].w, h.w);
        }
        *reinterpret_cast<float4*>(&g_h2[o * Mtot + e4]) = h;
        vals[o] = (h.x + h.y) + (h.z + h.w);
        vals[3 + o] = fmaf(h.x, h.x, h.y * h.y) + fmaf(h.z, h.z, h.w * h.w);
    }
    accumStats<6>(vals, sAcc, 12);
}

// ---------------- K_l3: BN2 + lrelu + layer3 + stats (float4) --------------
__global__ void __launch_bounds__(256) k_l3(const float* __restrict__ gma,
                                            const float* __restrict__ bta,
                                            const float* __restrict__ W3) {
    __shared__ float sMu[3], sIs[3], sG[3], sB[3], sW[3], sAcc[2];
    int tid = threadIdx.x;
    if (tid < 3) {
        double s = g_stats[12 + tid], sq = g_stats[15 + tid];
        double mu = s / (double)Mtot;
        double var = sq / (double)Mtot - mu * mu;
        sMu[tid] = (float)mu;
        sIs[tid] = (float)(1.0 / sqrt(var + (double)EPS_BN));
        sG[tid] = gma[tid]; sB[tid] = bta[tid];
        sW[tid] = W3[tid];
    }
    if (tid < 2) sAcc[tid] = 0.f;
    __syncthreads();
    int e4 = (blockIdx.x * 256 + tid) * 4;
    float4 h = make_float4(0.f, 0.f, 0.f, 0.f);
    #pragma unroll
    for (int i = 0; i < 3; i++) {
        float4 hv = *reinterpret_cast<const float4*>(&g_h2[i * Mtot + e4]);
        float sc = sIs[i] * sG[i], mu = sMu[i], bb = sB[i], w = sW[i];
        h.x = fmaf(w, lrelu02(fmaf((hv.x - mu), sc, bb)), h.x);
        h.y = fmaf(w, lrelu02(fmaf((hv.y - mu), sc, bb)), h.y);
        h.z = fmaf(w, lrelu02(fmaf((hv.z - mu), sc, bb)), h.z);
        h.w = fmaf(w, lrelu02(fmaf((hv.w - mu), sc, bb)), h.w);
    }
    *reinterpret_cast<float4*>(&g_h3[e4]) = h;
    float vals[2];
    vals[0] = (h.x + h.y) + (h.z + h.w);
    vals[1] = fmaf(h.x, h.x, h.y * h.y) + fmaf(h.z, h.z, h.w * h.w);
    accumStats<2>(vals, sAcc, 18);
}

// ---------------- K_out: softmax + aggregate, coalesced IO -----------------
__global__ void __launch_bounds__(256) k_out(const float* __restrict__ x,
                                             const float* __restrict__ g3,
                                             const float* __restrict__ b3,
                                             float* __restrict__ out) {
    __shared__ float agg[64][33];
    __shared__ float sMu, sIs;
    int tid = threadIdx.x, wid = tid >> 5, lane = tid & 31;
    if (tid == 0) {
        double s = g_stats[18], sq = g_stats[19];
        double mu = s / (double)Mtot;
        double var = sq / (double)Mtot - mu * mu;
        sMu = (float)mu;
        sIs = (float)(1.0 / sqrt(var + (double)EPS_BN));
    }
    __syncthreads();
    int b = blockIdx.y;
    int n0 = blockIdx.x * 32;
    float gv = g3[0], bv = b3[0];
    const float* xb = g_xT + (size_t)(b << 12) * Cch;

    #pragma unroll
    for (int i = 0; i < 4; i++) {
        int nl = wid * 4 + i;
        int r = (b << 12) + n0 + nl;
        float logit = -INFINITY;
        int jv = 0;
        if (lane < Kn) {
            float h = g_h3[r * Kn + lane];
            float t = fmaf((h - sMu) * sIs, gv, bv);
            logit = t > 0.f ? t : 0.2f * t;
            jv = g_idx[r * Kn + lane];
        }
        float mx = logit;
        #pragma unroll
        for (int off = 16; off; off >>= 1) mx = fmaxf(mx, __shfl_xor_sync(FULLMASK, mx, off));
        float ex = (lane < Kn) ? expf(logit - mx) : 0.f;
        float sm = ex;
        #pragma unroll
        for (int off = 16; off; off >>= 1) sm += __shfl_xor_sync(FULLMASK, sm, off);
        float att = ex / sm;

        float acc0 = 0.f, acc1 = 0.f;
        #pragma unroll 5
        for (int kk = 0; kk < Kn; kk++) {
            int j = __shfl_sync(FULLMASK, jv, kk);
            float a = __shfl_sync(FULLMASK, att, kk);
            const float* p = xb + j * Cch;
            acc0 = fmaf(a, p[lane], acc0);
            acc1 = fmaf(a, p[lane + 32], acc1);
        }
        agg[lane][nl] = acc0;
        agg[lane + 32][nl] = acc1;
    }
    __syncthreads();
    #pragma unroll
    for (int i = 0; i < 8; i++) {
        int e = i * 256 + tid;
        int c = e >> 5, nl = e & 31;
        size_t o = (size_t)b * (Cch * Np) + (size_t)c * Np + (size_t)(n0 + nl);
        out[o] = x[o] + agg[c][nl];
    }
}

// ---------------- launch ----------------------------------------------------
extern "C" void kernel_launch(void* const* d_in, const int* in_sizes, int n_in,
                              void* d_out, int out_size) {
    const float* xloc = (const float*)d_in[0];
    const float* x    = (const float*)d_in[1];
    const float* W1   = (const float*)d_in[2];
    const float* g1   = (const float*)d_in[3];
    const float* b1   = (const float*)d_in[4];
    const float* W2   = (const float*)d_in[5];
    const float* g2   = (const float*)d_in[6];
    const float* b2   = (const float*)d_in[7];
    const float* W3   = (const float*)d_in[8];
    const float* g3   = (const float*)d_in[9];
    const float* b3   = (const float*)d_in[10];
    float* out = (float*)d_out;

    static cudaStream_t s2 = nullptr;
    static cudaEvent_t evA = nullptr, evB = nullptr;
    if (!s2) {
        cudaStreamCreateWithFlags(&s2, cudaStreamNonBlocking);
        cudaEventCreateWithFlags(&evA, cudaEventDisableTiming);
        cudaEventCreateWithFlags(&evB, cudaEventDisableTiming);
    }

    size_t knnSmem = 4u * Np * sizeof(float) +
                     sizeof(unsigned long long) * KNN_WARPS * 2 * CAND_MAX;  // 112 KB
    cudaFuncSetAttribute(k_knn, cudaFuncAttributeMaxDynamicSharedMemorySize, (int)knnSmem);

    // fork: xT transpose on s2 (only consumed by k_out)
    cudaEventRecord(evA, 0);
    cudaStreamWaitEvent(s2, evA, 0);
    k_xt<<<dim3(Np / 32, Bz), 256, 0, s2>>>(x);
    cudaEventRecord(evB, s2);

    // main chain
    k_pts<<<Bz * Np / 256, 256>>>(xloc);          // pts4 + zero stats/work
    k_sort<<<Bz, 512>>>();                        // bucket sort by x
    k_knn<<<dim3(37, Bz), KNN_TPB, knnSmem>>>();
    k_feat<<<Mtot / 512, 256>>>(W1);
    k_l2<<<Mtot / 1024, 256>>>(g1, b1, W2);
    k_l3<<<Mtot / 1024, 256>>>(g2, b2, W3);

    // join: k_out needs xT
    cudaStreamWaitEvent(0, evB, 0);
    k_out<<<dim3(Np / 32, Bz), 256>>>(x, g3, b3, out);
}